// round 1
// baseline (speedup 1.0000x reference)
#include <cuda_runtime.h>

#define NB  8
#define CHN 256
#define HT  160
#define WDT 160
#define HW  25600
#define DD  512
#define NN  1600

// Scratch (static device globals — allocation-free per harness rules)
__device__ float g_fq[NB*DD*NN];   // 26.2 MB
__device__ float g_fk[NB*DD*NN];
__device__ float g_fv[NB*DD*NN];
__device__ float g_sc[NB*DD*DD];   // 8.4 MB (scores -> attn in place)
__device__ float g_op[NB*DD*NN];   // 26.2 MB

typedef unsigned long long u64;

__device__ __forceinline__ void ffma2(u64 &acc, u64 a, u64 b) {
    asm("fma.rn.f32x2 %0, %1, %2, %0;" : "+l"(acc) : "l"(a), "l"(b));
}
__device__ __forceinline__ u64 pk2(float x, float y) {
    u64 r; asm("mov.b64 %0, {%1, %2};" : "=l"(r) : "f"(x), "f"(y)); return r;
}
__device__ __forceinline__ float2 upk2(u64 v) {
    float2 f; asm("mov.b64 {%0, %1}, %2;" : "=f"(f.x), "=f"(f.y) : "l"(v)); return f;
}

// ---------------------------------------------------------------------------
// K1: fused q/k/v 1x1-conv + pixel_unshuffle.
// Per block: 128 pixels x 96 output rows (rows 0-31 = q(depth), 32-63 = v(depth),
// 64-95 = k(rgb)). 192 threads, thread tile 8 rows x 8 pixels (4 f32x2 pairs).
// ---------------------------------------------------------------------------
__global__ __launch_bounds__(192) void k_proj(
    const float* __restrict__ rgb, const float* __restrict__ depth,
    const float* __restrict__ Wq, const float* __restrict__ bq,
    const float* __restrict__ Wk, const float* __restrict__ bk,
    const float* __restrict__ Wv, const float* __restrict__ bv)
{
    __shared__ __align__(16) float Ws[16][97];
    __shared__ __align__(16) float Xd[16][130];
    __shared__ __align__(16) float Xr[16][130];

    const int blk  = blockIdx.x;
    const int b    = blk / 200;
    const int pix0 = (blk % 200) * 128;
    const int t  = threadIdx.x;
    const int tx = t & 15;    // pixel group
    const int ty = t >> 4;    // row group 0..11

    u64 acc[8][4];
#pragma unroll
    for (int r = 0; r < 8; r++)
#pragma unroll
        for (int p = 0; p < 4; p++) acc[r][p] = 0ull;

    const float* dbase = depth + (size_t)b*CHN*HW + pix0;
    const float* rbase = rgb   + (size_t)b*CHN*HW + pix0;

    for (int kc = 0; kc < CHN; kc += 16) {
        // weights: Ws[kk][r]
#pragma unroll
        for (int ii = 0; ii < 8; ii++) {
            int i = t + ii*192;
            int r = i >> 4, kk = i & 15;
            const float* wrow = (r < 32) ? (Wq + r*CHN)
                               : ((r < 64) ? (Wv + (r-32)*CHN) : (Wk + (r-64)*CHN));
            Ws[kk][r] = wrow[kc + kk];
        }
        // inputs: Xd/Xr[kk][p]
        for (int i = t; i < 2048; i += 192) {
            int kk = i >> 7, p = i & 127;
            Xd[kk][p] = dbase[(size_t)(kc+kk)*HW + p];
            Xr[kk][p] = rbase[(size_t)(kc+kk)*HW + p];
        }
        __syncthreads();

        const float (*Xs)[130] = (ty < 8) ? Xd : Xr;
#pragma unroll
        for (int kk = 0; kk < 16; kk++) {
            u64 xv[4];
#pragma unroll
            for (int pp = 0; pp < 4; pp++)
                xv[pp] = *(const u64*)&Xs[kk][tx*2 + pp*32];
#pragma unroll
            for (int rr = 0; rr < 8; rr++) {
                float a = Ws[kk][ty*8 + rr];
                u64 aa = pk2(a, a);
#pragma unroll
                for (int pp = 0; pp < 4; pp++) ffma2(acc[rr][pp], aa, xv[pp]);
            }
        }
        __syncthreads();
    }

    // epilogue: add bias, pixel_unshuffle scatter to [B, D, N]
#pragma unroll
    for (int rr = 0; rr < 8; rr++) {
        int r = ty*8 + rr;
        float* dst; const float* bias; int c;
        if (r < 32)      { dst = g_fq; bias = bq; c = r; }
        else if (r < 64) { dst = g_fv; bias = bv; c = r - 32; }
        else             { dst = g_fk; bias = bk; c = r - 64; }
        float bb = bias[c];
#pragma unroll
        for (int pp = 0; pp < 4; pp++) {
            float2 v = upk2(acc[rr][pp]);
#pragma unroll
            for (int half = 0; half < 2; half++) {
                int p = pix0 + tx*2 + pp*32 + half;
                int h = p / 160, w = p - h*160;
                int dd = c*16 + (h & 3)*4 + (w & 3);
                int n  = (h >> 2)*40 + (w >> 2);
                dst[((size_t)b*DD + dd)*NN + n] = ((half == 0) ? v.x : v.y) + bb;
            }
        }
    }
}

// ---------------------------------------------------------------------------
// K2: scores[b,d,e] = sum_n fq[b,d,n] * fk[b,e,n]   (raw; scaled in softmax)
// block tile 64(d) x 128(e), K=1600 in chunks of 16. 256 threads, 4x8 per thread.
// ---------------------------------------------------------------------------
__global__ __launch_bounds__(256) void k_scores()
{
    __shared__ __align__(16) float As[16][65];
    __shared__ __align__(16) float Bs[16][130];

    const int b  = blockIdx.z;
    const int d0 = blockIdx.y * 64;
    const int e0 = blockIdx.x * 128;
    const int t  = threadIdx.x;
    const int tx = t & 15, ty = t >> 4;

    const float* fqb = g_fq + (size_t)(b*DD + d0)*NN;
    const float* fkb = g_fk + (size_t)(b*DD + e0)*NN;

    u64 acc[4][4];
#pragma unroll
    for (int r = 0; r < 4; r++)
#pragma unroll
        for (int p = 0; p < 4; p++) acc[r][p] = 0ull;

    for (int kc = 0; kc < NN; kc += 16) {
#pragma unroll
        for (int ii = 0; ii < 4; ii++) {
            int i = t + ii*256;
            int d = i >> 4, kk = i & 15;
            As[kk][d] = fqb[(size_t)d*NN + kc + kk];
        }
#pragma unroll
        for (int ii = 0; ii < 8; ii++) {
            int i = t + ii*256;
            int e = i >> 4, kk = i & 15;
            Bs[kk][e] = fkb[(size_t)e*NN + kc + kk];
        }
        __syncthreads();
#pragma unroll
        for (int kk = 0; kk < 16; kk++) {
            u64 xv[4];
#pragma unroll
            for (int pp = 0; pp < 4; pp++)
                xv[pp] = *(const u64*)&Bs[kk][tx*2 + pp*32];
#pragma unroll
            for (int r = 0; r < 4; r++) {
                float a = As[kk][ty*4 + r];
                u64 aa = pk2(a, a);
#pragma unroll
                for (int pp = 0; pp < 4; pp++) ffma2(acc[r][pp], aa, xv[pp]);
            }
        }
        __syncthreads();
    }

    float* out = g_sc + (size_t)b*DD*DD;
#pragma unroll
    for (int r = 0; r < 4; r++) {
        int d = d0 + ty*4 + r;
#pragma unroll
        for (int pp = 0; pp < 4; pp++) {
            float2 v = upk2(acc[r][pp]);
            int e = e0 + tx*2 + pp*32;
            *(float2*)&out[(size_t)d*DD + e] = v;
        }
    }
}

// ---------------------------------------------------------------------------
// K3: softmax over last axis of scores/sqrt(D). One 128-thread block per row.
// ---------------------------------------------------------------------------
__global__ __launch_bounds__(128) void k_softmax()
{
    __shared__ float red[8];
    float* s = g_sc + (size_t)blockIdx.x * DD;
    const int t = threadIdx.x;

    float v0 = s[t], v1 = s[t+128], v2 = s[t+256], v3 = s[t+384];
    float m = fmaxf(fmaxf(v0, v1), fmaxf(v2, v3));
#pragma unroll
    for (int o = 16; o; o >>= 1) m = fmaxf(m, __shfl_xor_sync(0xffffffffu, m, o));
    if ((t & 31) == 0) red[t >> 5] = m;
    __syncthreads();
    m = fmaxf(fmaxf(red[0], red[1]), fmaxf(red[2], red[3]));

    const float inv = 0.04419417382415922f;  // 1/sqrt(512)
    float e0 = __expf((v0 - m) * inv);
    float e1 = __expf((v1 - m) * inv);
    float e2 = __expf((v2 - m) * inv);
    float e3 = __expf((v3 - m) * inv);
    float sum = e0 + e1 + e2 + e3;
#pragma unroll
    for (int o = 16; o; o >>= 1) sum += __shfl_xor_sync(0xffffffffu, sum, o);
    if ((t & 31) == 0) red[4 + (t >> 5)] = sum;
    __syncthreads();
    float r = 1.0f / (red[4] + red[5] + red[6] + red[7]);

    s[t]     = e0 * r;
    s[t+128] = e1 * r;
    s[t+256] = e2 * r;
    s[t+384] = e3 * r;
}

// ---------------------------------------------------------------------------
// K4: out_pre[b,d,n] = sum_e attn[b,d,e] * fv[b,e,n]
// block tile 64(d) x 128(n), K=512 in chunks of 16; N=1600 needs 13 n-tiles.
// ---------------------------------------------------------------------------
__global__ __launch_bounds__(256) void k_attnv()
{
    __shared__ __align__(16) float As[16][65];
    __shared__ __align__(16) float Bs[16][130];

    const int b  = blockIdx.z;
    const int d0 = blockIdx.y * 64;
    const int n0 = blockIdx.x * 128;
    const int t  = threadIdx.x;
    const int tx = t & 15, ty = t >> 4;

    const float* ab  = g_sc + (size_t)(b*DD + d0)*DD;
    const float* fvb = g_fv + (size_t)b*DD*NN;

    u64 acc[4][4];
#pragma unroll
    for (int r = 0; r < 4; r++)
#pragma unroll
        for (int p = 0; p < 4; p++) acc[r][p] = 0ull;

    for (int kc = 0; kc < DD; kc += 16) {
#pragma unroll
        for (int ii = 0; ii < 4; ii++) {
            int i = t + ii*256;
            int d = i >> 4, kk = i & 15;
            As[kk][d] = ab[(size_t)d*DD + kc + kk];
        }
#pragma unroll
        for (int ii = 0; ii < 8; ii++) {
            int i = t + ii*256;
            int kk = i >> 7, p = i & 127;
            int n = n0 + p;
            Bs[kk][p] = (n < NN) ? fvb[(size_t)(kc+kk)*NN + n] : 0.0f;
        }
        __syncthreads();
#pragma unroll
        for (int kk = 0; kk < 16; kk++) {
            u64 xv[4];
#pragma unroll
            for (int pp = 0; pp < 4; pp++)
                xv[pp] = *(const u64*)&Bs[kk][tx*2 + pp*32];
#pragma unroll
            for (int r = 0; r < 4; r++) {
                float a = As[kk][ty*4 + r];
                u64 aa = pk2(a, a);
#pragma unroll
                for (int pp = 0; pp < 4; pp++) ffma2(acc[r][pp], aa, xv[pp]);
            }
        }
        __syncthreads();
    }

#pragma unroll
    for (int r = 0; r < 4; r++) {
        int d = d0 + ty*4 + r;
#pragma unroll
        for (int pp = 0; pp < 4; pp++) {
            int n = n0 + tx*2 + pp*32;
            if (n < NN) {
                float2 v = upk2(acc[r][pp]);
                *(float2*)&g_op[((size_t)b*DD + d)*NN + n] = v;
            }
        }
    }
}

// ---------------------------------------------------------------------------
// K5: pixel_shuffle gather + final 1x1 conv (32 -> 256) + bias.
// block: 64 pixels x 256 channels; 256 threads, thread tile 8ch x 8pix. K=32.
// ---------------------------------------------------------------------------
__global__ __launch_bounds__(256) void k_final(
    const float* __restrict__ Wu, const float* __restrict__ bu,
    float* __restrict__ out)
{
    __shared__ __align__(16) float Ws2[32][257];
    __shared__ __align__(16) float Xs[32][66];

    const int blk  = blockIdx.x;
    const int b    = blk / 400;
    const int pix0 = (blk % 400) * 64;
    const int t  = threadIdx.x;
    const int tx = t & 7, ty = t >> 3;

    // Wu [256][32] -> Ws2[c][ch]
#pragma unroll
    for (int ii = 0; ii < 32; ii++) {
        int i = t + ii*256;
        int ch = i >> 5, c = i & 31;
        Ws2[c][ch] = Wu[i];
    }
    // gather out_pre with pixel_shuffle indexing: Xs[c][p]
#pragma unroll
    for (int ii = 0; ii < 8; ii++) {
        int i = t + ii*256;
        int c = i >> 6, p = i & 63;
        int px = pix0 + p;
        int h = px / 160, w = px - h*160;
        int dd = c*16 + (h & 3)*4 + (w & 3);
        int n  = (h >> 2)*40 + (w >> 2);
        Xs[c][p] = g_op[((size_t)b*DD + dd)*NN + n];
    }
    __syncthreads();

    u64 acc[8][4];
#pragma unroll
    for (int r = 0; r < 8; r++)
#pragma unroll
        for (int p = 0; p < 4; p++) acc[r][p] = 0ull;

#pragma unroll 8
    for (int c = 0; c < 32; c++) {
        u64 xv[4];
#pragma unroll
        for (int pp = 0; pp < 4; pp++)
            xv[pp] = *(const u64*)&Xs[c][tx*2 + pp*16];
#pragma unroll
        for (int rr = 0; rr < 8; rr++) {
            float a = Ws2[c][ty*8 + rr];
            u64 aa = pk2(a, a);
#pragma unroll
            for (int pp = 0; pp < 4; pp++) ffma2(acc[rr][pp], aa, xv[pp]);
        }
    }

#pragma unroll
    for (int rr = 0; rr < 8; rr++) {
        int ch = ty*8 + rr;
        float bb = bu[ch];
        float* ob = out + ((size_t)b*CHN + ch)*HW + pix0;
#pragma unroll
        for (int pp = 0; pp < 4; pp++) {
            float2 v = upk2(acc[rr][pp]);
            v.x += bb; v.y += bb;
            *(float2*)&ob[tx*2 + pp*16] = v;
        }
    }
}

// ---------------------------------------------------------------------------
extern "C" void kernel_launch(void* const* d_in, const int* in_sizes, int n_in,
                              void* d_out, int out_size)
{
    (void)in_sizes; (void)n_in; (void)out_size;
    const float* rgb   = (const float*)d_in[0];
    const float* depth = (const float*)d_in[1];
    const float* Wq    = (const float*)d_in[2];
    const float* bq    = (const float*)d_in[3];
    const float* Wk    = (const float*)d_in[4];
    const float* bk    = (const float*)d_in[5];
    const float* Wv    = (const float*)d_in[6];
    const float* bv    = (const float*)d_in[7];
    const float* Wu    = (const float*)d_in[8];
    const float* bu    = (const float*)d_in[9];
    float* out = (float*)d_out;

    k_proj   <<<1600, 192>>>(rgb, depth, Wq, bq, Wk, bk, Wv, bv);
    k_scores <<<dim3(4, 8, NB), 256>>>();
    k_softmax<<<NB*DD, 128>>>();
    k_attnv  <<<dim3(13, 8, NB), 256>>>();
    k_final  <<<3200, 256>>>(Wu, bu, out);
}

// round 3
// speedup vs baseline: 1.3831x; 1.3831x over previous
#include <cuda_runtime.h>
#include <cuda_bf16.h>
#include <cstdint>

#define NB  8
#define CHN 256
#define HW  25600
#define DD  512
#define NN  1600
#define NNP 1664

// ---------------- scratch (__device__ globals; allocation-free) ------------
__device__ float g_sc[NB*DD*DD];    // scores fp32
__device__ float g_op[NB*DD*NN];    // attn@V output fp32
__device__ __align__(128) __nv_bfloat16 g_fq_hi[NB*DD*NN];
__device__ __align__(128) __nv_bfloat16 g_fq_mi[NB*DD*NN];
__device__ __align__(128) __nv_bfloat16 g_fk_hi[NB*DD*NN];
__device__ __align__(128) __nv_bfloat16 g_fk_mi[NB*DD*NN];
__device__ __align__(128) __nv_bfloat16 g_fvT_hi[NB*NNP*DD];
__device__ __align__(128) __nv_bfloat16 g_fvT_mi[NB*NNP*DD];
__device__ __align__(128) __nv_bfloat16 g_at_hi[NB*DD*DD];
__device__ __align__(128) __nv_bfloat16 g_at_mi[NB*DD*DD];

typedef unsigned long long u64;

// ---------------- PTX helpers (baseline ISA only — no 'a'-suffix ops) ------
__device__ __forceinline__ void ffma2(u64 &acc, u64 a, u64 b) {
    asm("fma.rn.f32x2 %0, %1, %2, %0;" : "+l"(acc) : "l"(a), "l"(b));
}
__device__ __forceinline__ u64 pk2(float x, float y) {
    u64 r; asm("mov.b64 %0, {%1, %2};" : "=l"(r) : "f"(x), "f"(y)); return r;
}
__device__ __forceinline__ float2 upk2(u64 v) {
    float2 f; asm("mov.b64 {%0, %1}, %2;" : "=f"(f.x), "=f"(f.y) : "l"(v)); return f;
}
__device__ __forceinline__ uint32_t smem_u32(const void* p) {
    uint32_t a;
    asm("{ .reg .u64 t; cvta.to.shared.u64 t, %1; cvt.u32.u64 %0, t; }" : "=r"(a) : "l"(p));
    return a;
}
__device__ __forceinline__ void cpa16(uint32_t s, const void* g) {
    asm volatile("cp.async.cg.shared.global [%0], [%1], 16;" :: "r"(s), "l"(g));
}
#define CPA_COMMIT() asm volatile("cp.async.commit_group;" ::: "memory")

__device__ __forceinline__ void ldsm4(uint32_t* r, uint32_t a) {
    asm volatile("ldmatrix.sync.aligned.m8n8.x4.shared.b16 {%0,%1,%2,%3}, [%4];"
        : "=r"(r[0]), "=r"(r[1]), "=r"(r[2]), "=r"(r[3]) : "r"(a));
}
__device__ __forceinline__ void mma_bf16(float* d, const uint32_t* a, uint32_t b0, uint32_t b1) {
    asm volatile(
        "mma.sync.aligned.m16n8k16.row.col.f32.bf16.bf16.f32 "
        "{%0,%1,%2,%3},{%4,%5,%6,%7},{%8,%9},{%0,%1,%2,%3};"
        : "+f"(d[0]), "+f"(d[1]), "+f"(d[2]), "+f"(d[3])
        : "r"(a[0]), "r"(a[1]), "r"(a[2]), "r"(a[3]), "r"(b0), "r"(b1));
}

__device__ __forceinline__ void split_bf16(float v, __nv_bfloat16 &h, __nv_bfloat16 &m) {
    h = __float2bfloat16(v);
    m = __float2bfloat16(v - __bfloat162float(h));
}

// ---------------------------------------------------------------------------
// K0: zero the fvT padding rows (n = 1600..1663) so GEMM1's last n-tile
// reads defined data.
// ---------------------------------------------------------------------------
__global__ __launch_bounds__(256) void k_zero()
{
    int i = blockIdx.x * 256 + threadIdx.x;
    if (i < NB*64*DD) {
        int b = i / (64*DD);
        int r = i - b*(64*DD);
        size_t idx = (size_t)b*NNP*DD + (size_t)NN*DD + r;
        g_fvT_hi[idx] = __float2bfloat16(0.0f);
        g_fvT_mi[idx] = __float2bfloat16(0.0f);
    }
}

// ---------------------------------------------------------------------------
// K1: fused q/k/v 1x1-conv + pixel_unshuffle -> bf16 hi/mid split planes.
// ---------------------------------------------------------------------------
__global__ __launch_bounds__(192) void k_proj(
    const float* __restrict__ rgb, const float* __restrict__ depth,
    const float* __restrict__ Wq, const float* __restrict__ bq,
    const float* __restrict__ Wk, const float* __restrict__ bk,
    const float* __restrict__ Wv, const float* __restrict__ bv)
{
    __shared__ __align__(16) float Ws[16][97];
    __shared__ __align__(16) float Xd[16][130];
    __shared__ __align__(16) float Xr[16][130];

    const int blk  = blockIdx.x;
    const int b    = blk / 200;
    const int pix0 = (blk % 200) * 128;
    const int t  = threadIdx.x;
    const int tx = t & 15;
    const int ty = t >> 4;

    u64 acc[8][4];
#pragma unroll
    for (int r = 0; r < 8; r++)
#pragma unroll
        for (int p = 0; p < 4; p++) acc[r][p] = 0ull;

    const float* dbase = depth + (size_t)b*CHN*HW + pix0;
    const float* rbase = rgb   + (size_t)b*CHN*HW + pix0;

    for (int kc = 0; kc < CHN; kc += 16) {
#pragma unroll
        for (int ii = 0; ii < 8; ii++) {
            int i = t + ii*192;
            int r = i >> 4, kk = i & 15;
            const float* wrow = (r < 32) ? (Wq + r*CHN)
                               : ((r < 64) ? (Wv + (r-32)*CHN) : (Wk + (r-64)*CHN));
            Ws[kk][r] = wrow[kc + kk];
        }
        for (int i = t; i < 2048; i += 192) {
            int kk = i >> 7, p = i & 127;
            Xd[kk][p] = dbase[(size_t)(kc+kk)*HW + p];
            Xr[kk][p] = rbase[(size_t)(kc+kk)*HW + p];
        }
        __syncthreads();

        const float (*Xs)[130] = (ty < 8) ? Xd : Xr;
#pragma unroll
        for (int kk = 0; kk < 16; kk++) {
            u64 xv[4];
#pragma unroll
            for (int pp = 0; pp < 4; pp++)
                xv[pp] = *(const u64*)&Xs[kk][tx*2 + pp*32];
#pragma unroll
            for (int rr = 0; rr < 8; rr++) {
                float a = Ws[kk][ty*8 + rr];
                u64 aa = pk2(a, a);
#pragma unroll
                for (int pp = 0; pp < 4; pp++) ffma2(acc[rr][pp], aa, xv[pp]);
            }
        }
        __syncthreads();
    }

#pragma unroll
    for (int rr = 0; rr < 8; rr++) {
        int r = ty*8 + rr;
        int kind, c;
        const float* bias;
        if (r < 32)      { kind = 0; bias = bq; c = r; }
        else if (r < 64) { kind = 1; bias = bv; c = r - 32; }
        else             { kind = 2; bias = bk; c = r - 64; }
        float bb = bias[c];
#pragma unroll
        for (int pp = 0; pp < 4; pp++) {
            float2 v = upk2(acc[rr][pp]);
#pragma unroll
            for (int half = 0; half < 2; half++) {
                int p = pix0 + tx*2 + pp*32 + half;
                int h = p / 160, w = p - h*160;
                int dd = c*16 + (h & 3)*4 + (w & 3);
                int n  = (h >> 2)*40 + (w >> 2);
                float val = ((half == 0) ? v.x : v.y) + bb;
                __nv_bfloat16 hi, mi;
                split_bf16(val, hi, mi);
                if (kind == 0) {
                    size_t idx = ((size_t)b*DD + dd)*NN + n;
                    g_fq_hi[idx] = hi; g_fq_mi[idx] = mi;
                } else if (kind == 1) {
                    size_t idx = ((size_t)b*NNP + n)*DD + dd;   // transposed [n][e]
                    g_fvT_hi[idx] = hi; g_fvT_mi[idx] = mi;
                } else {
                    size_t idx = ((size_t)b*DD + dd)*NN + n;
                    g_fk_hi[idx] = hi; g_fk_mi[idx] = mi;
                }
            }
        }
    }
}

// ---------------------------------------------------------------------------
// Generic 128x128-tile mma.sync bf16-split3 GEMM:
//   C[b, m, n] = sum_k A[b,m,k] * B[b,n,k]   (both K-major, bf16 hi/mid)
// MODE 0: scores (A=fq, B=fk, K=1600, C=g_sc [512x512])
// MODE 1: attn@V (A=attn, B=fvT, K=512,  C=g_op [512x1600])
// 256 threads = 8 warps (2 m-groups x 4 n-groups), warp tile 64x32.
// Double-buffered cp.async, K-chunk 64 (128B SW128 rows, conflict-free ldsm).
// ---------------------------------------------------------------------------
template<int MODE>
__global__ __launch_bounds__(256) void k_gemm()
{
    constexpr int K    = (MODE == 0) ? 1600 : 512;
    constexpr int LD   = (MODE == 0) ? 1600 : 512;      // lda == ldb
    constexpr int LDC  = (MODE == 0) ? 512  : 1600;
    constexpr long SA  = (MODE == 0) ? (long)DD*NN : (long)DD*DD;
    constexpr long SB  = (MODE == 0) ? (long)DD*NN : (long)NNP*DD;
    constexpr long SC  = (MODE == 0) ? (long)DD*DD : (long)DD*NN;
    constexpr int NLIM = (MODE == 0) ? 512 : 1600;
    constexpr int NCH  = K / 64;

    extern __shared__ __align__(1024) char dsm[];   // 2 stages x 64KB

    const int b  = blockIdx.z;
    const int m0 = blockIdx.y * 128;
    const int n0 = blockIdx.x * 128;
    const int t    = threadIdx.x;
    const int lane = t & 31;
    const int wid  = t >> 5;
    const int wm   = wid & 1;          // m-group: 0/1 -> rows 0-63 / 64-127
    const int wn   = wid >> 1;         // n-group: 0..3 -> cols 32*wn

    const uint32_t smem_u = smem_u32(dsm);

    const __nv_bfloat16* Ahi = (MODE == 0 ? g_fq_hi : g_at_hi)  + b*SA + (long)m0*LD;
    const __nv_bfloat16* Ami = (MODE == 0 ? g_fq_mi : g_at_mi)  + b*SA + (long)m0*LD;
    const __nv_bfloat16* Bhi = (MODE == 0 ? g_fk_hi : g_fvT_hi) + b*SB + (long)n0*LD;
    const __nv_bfloat16* Bmi = (MODE == 0 ? g_fk_mi : g_fvT_mi) + b*SB + (long)n0*LD;
    float* C = (MODE == 0 ? g_sc : g_op) + b*SC;

    // stage layout: [s*64K] A_hi(16K) | A_mi(16K) | B_hi(16K) | B_mi(16K)
    auto load_stage = [&](int s, int kc) {
        uint32_t base = smem_u + s*65536;
#pragma unroll
        for (int ii = 0; ii < 4; ii++) {
            int i = t + ii*256;            // 1024 = 128 rows x 8 segs
            int row = i >> 3, seg = i & 7;
            uint32_t off = row*128 + seg*16;
            uint32_t sw  = off ^ ((off >> 3) & 0x70);
            long go = (long)row*LD + kc;
            cpa16(base + sw,         (const char*)(Ahi + go) + seg*16);
            cpa16(base + 16384 + sw, (const char*)(Ami + go) + seg*16);
            cpa16(base + 32768 + sw, (const char*)(Bhi + go) + seg*16);
            cpa16(base + 49152 + sw, (const char*)(Bmi + go) + seg*16);
        }
        CPA_COMMIT();
    };

    float acc[4][4][4];
#pragma unroll
    for (int i = 0; i < 4; i++)
#pragma unroll
        for (int j = 0; j < 4; j++)
#pragma unroll
            for (int r = 0; r < 4; r++) acc[i][j][r] = 0.0f;

    load_stage(0, 0);
    load_stage(1, 64);

    const int lr = lane & 15;          // ldmatrix row within 16
    const int lc = lane >> 4;          // ldmatrix col-half (0/1 -> +0/+16B)

    for (int c = 0; c < NCH; c++) {
        const int s = c & 1;
        if (c + 1 < NCH) asm volatile("cp.async.wait_group 1;" ::: "memory");
        else             asm volatile("cp.async.wait_group 0;" ::: "memory");
        __syncthreads();

        const uint32_t base = smem_u + s*65536;
#pragma unroll
        for (int kk = 0; kk < 4; kk++) {
            uint32_t a_hi[4][4], a_mi[4][4];
#pragma unroll
            for (int mt = 0; mt < 4; mt++) {
                int row = wm*64 + mt*16 + lr;
                uint32_t off = row*128 + kk*32 + lc*16;
                uint32_t sw  = off ^ ((off >> 3) & 0x70);
                ldsm4(a_hi[mt], base + sw);
                ldsm4(a_mi[mt], base + 16384 + sw);
            }
            uint32_t b_hi[2][4], b_mi[2][4];
#pragma unroll
            for (int bt = 0; bt < 2; bt++) {
                int row = wn*32 + bt*16 + lr;
                uint32_t off = row*128 + kk*32 + lc*16;
                uint32_t sw  = off ^ ((off >> 3) & 0x70);
                ldsm4(b_hi[bt], base + 32768 + sw);
                ldsm4(b_mi[bt], base + 49152 + sw);
            }
#pragma unroll
            for (int mt = 0; mt < 4; mt++) {
#pragma unroll
                for (int nt = 0; nt < 4; nt++) {
                    int bt = nt >> 1, hf = nt & 1;
                    mma_bf16(acc[mt][nt], a_hi[mt], b_hi[bt][hf], b_hi[bt][hf+2]);
                    mma_bf16(acc[mt][nt], a_hi[mt], b_mi[bt][hf], b_mi[bt][hf+2]);
                    mma_bf16(acc[mt][nt], a_mi[mt], b_hi[bt][hf], b_hi[bt][hf+2]);
                }
            }
        }
        __syncthreads();
        if (c + 2 < NCH) load_stage(s, (c + 2)*64);
    }

    // epilogue: registers -> gmem (float2)
    const int rq = lane >> 2;          // row within m16 tile (0..7)
    const int cq = (lane & 3) * 2;     // col within n8 tile
#pragma unroll
    for (int mt = 0; mt < 4; mt++) {
#pragma unroll
        for (int nt = 0; nt < 4; nt++) {
            int col = n0 + wn*32 + nt*8 + cq;
            if (col < NLIM) {
                int row = m0 + wm*64 + mt*16 + rq;
                float* p0 = C + (long)row*LDC + col;
                *(float2*)p0              = make_float2(acc[mt][nt][0], acc[mt][nt][1]);
                *(float2*)(p0 + 8L*LDC)   = make_float2(acc[mt][nt][2], acc[mt][nt][3]);
            }
        }
    }
}

// ---------------------------------------------------------------------------
// K3: softmax over rows of g_sc, writes attn as bf16 hi/mid split.
// ---------------------------------------------------------------------------
__global__ __launch_bounds__(128) void k_softmax()
{
    __shared__ float red[8];
    const size_t row = blockIdx.x;
    const float* s = g_sc + row * DD;
    const int t = threadIdx.x;

    float v0 = s[t], v1 = s[t+128], v2 = s[t+256], v3 = s[t+384];
    float m = fmaxf(fmaxf(v0, v1), fmaxf(v2, v3));
#pragma unroll
    for (int o = 16; o; o >>= 1) m = fmaxf(m, __shfl_xor_sync(0xffffffffu, m, o));
    if ((t & 31) == 0) red[t >> 5] = m;
    __syncthreads();
    m = fmaxf(fmaxf(red[0], red[1]), fmaxf(red[2], red[3]));

    const float inv = 0.04419417382415922f;  // 1/sqrt(512)
    float e0 = __expf((v0 - m) * inv);
    float e1 = __expf((v1 - m) * inv);
    float e2 = __expf((v2 - m) * inv);
    float e3 = __expf((v3 - m) * inv);
    float sum = e0 + e1 + e2 + e3;
#pragma unroll
    for (int o = 16; o; o >>= 1) sum += __shfl_xor_sync(0xffffffffu, sum, o);
    if ((t & 31) == 0) red[4 + (t >> 5)] = sum;
    __syncthreads();
    float r = 1.0f / (red[4] + red[5] + red[6] + red[7]);

    size_t base = row * DD;
    __nv_bfloat16 hi, mi;
    float a;
    a = e0 * r; split_bf16(a, hi, mi); g_at_hi[base + t]       = hi; g_at_mi[base + t]       = mi;
    a = e1 * r; split_bf16(a, hi, mi); g_at_hi[base + t + 128] = hi; g_at_mi[base + t + 128] = mi;
    a = e2 * r; split_bf16(a, hi, mi); g_at_hi[base + t + 256] = hi; g_at_mi[base + t + 256] = mi;
    a = e3 * r; split_bf16(a, hi, mi); g_at_hi[base + t + 384] = hi; g_at_mi[base + t + 384] = mi;
}

// ---------------------------------------------------------------------------
// K5: pixel_shuffle gather + final 1x1 conv (32 -> 256) + bias. (fp32 FFMA2)
// ---------------------------------------------------------------------------
__global__ __launch_bounds__(256) void k_final(
    const float* __restrict__ Wu, const float* __restrict__ bu,
    float* __restrict__ out)
{
    __shared__ __align__(16) float Ws2[32][257];
    __shared__ __align__(16) float Xs[32][66];

    const int blk  = blockIdx.x;
    const int b    = blk / 400;
    const int pix0 = (blk % 400) * 64;
    const int t  = threadIdx.x;
    const int tx = t & 7, ty = t >> 3;

#pragma unroll
    for (int ii = 0; ii < 32; ii++) {
        int i = t + ii*256;
        int ch = i >> 5, c = i & 31;
        Ws2[c][ch] = Wu[i];
    }
#pragma unroll
    for (int ii = 0; ii < 8; ii++) {
        int i = t + ii*256;
        int c = i >> 6, p = i & 63;
        int px = pix0 + p;
        int h = px / 160, w = px - h*160;
        int dd = c*16 + (h & 3)*4 + (w & 3);
        int n  = (h >> 2)*40 + (w >> 2);
        Xs[c][p] = g_op[((size_t)b*DD + dd)*NN + n];
    }
    __syncthreads();

    u64 acc[8][4];
#pragma unroll
    for (int r = 0; r < 8; r++)
#pragma unroll
        for (int p = 0; p < 4; p++) acc[r][p] = 0ull;

#pragma unroll 8
    for (int c = 0; c < 32; c++) {
        u64 xv[4];
#pragma unroll
        for (int pp = 0; pp < 4; pp++)
            xv[pp] = *(const u64*)&Xs[c][tx*2 + pp*16];
#pragma unroll
        for (int rr = 0; rr < 8; rr++) {
            float a = Ws2[c][ty*8 + rr];
            u64 aa = pk2(a, a);
#pragma unroll
            for (int pp = 0; pp < 4; pp++) ffma2(acc[rr][pp], aa, xv[pp]);
        }
    }

#pragma unroll
    for (int rr = 0; rr < 8; rr++) {
        int ch = ty*8 + rr;
        float bb = bu[ch];
        float* ob = out + ((size_t)b*CHN + ch)*HW + pix0;
#pragma unroll
        for (int pp = 0; pp < 4; pp++) {
            float2 v = upk2(acc[rr][pp]);
            v.x += bb; v.y += bb;
            *(float2*)&ob[tx*2 + pp*16] = v;
        }
    }
}

// ---------------------------------------------------------------------------
extern "C" void kernel_launch(void* const* d_in, const int* in_sizes, int n_in,
                              void* d_out, int out_size)
{
    (void)in_sizes; (void)n_in; (void)out_size;
    const float* rgb   = (const float*)d_in[0];
    const float* depth = (const float*)d_in[1];
    const float* Wq    = (const float*)d_in[2];
    const float* bq    = (const float*)d_in[3];
    const float* Wk    = (const float*)d_in[4];
    const float* bk    = (const float*)d_in[5];
    const float* Wv    = (const float*)d_in[6];
    const float* bv    = (const float*)d_in[7];
    const float* Wu    = (const float*)d_in[8];
    const float* bu    = (const float*)d_in[9];
    float* out = (float*)d_out;

    cudaFuncSetAttribute(k_gemm<0>, cudaFuncAttributeMaxDynamicSharedMemorySize, 131072);
    cudaFuncSetAttribute(k_gemm<1>, cudaFuncAttributeMaxDynamicSharedMemorySize, 131072);

    k_zero   <<<(NB*64*DD + 255)/256, 256>>>();
    k_proj   <<<1600, 192>>>(rgb, depth, Wq, bq, Wk, bk, Wv, bv);
    k_gemm<0><<<dim3(4, 4, NB), 256, 131072>>>();
    k_softmax<<<NB*DD, 128>>>();
    k_gemm<1><<<dim3(13, 4, NB), 256, 131072>>>();
    k_final  <<<3200, 256>>>(Wu, bu, out);
}

// round 4
// speedup vs baseline: 1.4586x; 1.0546x over previous
#include <cuda_runtime.h>
#include <cuda_bf16.h>
#include <cstdint>

#define NB  8
#define CHN 256
#define HW  25600
#define DD  512
#define NN  1600
#define NNP 1664

// ---------------- scratch (__device__ globals; allocation-free) ------------
__device__ float g_sc[NB*DD*DD];    // scores fp32
__device__ float g_op[NB*DD*NN];    // attn@V output fp32
__device__ __align__(128) __nv_bfloat16 g_fq_hi[NB*DD*NN];
__device__ __align__(128) __nv_bfloat16 g_fq_mi[NB*DD*NN];
__device__ __align__(128) __nv_bfloat16 g_fk_hi[NB*DD*NN];
__device__ __align__(128) __nv_bfloat16 g_fk_mi[NB*DD*NN];
__device__ __align__(128) __nv_bfloat16 g_fvT_hi[NB*NNP*DD];
__device__ __align__(128) __nv_bfloat16 g_fvT_mi[NB*NNP*DD];
__device__ __align__(128) __nv_bfloat16 g_at_hi[NB*DD*DD];
__device__ __align__(128) __nv_bfloat16 g_at_mi[NB*DD*DD];
__device__ __align__(128) __nv_bfloat16 g_w_hi[96*256];   // qkv weights split
__device__ __align__(128) __nv_bfloat16 g_w_mi[96*256];

typedef unsigned long long u64;

// ---------------- PTX helpers (baseline ISA only) ---------------------------
__device__ __forceinline__ void ffma2(u64 &acc, u64 a, u64 b) {
    asm("fma.rn.f32x2 %0, %1, %2, %0;" : "+l"(acc) : "l"(a), "l"(b));
}
__device__ __forceinline__ u64 pk2(float x, float y) {
    u64 r; asm("mov.b64 %0, {%1, %2};" : "=l"(r) : "f"(x), "f"(y)); return r;
}
__device__ __forceinline__ float2 upk2(u64 v) {
    float2 f; asm("mov.b64 {%0, %1}, %2;" : "=f"(f.x), "=f"(f.y) : "l"(v)); return f;
}
__device__ __forceinline__ uint32_t smem_u32(const void* p) {
    uint32_t a;
    asm("{ .reg .u64 t; cvta.to.shared.u64 t, %1; cvt.u32.u64 %0, t; }" : "=r"(a) : "l"(p));
    return a;
}
__device__ __forceinline__ void cpa16(uint32_t s, const void* g) {
    asm volatile("cp.async.cg.shared.global [%0], [%1], 16;" :: "r"(s), "l"(g));
}
#define CPA_COMMIT() asm volatile("cp.async.commit_group;" ::: "memory")

__device__ __forceinline__ void ldsm4(uint32_t* r, uint32_t a) {
    asm volatile("ldmatrix.sync.aligned.m8n8.x4.shared.b16 {%0,%1,%2,%3}, [%4];"
        : "=r"(r[0]), "=r"(r[1]), "=r"(r[2]), "=r"(r[3]) : "r"(a));
}
__device__ __forceinline__ void ldsm4t(uint32_t* r, uint32_t a) {
    asm volatile("ldmatrix.sync.aligned.m8n8.x4.trans.shared.b16 {%0,%1,%2,%3}, [%4];"
        : "=r"(r[0]), "=r"(r[1]), "=r"(r[2]), "=r"(r[3]) : "r"(a));
}
__device__ __forceinline__ void mma_bf16(float* d, const uint32_t* a, uint32_t b0, uint32_t b1) {
    asm volatile(
        "mma.sync.aligned.m16n8k16.row.col.f32.bf16.bf16.f32 "
        "{%0,%1,%2,%3},{%4,%5,%6,%7},{%8,%9},{%0,%1,%2,%3};"
        : "+f"(d[0]), "+f"(d[1]), "+f"(d[2]), "+f"(d[3])
        : "r"(a[0]), "r"(a[1]), "r"(a[2]), "r"(a[3]), "r"(b0), "r"(b1));
}

__device__ __forceinline__ void split_bf16(float v, __nv_bfloat16 &h, __nv_bfloat16 &m) {
    h = __float2bfloat16(v);
    m = __float2bfloat16(v - __bfloat162float(h));
}
__device__ __forceinline__ uint32_t pack2bf(__nv_bfloat16 a, __nv_bfloat16 b) {
    __nv_bfloat162 t(a, b);
    return *(uint32_t*)&t;
}

// ---------------------------------------------------------------------------
// K-1: split W q/v/k rows (0-31 q, 32-63 v, 64-95 k) into bf16 hi/mid planes.
// ---------------------------------------------------------------------------
__global__ __launch_bounds__(256) void k_wsplit(
    const float* __restrict__ Wq, const float* __restrict__ Wv, const float* __restrict__ Wk)
{
    int i = blockIdx.x * 256 + threadIdx.x;
    if (i >= 96*256) return;
    int r = i >> 8, kk = i & 255;
    float v = (r < 32) ? Wq[r*256 + kk] : ((r < 64) ? Wv[(r-32)*256 + kk] : Wk[(r-64)*256 + kk]);
    __nv_bfloat16 h, m;
    split_bf16(v, h, m);
    g_w_hi[i] = h; g_w_mi[i] = m;
}

// ---------------------------------------------------------------------------
// K0: zero the fvT padding rows (n = 1600..1663).
// ---------------------------------------------------------------------------
__global__ __launch_bounds__(256) void k_zero()
{
    int i = blockIdx.x * 256 + threadIdx.x;
    if (i < NB*64*DD) {
        int b = i / (64*DD);
        int r = i - b*(64*DD);
        size_t idx = (size_t)b*NNP*DD + (size_t)NN*DD + r;
        g_fvT_hi[idx] = __float2bfloat16(0.0f);
        g_fvT_mi[idx] = __float2bfloat16(0.0f);
    }
}

// ---------------------------------------------------------------------------
// K1: tensor-core fused q/k/v 1x1 conv + pixel_unshuffle.
// C[96 rows][256 pix] per CTA; rows 0-31 q(depth), 32-63 v(depth), 64-95 k(rgb).
// A = W bf16 hi/mid (smem, ldmatrix). B = x, staged fp32->regs->split bf16 smem
// in [cin][pix] layout, consumed via ldmatrix.trans. Split-3 accumulation.
// smem: W planes 2x48KB @0/49152; x stages @98304: s*32768 + plane*8192
//       (plane: 0=d_hi 1=d_mi 2=r_hi 3=r_mi), each [32 cin][128 pix] bf16.
// ---------------------------------------------------------------------------
__global__ __launch_bounds__(256, 1) void k_projT(
    const float* __restrict__ rgb, const float* __restrict__ depth,
    const float* __restrict__ bq, const float* __restrict__ bk,
    const float* __restrict__ bv)
{
    extern __shared__ __align__(1024) char sm[];
    const int b   = blockIdx.x / 100;
    const int grp = blockIdx.x % 100;
    const int t = threadIdx.x, lane = t & 31, wid = t >> 5;
    const int wm = wid & 1, wn = wid >> 1;
    const uint32_t su = smem_u32(sm);
    const uint32_t XB = su + 98304;

    // ---- load W planes into smem (chunk ^ (m&7) swizzle, 512B row pitch) ----
    for (int i = t; i < 96*32; i += 256) {
        int m = i >> 5, c = i & 31;
        uint4 v1 = *(const uint4*)((const char*)g_w_hi + m*512 + c*16);
        uint4 v2 = *(const uint4*)((const char*)g_w_mi + m*512 + c*16);
        int sw = (c ^ (m & 7)) * 16;
        *(uint4*)(sm + m*512 + sw)         = v1;
        *(uint4*)(sm + 49152 + m*512 + sw) = v2;
    }

    // bias / row-kind precompute for this thread's 6 output rows
    float bias_v[3][2];
#pragma unroll
    for (int mt = 0; mt < 3; mt++) {
#pragma unroll
        for (int hh = 0; hh < 2; hh++) {
            int r = wm*48 + mt*16 + (lane >> 2) + hh*8;
            bias_v[mt][hh] = (r < 32) ? bq[r] : ((r < 64) ? bv[r-32] : bk[r-64]);
        }
    }
    __syncthreads();

    const float* dbase = depth + (size_t)b*CHN*HW;
    const float* rbase = rgb   + (size_t)b*CHN*HW;

    for (int sub = 0; sub < 2; sub++) {
        const int pixbase = grp*256 + sub*128;

        float4 rd[4], rr[4];
        auto ldg_chunk = [&](int c) {
#pragma unroll
            for (int it = 0; it < 4; it++) {
                int row = wid + it*8;
                size_t off = (size_t)(c*32 + row)*HW + pixbase + lane*4;
                rd[it] = *(const float4*)(dbase + off);
                rr[it] = *(const float4*)(rbase + off);
            }
        };
        auto sts_chunk = [&](int s) {
            uint32_t base = XB + s*32768;
#pragma unroll
            for (int it = 0; it < 4; it++) {
                int k = wid + it*8;
                int sw = ((lane >> 1) ^ (k & 7)) * 16 + (lane & 1) * 8;
                uint32_t a = base + k*256 + sw;
                __nv_bfloat16 h0,m0,h1,m1,h2,m2,h3,m3;
                split_bf16(rd[it].x, h0, m0); split_bf16(rd[it].y, h1, m1);
                split_bf16(rd[it].z, h2, m2); split_bf16(rd[it].w, h3, m3);
                uint2 vh = make_uint2(pack2bf(h0,h1), pack2bf(h2,h3));
                uint2 vm = make_uint2(pack2bf(m0,m1), pack2bf(m2,m3));
                *(uint2*)(sm + (a - su))          = vh;
                *(uint2*)(sm + (a - su) + 8192)   = vm;
                split_bf16(rr[it].x, h0, m0); split_bf16(rr[it].y, h1, m1);
                split_bf16(rr[it].z, h2, m2); split_bf16(rr[it].w, h3, m3);
                vh = make_uint2(pack2bf(h0,h1), pack2bf(h2,h3));
                vm = make_uint2(pack2bf(m0,m1), pack2bf(m2,m3));
                *(uint2*)(sm + (a - su) + 16384)  = vh;
                *(uint2*)(sm + (a - su) + 24576)  = vm;
            }
        };

        float acc[3][4][4];
#pragma unroll
        for (int i = 0; i < 3; i++)
#pragma unroll
            for (int j = 0; j < 4; j++)
#pragma unroll
                for (int r = 0; r < 4; r++) acc[i][j][r] = 0.0f;

        ldg_chunk(0);
        sts_chunk(0);
        ldg_chunk(1);

        for (int c = 0; c < 8; c++) {
            __syncthreads();                    // prev MMA done; STS(c) visible
            if (c + 1 < 8) sts_chunk((c + 1) & 1);
            if (c + 2 < 8) ldg_chunk(c + 2);
            __syncthreads();                    // STS(c+1) ordered; MMA reads stage c&1

            const uint32_t xs = XB + (c & 1)*32768;
#pragma unroll
            for (int kk = 0; kk < 2; kk++) {
                uint32_t ah[3][4], am[3][4];
#pragma unroll
                for (int mt = 0; mt < 3; mt++) {
                    int m = wm*48 + mt*16 + (lane & 15);
                    int ca = c*4 + kk*2 + (lane >> 4);
                    uint32_t addr = su + m*512 + ((ca ^ (m & 7)) & 31)*16;
                    ldsm4(ah[mt], addr);
                    ldsm4(am[mt], addr + 49152);
                }
                uint32_t bh[2][2][4], bm[2][2][4];   // [src d/r][ln][reg]
                int krow = kk*16 + (lane & 15);
                int cb = wn*4 + (lane >> 4);
#pragma unroll
                for (int ln = 0; ln < 2; ln++) {
                    uint32_t addr = xs + krow*256 + (((cb + ln*2) ^ (krow & 7)) & 15)*16;
                    ldsm4t(bh[0][ln], addr);
                    ldsm4t(bm[0][ln], addr + 8192);
                    if (wm == 1) {
                        ldsm4t(bh[1][ln], addr + 16384);
                        ldsm4t(bm[1][ln], addr + 24576);
                    }
                }
#pragma unroll
                for (int mt = 0; mt < 3; mt++) {
                    int src = (wm*3 + mt < 4) ? 0 : 1;
#pragma unroll
                    for (int nt = 0; nt < 4; nt++) {
                        int ln = nt >> 1, hf = nt & 1;
                        uint32_t b0h = bh[src][ln][hf*2], b1h = bh[src][ln][hf*2+1];
                        uint32_t b0m = bm[src][ln][hf*2], b1m = bm[src][ln][hf*2+1];
                        mma_bf16(acc[mt][nt], ah[mt], b0h, b1h);
                        mma_bf16(acc[mt][nt], ah[mt], b0m, b1m);
                        mma_bf16(acc[mt][nt], am[mt], b0h, b1h);
                    }
                }
            }
        }

        // ---- epilogue: bias + split + pixel_unshuffle scatter ----
#pragma unroll
        for (int mt = 0; mt < 3; mt++) {
#pragma unroll
            for (int hh = 0; hh < 2; hh++) {
                int r = wm*48 + mt*16 + (lane >> 2) + hh*8;
                int kind, cch;
                if (r < 32)      { kind = 0; cch = r; }
                else if (r < 64) { kind = 1; cch = r - 32; }
                else             { kind = 2; cch = r - 64; }
                float bb = bias_v[mt][hh];
#pragma unroll
                for (int nt = 0; nt < 4; nt++) {
#pragma unroll
                    for (int half = 0; half < 2; half++) {
                        float val = acc[mt][nt][hh*2 + half] + bb;
                        int p = pixbase + wn*32 + nt*8 + (lane & 3)*2 + half;
                        int h = p / 160, w = p - h*160;
                        int dd = cch*16 + (h & 3)*4 + (w & 3);
                        int n  = (h >> 2)*40 + (w >> 2);
                        __nv_bfloat16 hi, mi;
                        split_bf16(val, hi, mi);
                        if (kind == 0) {
                            size_t idx = ((size_t)b*DD + dd)*NN + n;
                            g_fq_hi[idx] = hi; g_fq_mi[idx] = mi;
                        } else if (kind == 1) {
                            size_t idx = ((size_t)b*NNP + n)*DD + dd;
                            g_fvT_hi[idx] = hi; g_fvT_mi[idx] = mi;
                        } else {
                            size_t idx = ((size_t)b*DD + dd)*NN + n;
                            g_fk_hi[idx] = hi; g_fk_mi[idx] = mi;
                        }
                    }
                }
            }
        }
        __syncthreads();
    }
}

// ---------------------------------------------------------------------------
// Generic 128x128-tile mma.sync bf16-split3 GEMM (unchanged from round 3).
// ---------------------------------------------------------------------------
template<int MODE>
__global__ __launch_bounds__(256) void k_gemm()
{
    constexpr int K    = (MODE == 0) ? 1600 : 512;
    constexpr int LD   = (MODE == 0) ? 1600 : 512;
    constexpr int LDC  = (MODE == 0) ? 512  : 1600;
    constexpr long SA  = (MODE == 0) ? (long)DD*NN : (long)DD*DD;
    constexpr long SB  = (MODE == 0) ? (long)DD*NN : (long)NNP*DD;
    constexpr long SC  = (MODE == 0) ? (long)DD*DD : (long)DD*NN;
    constexpr int NLIM = (MODE == 0) ? 512 : 1600;
    constexpr int NCH  = K / 64;

    extern __shared__ __align__(1024) char dsm[];

    const int b  = blockIdx.z;
    const int m0 = blockIdx.y * 128;
    const int n0 = blockIdx.x * 128;
    const int t    = threadIdx.x;
    const int lane = t & 31;
    const int wid  = t >> 5;
    const int wm   = wid & 1;
    const int wn   = wid >> 1;

    const uint32_t smem_u = smem_u32(dsm);

    const __nv_bfloat16* Ahi = (MODE == 0 ? g_fq_hi : g_at_hi)  + b*SA + (long)m0*LD;
    const __nv_bfloat16* Ami = (MODE == 0 ? g_fq_mi : g_at_mi)  + b*SA + (long)m0*LD;
    const __nv_bfloat16* Bhi = (MODE == 0 ? g_fk_hi : g_fvT_hi) + b*SB + (long)n0*LD;
    const __nv_bfloat16* Bmi = (MODE == 0 ? g_fk_mi : g_fvT_mi) + b*SB + (long)n0*LD;
    float* C = (MODE == 0 ? g_sc : g_op) + b*SC;

    auto load_stage = [&](int s, int kc) {
        uint32_t base = smem_u + s*65536;
#pragma unroll
        for (int ii = 0; ii < 4; ii++) {
            int i = t + ii*256;
            int row = i >> 3, seg = i & 7;
            uint32_t off = row*128 + seg*16;
            uint32_t sw  = off ^ ((off >> 3) & 0x70);
            long go = (long)row*LD + kc;
            cpa16(base + sw,         (const char*)(Ahi + go) + seg*16);
            cpa16(base + 16384 + sw, (const char*)(Ami + go) + seg*16);
            cpa16(base + 32768 + sw, (const char*)(Bhi + go) + seg*16);
            cpa16(base + 49152 + sw, (const char*)(Bmi + go) + seg*16);
        }
        CPA_COMMIT();
    };

    float acc[4][4][4];
#pragma unroll
    for (int i = 0; i < 4; i++)
#pragma unroll
        for (int j = 0; j < 4; j++)
#pragma unroll
            for (int r = 0; r < 4; r++) acc[i][j][r] = 0.0f;

    load_stage(0, 0);
    load_stage(1, 64);

    const int lr = lane & 15;
    const int lc = lane >> 4;

    for (int c = 0; c < NCH; c++) {
        const int s = c & 1;
        if (c + 1 < NCH) asm volatile("cp.async.wait_group 1;" ::: "memory");
        else             asm volatile("cp.async.wait_group 0;" ::: "memory");
        __syncthreads();

        const uint32_t base = smem_u + s*65536;
#pragma unroll
        for (int kk = 0; kk < 4; kk++) {
            uint32_t a_hi[4][4], a_mi[4][4];
#pragma unroll
            for (int mt = 0; mt < 4; mt++) {
                int row = wm*64 + mt*16 + lr;
                uint32_t off = row*128 + kk*32 + lc*16;
                uint32_t sw  = off ^ ((off >> 3) & 0x70);
                ldsm4(a_hi[mt], base + sw);
                ldsm4(a_mi[mt], base + 16384 + sw);
            }
            uint32_t b_hi[2][4], b_mi[2][4];
#pragma unroll
            for (int bt = 0; bt < 2; bt++) {
                int row = wn*32 + bt*16 + lr;
                uint32_t off = row*128 + kk*32 + lc*16;
                uint32_t sw  = off ^ ((off >> 3) & 0x70);
                ldsm4(b_hi[bt], base + 32768 + sw);
                ldsm4(b_mi[bt], base + 49152 + sw);
            }
#pragma unroll
            for (int mt = 0; mt < 4; mt++) {
#pragma unroll
                for (int nt = 0; nt < 4; nt++) {
                    int bt = nt >> 1, hf = nt & 1;
                    mma_bf16(acc[mt][nt], a_hi[mt], b_hi[bt][hf], b_hi[bt][hf+2]);
                    mma_bf16(acc[mt][nt], a_hi[mt], b_mi[bt][hf], b_mi[bt][hf+2]);
                    mma_bf16(acc[mt][nt], a_mi[mt], b_hi[bt][hf], b_hi[bt][hf+2]);
                }
            }
        }
        __syncthreads();
        if (c + 2 < NCH) load_stage(s, (c + 2)*64);
    }

    const int rq = lane >> 2;
    const int cq = (lane & 3) * 2;
#pragma unroll
    for (int mt = 0; mt < 4; mt++) {
#pragma unroll
        for (int nt = 0; nt < 4; nt++) {
            int col = n0 + wn*32 + nt*8 + cq;
            if (col < NLIM) {
                int row = m0 + wm*64 + mt*16 + rq;
                float* p0 = C + (long)row*LDC + col;
                *(float2*)p0              = make_float2(acc[mt][nt][0], acc[mt][nt][1]);
                *(float2*)(p0 + 8L*LDC)   = make_float2(acc[mt][nt][2], acc[mt][nt][3]);
            }
        }
    }
}

// ---------------------------------------------------------------------------
// K3: softmax over rows of g_sc, writes attn as bf16 hi/mid split.
// ---------------------------------------------------------------------------
__global__ __launch_bounds__(128) void k_softmax()
{
    __shared__ float red[8];
    const size_t row = blockIdx.x;
    const float* s = g_sc + row * DD;
    const int t = threadIdx.x;

    float v0 = s[t], v1 = s[t+128], v2 = s[t+256], v3 = s[t+384];
    float m = fmaxf(fmaxf(v0, v1), fmaxf(v2, v3));
#pragma unroll
    for (int o = 16; o; o >>= 1) m = fmaxf(m, __shfl_xor_sync(0xffffffffu, m, o));
    if ((t & 31) == 0) red[t >> 5] = m;
    __syncthreads();
    m = fmaxf(fmaxf(red[0], red[1]), fmaxf(red[2], red[3]));

    const float inv = 0.04419417382415922f;  // 1/sqrt(512)
    float e0 = __expf((v0 - m) * inv);
    float e1 = __expf((v1 - m) * inv);
    float e2 = __expf((v2 - m) * inv);
    float e3 = __expf((v3 - m) * inv);
    float sum = e0 + e1 + e2 + e3;
#pragma unroll
    for (int o = 16; o; o >>= 1) sum += __shfl_xor_sync(0xffffffffu, sum, o);
    if ((t & 31) == 0) red[4 + (t >> 5)] = sum;
    __syncthreads();
    float r = 1.0f / (red[4] + red[5] + red[6] + red[7]);

    size_t base = row * DD;
    __nv_bfloat16 hi, mi;
    float a;
    a = e0 * r; split_bf16(a, hi, mi); g_at_hi[base + t]       = hi; g_at_mi[base + t]       = mi;
    a = e1 * r; split_bf16(a, hi, mi); g_at_hi[base + t + 128] = hi; g_at_mi[base + t + 128] = mi;
    a = e2 * r; split_bf16(a, hi, mi); g_at_hi[base + t + 256] = hi; g_at_mi[base + t + 256] = mi;
    a = e3 * r; split_bf16(a, hi, mi); g_at_hi[base + t + 384] = hi; g_at_mi[base + t + 384] = mi;
}

// ---------------------------------------------------------------------------
// K5: pixel_shuffle gather + final 1x1 conv (32 -> 256) + bias. (fp32 FFMA2)
// ---------------------------------------------------------------------------
__global__ __launch_bounds__(256) void k_final(
    const float* __restrict__ Wu, const float* __restrict__ bu,
    float* __restrict__ out)
{
    __shared__ __align__(16) float Ws2[32][257];
    __shared__ __align__(16) float Xs[32][66];

    const int blk  = blockIdx.x;
    const int b    = blk / 400;
    const int pix0 = (blk % 400) * 64;
    const int t  = threadIdx.x;
    const int tx = t & 7, ty = t >> 3;

#pragma unroll
    for (int ii = 0; ii < 32; ii++) {
        int i = t + ii*256;
        int ch = i >> 5, c = i & 31;
        Ws2[c][ch] = Wu[i];
    }
#pragma unroll
    for (int ii = 0; ii < 8; ii++) {
        int i = t + ii*256;
        int c = i >> 6, p = i & 63;
        int px = pix0 + p;
        int h = px / 160, w = px - h*160;
        int dd = c*16 + (h & 3)*4 + (w & 3);
        int n  = (h >> 2)*40 + (w >> 2);
        Xs[c][p] = g_op[((size_t)b*DD + dd)*NN + n];
    }
    __syncthreads();

    u64 acc[8][4];
#pragma unroll
    for (int r = 0; r < 8; r++)
#pragma unroll
        for (int p = 0; p < 4; p++) acc[r][p] = 0ull;

#pragma unroll 8
    for (int c = 0; c < 32; c++) {
        u64 xv[4];
#pragma unroll
        for (int pp = 0; pp < 4; pp++)
            xv[pp] = *(const u64*)&Xs[c][tx*2 + pp*16];
#pragma unroll
        for (int rr = 0; rr < 8; rr++) {
            float a = Ws2[c][ty*8 + rr];
            u64 aa = pk2(a, a);
#pragma unroll
            for (int pp = 0; pp < 4; pp++) ffma2(acc[rr][pp], aa, xv[pp]);
        }
    }

#pragma unroll
    for (int rr = 0; rr < 8; rr++) {
        int ch = ty*8 + rr;
        float bb = bu[ch];
        float* ob = out + ((size_t)b*CHN + ch)*HW + pix0;
#pragma unroll
        for (int pp = 0; pp < 4; pp++) {
            float2 v = upk2(acc[rr][pp]);
            v.x += bb; v.y += bb;
            *(float2*)&ob[tx*2 + pp*16] = v;
        }
    }
}

// ---------------------------------------------------------------------------
extern "C" void kernel_launch(void* const* d_in, const int* in_sizes, int n_in,
                              void* d_out, int out_size)
{
    (void)in_sizes; (void)n_in; (void)out_size;
    const float* rgb   = (const float*)d_in[0];
    const float* depth = (const float*)d_in[1];
    const float* Wq    = (const float*)d_in[2];
    const float* bq    = (const float*)d_in[3];
    const float* Wk    = (const float*)d_in[4];
    const float* bk    = (const float*)d_in[5];
    const float* Wv    = (const float*)d_in[6];
    const float* bv    = (const float*)d_in[7];
    const float* Wu    = (const float*)d_in[8];
    const float* bu    = (const float*)d_in[9];
    float* out = (float*)d_out;

    cudaFuncSetAttribute(k_projT,  cudaFuncAttributeMaxDynamicSharedMemorySize, 163840);
    cudaFuncSetAttribute(k_gemm<0>, cudaFuncAttributeMaxDynamicSharedMemorySize, 131072);
    cudaFuncSetAttribute(k_gemm<1>, cudaFuncAttributeMaxDynamicSharedMemorySize, 131072);

    k_wsplit <<<96, 256>>>(Wq, Wv, Wk);
    k_zero   <<<(NB*64*DD + 255)/256, 256>>>();
    k_projT  <<<800, 256, 163840>>>(rgb, depth, bq, bk, bv);
    k_gemm<0><<<dim3(4, 4, NB), 256, 131072>>>();
    k_softmax<<<NB*DD, 128>>>();
    k_gemm<1><<<dim3(13, 4, NB), 256, 131072>>>();
    k_final  <<<3200, 256>>>(Wu, bu, out);
}

// round 5
// speedup vs baseline: 2.0101x; 1.3781x over previous
#include <cuda_runtime.h>
#include <cuda_bf16.h>
#include <cstdint>

#define NB  8
#define CHN 256
#define HW  25600
#define DD  512
#define NN  1600
#define NNP 1664

// ---------------- scratch (__device__ globals; allocation-free) ------------
__device__ float g_sc[NB*DD*DD];    // scores fp32 [d][e']
__device__ float g_op[NB*DD*NN];    // attn@V output fp32 [d][n]
__device__ __align__(128) __nv_bfloat16 g_fq_hi[NB*DD*NN];   // [d][n]
__device__ __align__(128) __nv_bfloat16 g_fq_mi[NB*DD*NN];
__device__ __align__(128) __nv_bfloat16 g_fk_hi[NB*DD*NN];   // [e'][n], e' = (i*4+j)*32+c
__device__ __align__(128) __nv_bfloat16 g_fk_mi[NB*DD*NN];
__device__ __align__(128) __nv_bfloat16 g_fvT_hi[NB*NNP*DD]; // [n][e']
__device__ __align__(128) __nv_bfloat16 g_fvT_mi[NB*NNP*DD];
__device__ __align__(128) __nv_bfloat16 g_at_hi[NB*DD*DD];   // [d][e']
__device__ __align__(128) __nv_bfloat16 g_at_mi[NB*DD*DD];
__device__ __align__(128) __nv_bfloat16 g_w_hi[96*256];      // qkv weights split
__device__ __align__(128) __nv_bfloat16 g_w_mi[96*256];

typedef unsigned long long u64;

// ---------------- PTX helpers (baseline ISA only) ---------------------------
__device__ __forceinline__ void ffma2(u64 &acc, u64 a, u64 b) {
    asm("fma.rn.f32x2 %0, %1, %2, %0;" : "+l"(acc) : "l"(a), "l"(b));
}
__device__ __forceinline__ u64 pk2(float x, float y) {
    u64 r; asm("mov.b64 %0, {%1, %2};" : "=l"(r) : "f"(x), "f"(y)); return r;
}
__device__ __forceinline__ float2 upk2(u64 v) {
    float2 f; asm("mov.b64 {%0, %1}, %2;" : "=f"(f.x), "=f"(f.y) : "l"(v)); return f;
}
__device__ __forceinline__ uint32_t smem_u32(const void* p) {
    uint32_t a;
    asm("{ .reg .u64 t; cvta.to.shared.u64 t, %1; cvt.u32.u64 %0, t; }" : "=r"(a) : "l"(p));
    return a;
}
__device__ __forceinline__ void cpa16(uint32_t s, const void* g) {
    asm volatile("cp.async.cg.shared.global [%0], [%1], 16;" :: "r"(s), "l"(g));
}
#define CPA_COMMIT() asm volatile("cp.async.commit_group;" ::: "memory")

__device__ __forceinline__ void ldsm4(uint32_t* r, uint32_t a) {
    asm volatile("ldmatrix.sync.aligned.m8n8.x4.shared.b16 {%0,%1,%2,%3}, [%4];"
        : "=r"(r[0]), "=r"(r[1]), "=r"(r[2]), "=r"(r[3]) : "r"(a));
}
__device__ __forceinline__ void ldsm4t(uint32_t* r, uint32_t a) {
    asm volatile("ldmatrix.sync.aligned.m8n8.x4.trans.shared.b16 {%0,%1,%2,%3}, [%4];"
        : "=r"(r[0]), "=r"(r[1]), "=r"(r[2]), "=r"(r[3]) : "r"(a));
}
__device__ __forceinline__ void ldsm2t(uint32_t* r, uint32_t a) {
    asm volatile("ldmatrix.sync.aligned.m8n8.x2.trans.shared.b16 {%0,%1}, [%2];"
        : "=r"(r[0]), "=r"(r[1]) : "r"(a));
}
__device__ __forceinline__ void mma_bf16(float* d, const uint32_t* a, uint32_t b0, uint32_t b1) {
    asm volatile(
        "mma.sync.aligned.m16n8k16.row.col.f32.bf16.bf16.f32 "
        "{%0,%1,%2,%3},{%4,%5,%6,%7},{%8,%9},{%0,%1,%2,%3};"
        : "+f"(d[0]), "+f"(d[1]), "+f"(d[2]), "+f"(d[3])
        : "r"(a[0]), "r"(a[1]), "r"(a[2]), "r"(a[3]), "r"(b0), "r"(b1));
}

__device__ __forceinline__ void split_bf16(float v, __nv_bfloat16 &h, __nv_bfloat16 &m) {
    h = __float2bfloat16(v);
    m = __float2bfloat16(v - __bfloat162float(h));
}
// fast pair split: hi = bit-truncation (PRMT-packed), mi = rn of residuals.
// hi = {lo: tr(a), hi: tr(b)},  mi = {lo: rn(a-tr(a)), hi: rn(b-tr(b))}
__device__ __forceinline__ void split2(float a, float b, uint32_t &hi, uint32_t &mi) {
    uint32_t ua = __float_as_uint(a), ub = __float_as_uint(b);
    hi = __byte_perm(ua, ub, 0x7632);
    float ra = a - __uint_as_float(ua & 0xFFFF0000u);
    float rb = b - __uint_as_float(ub & 0xFFFF0000u);
    asm("cvt.rn.bf16x2.f32 %0, %1, %2;" : "=r"(mi) : "f"(rb), "f"(ra));
}

// ---------------------------------------------------------------------------
// K-1: split W q/v/k rows (0-31 q, 32-63 v, 64-95 k) into bf16 hi/mid planes.
// ---------------------------------------------------------------------------
__global__ __launch_bounds__(256) void k_wsplit(
    const float* __restrict__ Wq, const float* __restrict__ Wv, const float* __restrict__ Wk)
{
    int i = blockIdx.x * 256 + threadIdx.x;
    if (i >= 96*256) return;
    int r = i >> 8, kk = i & 255;
    float v = (r < 32) ? Wq[r*256 + kk] : ((r < 64) ? Wv[(r-32)*256 + kk] : Wk[(r-64)*256 + kk]);
    __nv_bfloat16 h, m;
    split_bf16(v, h, m);
    g_w_hi[i] = h; g_w_mi[i] = m;
}

// ---------------------------------------------------------------------------
// K1: tensor-core fused q/k/v 1x1 conv + pixel_unshuffle, coalesced epilogue.
// CTA = (b, hp): pixels of rows h = 2hp, 2hp+1 (2 x 160). M=96 rows.
// Sub-loop over the 2 h-rows (N=160 each). K=256 in 8 chunks of 32.
// smem: W hi @0 (48K), W mi @49152 (48K); x stages @98304 (2 x 49152):
//   plane offsets within stage: d_hi 0, d_mi 12288, r_hi 24576, r_mi 36864;
//   each plane [32 cin][192 px pad] bf16 (384B rows, XOR-16B swizzle).
// Epilogue buffer overlays x region: [4 j][96 r][42 nw] f32.
// ---------------------------------------------------------------------------
__global__ __launch_bounds__(256, 1) void k_projT(
    const float* __restrict__ rgb, const float* __restrict__ depth,
    const float* __restrict__ bq, const float* __restrict__ bk,
    const float* __restrict__ bv)
{
    extern __shared__ __align__(1024) char sm[];
    const int b  = blockIdx.x / 80;
    const int hp = blockIdx.x % 80;
    const int t = threadIdx.x, lane = t & 31, wid = t >> 5;
    const int wm = wid & 1, wn = wid >> 1;
    const uint32_t su = smem_u32(sm);
    const uint32_t XB = su + 98304;
    float* const epi = (float*)(sm + 98304);

    // ---- W planes into smem (32x16B chunks/row, chunk ^ (m&7) swizzle) ----
    for (int i = t; i < 96*32; i += 256) {
        int m = i >> 5, c = i & 31;
        uint4 v1 = *(const uint4*)((const char*)g_w_hi + m*512 + c*16);
        uint4 v2 = *(const uint4*)((const char*)g_w_mi + m*512 + c*16);
        int sw = (c ^ (m & 7)) * 16;
        *(uint4*)(sm + m*512 + sw)         = v1;
        *(uint4*)(sm + 49152 + m*512 + sw) = v2;
    }

    float bias_v[3][2];
#pragma unroll
    for (int mt = 0; mt < 3; mt++)
#pragma unroll
        for (int hh = 0; hh < 2; hh++) {
            int r = wm*48 + mt*16 + (lane >> 2) + hh*8;
            bias_v[mt][hh] = (r < 32) ? bq[r] : ((r < 64) ? bv[r-32] : bk[r-64]);
        }

    // per-thread ldg mapping (j<5 depth, j>=5 rgb)
    int cin_[10], c4_[10];
#pragma unroll
    for (int j = 0; j < 10; j++) {
        int ii = (t + j*256) % 1280;
        cin_[j] = ii / 40; c4_[j] = ii % 40;
    }
    __syncthreads();

    const float* dbase = depth + (size_t)b*CHN*HW;
    const float* rbase = rgb   + (size_t)b*CHN*HW;

    for (int sub = 0; sub < 2; sub++) {
        const int h  = hp*2 + sub;
        const int ip = h & 3, hn = h >> 2;
        const size_t rowoff = (size_t)h * 160;

        float4 rv[10];
        auto ldg_chunk = [&](int c) {
#pragma unroll
            for (int j = 0; j < 10; j++) {
                const float* bp = (j < 5) ? dbase : rbase;
                rv[j] = *(const float4*)(bp + (size_t)(c*32 + cin_[j])*HW + rowoff + c4_[j]*4);
            }
        };
        auto sts_chunk = [&](int s) {
            const int soff = 98304 + s*49152;
#pragma unroll
            for (int j = 0; j < 10; j++) {
                int pl = (j < 5) ? 0 : 24576;
                int row = cin_[j], c4 = c4_[j];
                int a = soff + pl + row*384 + (((c4 >> 1) ^ (row & 7)) * 16) + (c4 & 1)*8;
                uint32_t h01, m01, h23, m23;
                split2(rv[j].x, rv[j].y, h01, m01);
                split2(rv[j].z, rv[j].w, h23, m23);
                *(uint2*)(sm + a)         = make_uint2(h01, h23);
                *(uint2*)(sm + a + 12288) = make_uint2(m01, m23);
            }
        };

        float acc[3][5][4];
#pragma unroll
        for (int i = 0; i < 3; i++)
#pragma unroll
            for (int j = 0; j < 5; j++)
#pragma unroll
                for (int r = 0; r < 4; r++) acc[i][j][r] = 0.0f;

        ldg_chunk(0);
        sts_chunk(0);
        ldg_chunk(1);

        for (int c = 0; c < 8; c++) {
            __syncthreads();                    // prev MMA done before overwriting
            if (c + 1 < 8) sts_chunk((c + 1) & 1);
            if (c + 2 < 8) ldg_chunk(c + 2);
            __syncthreads();                    // stage c&1 ready

            const uint32_t xs = XB + (c & 1)*49152;
#pragma unroll
            for (int kk = 0; kk < 2; kk++) {
                // A fragments
                uint32_t ah[3][4], am[3][4];
#pragma unroll
                for (int mt = 0; mt < 3; mt++) {
                    int m = wm*48 + mt*16 + (lane & 15);
                    int ca = c*4 + kk*2 + (lane >> 4);
                    uint32_t addr = su + m*512 + (ca ^ (m & 7))*16;
                    ldsm4(ah[mt], addr);
                    ldsm4(am[mt], addr + 49152);
                }
                // B fragments (depth; rgb only needed by wm==1)
                const int krow = kk*16 + (lane & 15);
                const int swz = krow & 7;
                const uint32_t rbase_a = xs + krow*384;
                uint32_t bdh[2][4], bdm[2][4], bdh2[2], bdm2[2];
#pragma unroll
                for (int tt = 0; tt < 2; tt++) {
                    int cc = wn*5 + tt*2 + (lane >> 4);
                    uint32_t addr = rbase_a + (cc ^ swz)*16;
                    ldsm4t(bdh[tt], addr);
                    ldsm4t(bdm[tt], addr + 12288);
                }
                {
                    int cc = wn*5 + 4;
                    uint32_t addr = rbase_a + (cc ^ swz)*16;
                    ldsm2t(bdh2, addr);
                    ldsm2t(bdm2, addr + 12288);
                }
                uint32_t brh[2][4], brm[2][4], brh2[2], brm2[2];
                if (wm == 1) {
#pragma unroll
                    for (int tt = 0; tt < 2; tt++) {
                        int cc = wn*5 + tt*2 + (lane >> 4);
                        uint32_t addr = rbase_a + 24576 + (cc ^ swz)*16;
                        ldsm4t(brh[tt], addr);
                        ldsm4t(brm[tt], addr + 12288);
                    }
                    int cc = wn*5 + 4;
                    uint32_t addr = rbase_a + 24576 + (cc ^ swz)*16;
                    ldsm2t(brh2, addr);
                    ldsm2t(brm2, addr + 12288);
                }
#pragma unroll
                for (int mt = 0; mt < 3; mt++) {
                    const bool dep = (wm*3 + mt) < 4;   // rows <64 use depth
#pragma unroll
                    for (int nt = 0; nt < 5; nt++) {
                        uint32_t b0h, b1h, b0m, b1m;
                        if (nt < 4) {
                            int g = nt >> 1, hf = nt & 1;
                            b0h = dep ? bdh[g][hf*2]   : brh[g][hf*2];
                            b1h = dep ? bdh[g][hf*2+1] : brh[g][hf*2+1];
                            b0m = dep ? bdm[g][hf*2]   : brm[g][hf*2];
                            b1m = dep ? bdm[g][hf*2+1] : brm[g][hf*2+1];
                        } else {
                            b0h = dep ? bdh2[0] : brh2[0];
                            b1h = dep ? bdh2[1] : brh2[1];
                            b0m = dep ? bdm2[0] : brm2[0];
                            b1m = dep ? bdm2[1] : brm2[1];
                        }
                        mma_bf16(acc[mt][nt], ah[mt], b0h, b1h);
                        mma_bf16(acc[mt][nt], ah[mt], b0m, b1m);
                        mma_bf16(acc[mt][nt], am[mt], b0h, b1h);
                    }
                }
            }
        }

        // ---- stage C tile into epi[j][r][nw] (bias added) ----
        __syncthreads();
#pragma unroll
        for (int mt = 0; mt < 3; mt++) {
#pragma unroll
            for (int nt = 0; nt < 5; nt++) {
                int col0 = wn*40 + nt*8 + (lane & 3)*2;
                int nw = col0 >> 2, j0 = col0 & 3;      // j0 in {0,2}
#pragma unroll
                for (int hh = 0; hh < 2; hh++) {
                    int r = wm*48 + mt*16 + (lane >> 2) + hh*8;
                    epi[(j0*96 + r)*42 + nw]     = acc[mt][nt][hh*2]   + bias_v[mt][hh];
                    epi[((j0+1)*96 + r)*42 + nw] = acc[mt][nt][hh*2+1] + bias_v[mt][hh];
                }
            }
        }
        __syncthreads();

        // ---- coalesced drain ----
        for (int tk = wid; tk < 416; tk += 8) {
            if (tk < 256) {
                // q (rows 0-31) and k (rows 64-95): runs over n for fixed (row, j)
                if (lane < 20) {
                    int rr = tk >> 2, j = tk & 3;
                    int row = (rr < 32) ? rr : rr + 32;
                    float2 v = *(const float2*)&epi[(j*96 + row)*42 + lane*2];
                    uint32_t hi, mi;
                    split2(v.x, v.y, hi, mi);
                    int dd = (rr < 32) ? (rr*16 + ip*4 + j)
                                       : ((ip*4 + j)*32 + (rr - 32));
                    size_t base = ((size_t)(b*DD + dd))*NN + hn*40 + lane*2;
                    __nv_bfloat16* dh = (rr < 32) ? g_fq_hi : g_fk_hi;
                    __nv_bfloat16* dm = (rr < 32) ? g_fq_mi : g_fk_mi;
                    *(uint32_t*)(dh + base) = hi;
                    *(uint32_t*)(dm + base) = mi;
                }
            } else {
                // v (rows 32-63) -> fvT[n][e'], contiguous over e'
                if (lane < 16) {
                    int tv = tk - 256;
                    int nw = tv >> 2, j = tv & 3;
                    float v0 = epi[(j*96 + 32 + lane*2)*42 + nw];
                    float v1 = epi[(j*96 + 33 + lane*2)*42 + nw];
                    uint32_t hi, mi;
                    split2(v0, v1, hi, mi);
                    int n = hn*40 + nw;
                    size_t base = ((size_t)b*NNP + n)*DD + (ip*4 + j)*32 + lane*2;
                    *(uint32_t*)(g_fvT_hi + base) = hi;
                    *(uint32_t*)(g_fvT_mi + base) = mi;
                }
            }
        }
        __syncthreads();   // epi region reused as x stages next sub
    }
}

// ---------------------------------------------------------------------------
// Generic 128x64-tile mma.sync bf16-split3 GEMM (2 CTAs/SM):
//   C[b, m, n] = sum_k A[b,m,k] * B[b,n,k]   (both K-major, bf16 hi/mid)
// MODE 0: scores (A=fq, B=fk, K=1600, C=g_sc [512x512])
// MODE 1: attn@V (A=attn, B=fvT, K=512,  C=g_op [512x1600])
// ---------------------------------------------------------------------------
template<int MODE>
__global__ __launch_bounds__(256, 2) void k_gemm()
{
    constexpr int K    = (MODE == 0) ? 1600 : 512;
    constexpr int LD   = (MODE == 0) ? 1600 : 512;
    constexpr int LDC  = (MODE == 0) ? 512  : 1600;
    constexpr long SA  = (MODE == 0) ? (long)DD*NN : (long)DD*DD;
    constexpr long SB  = (MODE == 0) ? (long)DD*NN : (long)NNP*DD;
    constexpr long SC  = (MODE == 0) ? (long)DD*DD : (long)DD*NN;
    constexpr int NCH  = K / 64;

    extern __shared__ __align__(1024) char dsm[];

    const int b  = blockIdx.z;
    const int m0 = blockIdx.y * 128;
    const int n0 = blockIdx.x * 64;
    const int t    = threadIdx.x;
    const int lane = t & 31;
    const int wid  = t >> 5;
    const int wm   = wid & 3;          // 4 m-groups of 32 rows
    const int wn   = wid >> 2;         // 2 n-groups of 32 cols

    const uint32_t smem_u = smem_u32(dsm);

    const __nv_bfloat16* Ahi = (MODE == 0 ? g_fq_hi : g_at_hi)  + b*SA + (long)m0*LD;
    const __nv_bfloat16* Ami = (MODE == 0 ? g_fq_mi : g_at_mi)  + b*SA + (long)m0*LD;
    const __nv_bfloat16* Bhi = (MODE == 0 ? g_fk_hi : g_fvT_hi) + b*SB + (long)n0*LD;
    const __nv_bfloat16* Bmi = (MODE == 0 ? g_fk_mi : g_fvT_mi) + b*SB + (long)n0*LD;
    float* C = (MODE == 0 ? g_sc : g_op) + b*SC;

    // stage: Ahi 16K | Ami 16K | Bhi 8K | Bmi 8K ; stride 49152
    auto load_stage = [&](int s, int kc) {
        uint32_t base = smem_u + s*49152;
#pragma unroll
        for (int ii = 0; ii < 4; ii++) {
            int i = t + ii*256;
            int row = i >> 3, seg = i & 7;
            uint32_t off = row*128 + seg*16;
            uint32_t sw  = off ^ ((off >> 3) & 0x70);
            long go = (long)row*LD + kc;
            cpa16(base + sw,         (const char*)(Ahi + go) + seg*16);
            cpa16(base + 16384 + sw, (const char*)(Ami + go) + seg*16);
        }
#pragma unroll
        for (int ii = 0; ii < 2; ii++) {
            int i = t + ii*256;
            int row = i >> 3, seg = i & 7;
            uint32_t off = row*128 + seg*16;
            uint32_t sw  = off ^ ((off >> 3) & 0x70);
            long go = (long)row*LD + kc;
            cpa16(base + 32768 + sw, (const char*)(Bhi + go) + seg*16);
            cpa16(base + 40960 + sw, (const char*)(Bmi + go) + seg*16);
        }
        CPA_COMMIT();
    };

    float acc[2][4][4];
#pragma unroll
    for (int i = 0; i < 2; i++)
#pragma unroll
        for (int j = 0; j < 4; j++)
#pragma unroll
            for (int r = 0; r < 4; r++) acc[i][j][r] = 0.0f;

    load_stage(0, 0);
    load_stage(1, 64);

    const int lr = lane & 15;
    const int lc = lane >> 4;

    for (int c = 0; c < NCH; c++) {
        const int s = c & 1;
        if (c + 1 < NCH) asm volatile("cp.async.wait_group 1;" ::: "memory");
        else             asm volatile("cp.async.wait_group 0;" ::: "memory");
        __syncthreads();

        const uint32_t base = smem_u + s*49152;
#pragma unroll
        for (int kk = 0; kk < 4; kk++) {
            uint32_t a_hi[2][4], a_mi[2][4];
#pragma unroll
            for (int mt = 0; mt < 2; mt++) {
                int row = wm*32 + mt*16 + lr;
                uint32_t off = row*128 + kk*32 + lc*16;
                uint32_t sw  = off ^ ((off >> 3) & 0x70);
                ldsm4(a_hi[mt], base + sw);
                ldsm4(a_mi[mt], base + 16384 + sw);
            }
            uint32_t b_hi[2][4], b_mi[2][4];
#pragma unroll
            for (int bt = 0; bt < 2; bt++) {
                int row = wn*32 + bt*16 + lr;
                uint32_t off = row*128 + kk*32 + lc*16;
                uint32_t sw  = off ^ ((off >> 3) & 0x70);
                ldsm4(b_hi[bt], base + 32768 + sw);
                ldsm4(b_mi[bt], base + 40960 + sw);
            }
#pragma unroll
            for (int mt = 0; mt < 2; mt++) {
#pragma unroll
                for (int nt = 0; nt < 4; nt++) {
                    int bt = nt >> 1, hf = nt & 1;
                    mma_bf16(acc[mt][nt], a_hi[mt], b_hi[bt][hf], b_hi[bt][hf+2]);
                    mma_bf16(acc[mt][nt], a_hi[mt], b_mi[bt][hf], b_mi[bt][hf+2]);
                    mma_bf16(acc[mt][nt], a_mi[mt], b_hi[bt][hf], b_hi[bt][hf+2]);
                }
            }
        }
        __syncthreads();
        if (c + 2 < NCH) load_stage(s, (c + 2)*64);
    }

    const int rq = lane >> 2;
    const int cq = (lane & 3) * 2;
#pragma unroll
    for (int mt = 0; mt < 2; mt++) {
#pragma unroll
        for (int nt = 0; nt < 4; nt++) {
            int col = n0 + wn*32 + nt*8 + cq;
            int row = m0 + wm*32 + mt*16 + rq;
            float* p0 = C + (long)row*LDC + col;
            *(float2*)p0            = make_float2(acc[mt][nt][0], acc[mt][nt][1]);
            *(float2*)(p0 + 8L*LDC) = make_float2(acc[mt][nt][2], acc[mt][nt][3]);
        }
    }
}

// ---------------------------------------------------------------------------
// K3: softmax over rows of g_sc, writes attn as bf16 hi/mid split.
// ---------------------------------------------------------------------------
__global__ __launch_bounds__(128) void k_softmax()
{
    __shared__ float red[8];
    const size_t row = blockIdx.x;
    const float* s = g_sc + row * DD;
    const int t = threadIdx.x;

    float v0 = s[t], v1 = s[t+128], v2 = s[t+256], v3 = s[t+384];
    float m = fmaxf(fmaxf(v0, v1), fmaxf(v2, v3));
#pragma unroll
    for (int o = 16; o; o >>= 1) m = fmaxf(m, __shfl_xor_sync(0xffffffffu, m, o));
    if ((t & 31) == 0) red[t >> 5] = m;
    __syncthreads();
    m = fmaxf(fmaxf(red[0], red[1]), fmaxf(red[2], red[3]));

    const float inv = 0.04419417382415922f;  // 1/sqrt(512)
    float e0 = __expf((v0 - m) * inv);
    float e1 = __expf((v1 - m) * inv);
    float e2 = __expf((v2 - m) * inv);
    float e3 = __expf((v3 - m) * inv);
    float sum = e0 + e1 + e2 + e3;
#pragma unroll
    for (int o = 16; o; o >>= 1) sum += __shfl_xor_sync(0xffffffffu, sum, o);
    if ((t & 31) == 0) red[4 + (t >> 5)] = sum;
    __syncthreads();
    float r = 1.0f / (red[4] + red[5] + red[6] + red[7]);

    size_t base = row * DD;
    __nv_bfloat16 hi, mi;
    float a;
    a = e0 * r; split_bf16(a, hi, mi); g_at_hi[base + t]       = hi; g_at_mi[base + t]       = mi;
    a = e1 * r; split_bf16(a, hi, mi); g_at_hi[base + t + 128] = hi; g_at_mi[base + t + 128] = mi;
    a = e2 * r; split_bf16(a, hi, mi); g_at_hi[base + t + 256] = hi; g_at_mi[base + t + 256] = mi;
    a = e3 * r; split_bf16(a, hi, mi); g_at_hi[base + t + 384] = hi; g_at_mi[base + t + 384] = mi;
}

// ---------------------------------------------------------------------------
// K5: pixel_shuffle gather + final 1x1 conv (32 -> 256) + bias. (fp32 FFMA2)
// ---------------------------------------------------------------------------
__global__ __launch_bounds__(256) void k_final(
    const float* __restrict__ Wu, const float* __restrict__ bu,
    float* __restrict__ out)
{
    __shared__ __align__(16) float Ws2[32][257];
    __shared__ __align__(16) float Xs[32][66];

    const int blk  = blockIdx.x;
    const int b    = blk / 400;
    const int pix0 = (blk % 400) * 64;
    const int t  = threadIdx.x;
    const int tx = t & 7, ty = t >> 3;

#pragma unroll
    for (int ii = 0; ii < 32; ii++) {
        int i = t + ii*256;
        int ch = i >> 5, c = i & 31;
        Ws2[c][ch] = Wu[i];
    }
#pragma unroll
    for (int ii = 0; ii < 8; ii++) {
        int i = t + ii*256;
        int c = i >> 6, p = i & 63;
        int px = pix0 + p;
        int h = px / 160, w = px - h*160;
        int dd = c*16 + (h & 3)*4 + (w & 3);
        int n  = (h >> 2)*40 + (w >> 2);
        Xs[c][p] = g_op[((size_t)b*DD + dd)*NN + n];
    }
    __syncthreads();

    u64 acc[8][4];
#pragma unroll
    for (int r = 0; r < 8; r++)
#pragma unroll
        for (int p = 0; p < 4; p++) acc[r][p] = 0ull;

#pragma unroll 8
    for (int c = 0; c < 32; c++) {
        u64 xv[4];
#pragma unroll
        for (int pp = 0; pp < 4; pp++)
            xv[pp] = *(const u64*)&Xs[c][tx*2 + pp*16];
#pragma unroll
        for (int rr = 0; rr < 8; rr++) {
            float a = Ws2[c][ty*8 + rr];
            u64 aa = pk2(a, a);
#pragma unroll
            for (int pp = 0; pp < 4; pp++) ffma2(acc[rr][pp], aa, xv[pp]);
        }
    }

#pragma unroll
    for (int rr = 0; rr < 8; rr++) {
        int ch = ty*8 + rr;
        float bb = bu[ch];
        float* ob = out + ((size_t)b*CHN + ch)*HW + pix0;
#pragma unroll
        for (int pp = 0; pp < 4; pp++) {
            float2 v = upk2(acc[rr][pp]);
            v.x += bb; v.y += bb;
            *(float2*)&ob[tx*2 + pp*16] = v;
        }
    }
}

// ---------------------------------------------------------------------------
extern "C" void kernel_launch(void* const* d_in, const int* in_sizes, int n_in,
                              void* d_out, int out_size)
{
    (void)in_sizes; (void)n_in; (void)out_size;
    const float* rgb   = (const float*)d_in[0];
    const float* depth = (const float*)d_in[1];
    const float* Wq    = (const float*)d_in[2];
    const float* bq    = (const float*)d_in[3];
    const float* Wk    = (const float*)d_in[4];
    const float* bk    = (const float*)d_in[5];
    const float* Wv    = (const float*)d_in[6];
    const float* bv    = (const float*)d_in[7];
    const float* Wu    = (const float*)d_in[8];
    const float* bu    = (const float*)d_in[9];
    float* out = (float*)d_out;

    cudaFuncSetAttribute(k_projT,   cudaFuncAttributeMaxDynamicSharedMemorySize, 196608);
    cudaFuncSetAttribute(k_gemm<0>, cudaFuncAttributeMaxDynamicSharedMemorySize, 98304);
    cudaFuncSetAttribute(k_gemm<1>, cudaFuncAttributeMaxDynamicSharedMemorySize, 98304);

    k_wsplit <<<96, 256>>>(Wq, Wv, Wk);
    k_projT  <<<NB*80, 256, 196608>>>(rgb, depth, bq, bk, bv);
    k_gemm<0><<<dim3(8, 4, NB), 256, 98304>>>();
    k_softmax<<<NB*DD, 128>>>();
    k_gemm<1><<<dim3(25, 4, NB), 256, 98304>>>();
    k_final  <<<3200, 256>>>(Wu, bu, out);
}

// round 6
// speedup vs baseline: 2.0592x; 1.0244x over previous
#include <cuda_runtime.h>
#include <cuda_bf16.h>
#include <cstdint>

#define NB  8
#define CHN 256
#define HW  25600
#define DD  512
#define NN  1600
#define NNP 1664

// ---------------- scratch (__device__ globals; allocation-free) ------------
__device__ float g_sc[NB*DD*DD];    // scores fp32 [d][e']
__device__ float g_op[NB*DD*NN];    // attn@V output fp32 [d][n]
__device__ __align__(128) __nv_bfloat16 g_fq_hi[NB*DD*NN];   // [d][n]
__device__ __align__(128) __nv_bfloat16 g_fq_mi[NB*DD*NN];
__device__ __align__(128) __nv_bfloat16 g_fk_hi[NB*DD*NN];   // [e'][n], e' = (i*4+j)*32+c
__device__ __align__(128) __nv_bfloat16 g_fk_mi[NB*DD*NN];
__device__ __align__(128) __nv_bfloat16 g_fvT_hi[NB*NNP*DD]; // [n][e']
__device__ __align__(128) __nv_bfloat16 g_fvT_mi[NB*NNP*DD];
__device__ __align__(128) __nv_bfloat16 g_at_hi[NB*DD*DD];   // [d][e']
__device__ __align__(128) __nv_bfloat16 g_at_mi[NB*DD*DD];
__device__ __align__(128) __nv_bfloat16 g_w_hi[96*256];      // qkv weights split
__device__ __align__(128) __nv_bfloat16 g_w_mi[96*256];
__device__ __align__(128) __nv_bfloat16 g_wu_hi[256*32];     // Wu split
__device__ __align__(128) __nv_bfloat16 g_wu_mi[256*32];

typedef unsigned long long u64;

// ---------------- PTX helpers (baseline ISA only) ---------------------------
__device__ __forceinline__ uint32_t smem_u32(const void* p) {
    uint32_t a;
    asm("{ .reg .u64 t; cvta.to.shared.u64 t, %1; cvt.u32.u64 %0, t; }" : "=r"(a) : "l"(p));
    return a;
}
__device__ __forceinline__ void cpa16(uint32_t s, const void* g) {
    asm volatile("cp.async.cg.shared.global [%0], [%1], 16;" :: "r"(s), "l"(g));
}
#define CPA_COMMIT() asm volatile("cp.async.commit_group;" ::: "memory")

__device__ __forceinline__ void ldsm4(uint32_t* r, uint32_t a) {
    asm volatile("ldmatrix.sync.aligned.m8n8.x4.shared.b16 {%0,%1,%2,%3}, [%4];"
        : "=r"(r[0]), "=r"(r[1]), "=r"(r[2]), "=r"(r[3]) : "r"(a));
}
__device__ __forceinline__ void ldsm4t(uint32_t* r, uint32_t a) {
    asm volatile("ldmatrix.sync.aligned.m8n8.x4.trans.shared.b16 {%0,%1,%2,%3}, [%4];"
        : "=r"(r[0]), "=r"(r[1]), "=r"(r[2]), "=r"(r[3]) : "r"(a));
}
__device__ __forceinline__ void ldsm2t(uint32_t* r, uint32_t a) {
    asm volatile("ldmatrix.sync.aligned.m8n8.x2.trans.shared.b16 {%0,%1}, [%2];"
        : "=r"(r[0]), "=r"(r[1]) : "r"(a));
}
__device__ __forceinline__ void mma_bf16(float* d, const uint32_t* a, uint32_t b0, uint32_t b1) {
    asm volatile(
        "mma.sync.aligned.m16n8k16.row.col.f32.bf16.bf16.f32 "
        "{%0,%1,%2,%3},{%4,%5,%6,%7},{%8,%9},{%0,%1,%2,%3};"
        : "+f"(d[0]), "+f"(d[1]), "+f"(d[2]), "+f"(d[3])
        : "r"(a[0]), "r"(a[1]), "r"(a[2]), "r"(a[3]), "r"(b0), "r"(b1));
}

__device__ __forceinline__ void split_bf16(float v, __nv_bfloat16 &h, __nv_bfloat16 &m) {
    h = __float2bfloat16(v);
    m = __float2bfloat16(v - __bfloat162float(h));
}
// fast pair split: hi = bit-truncation (PRMT-packed), mi = rn of residuals.
__device__ __forceinline__ void split2(float a, float b, uint32_t &hi, uint32_t &mi) {
    uint32_t ua = __float_as_uint(a), ub = __float_as_uint(b);
    hi = __byte_perm(ua, ub, 0x7632);
    float ra = a - __uint_as_float(ua & 0xFFFF0000u);
    float rb = b - __uint_as_float(ub & 0xFFFF0000u);
    asm("cvt.rn.bf16x2.f32 %0, %1, %2;" : "=r"(mi) : "f"(rb), "f"(ra));
}

// ---------------------------------------------------------------------------
// K-1: split W q/v/k rows (0-31 q, 32-63 v, 64-95 k) into bf16 hi/mid planes,
// plus Wu [256][32].
// ---------------------------------------------------------------------------
__global__ __launch_bounds__(256) void k_wsplit(
    const float* __restrict__ Wq, const float* __restrict__ Wv, const float* __restrict__ Wk,
    const float* __restrict__ Wu)
{
    int i = blockIdx.x * 256 + threadIdx.x;
    if (i < 96*256) {
        int r = i >> 8, kk = i & 255;
        float v = (r < 32) ? Wq[r*256 + kk] : ((r < 64) ? Wv[(r-32)*256 + kk] : Wk[(r-64)*256 + kk]);
        __nv_bfloat16 h, m;
        split_bf16(v, h, m);
        g_w_hi[i] = h; g_w_mi[i] = m;
    }
    if (i < 256*32) {
        __nv_bfloat16 h, m;
        split_bf16(Wu[i], h, m);
        g_wu_hi[i] = h; g_wu_mi[i] = m;
    }
}

// ---------------------------------------------------------------------------
// K1: tensor-core fused q/k/v 1x1 conv + pixel_unshuffle, coalesced epilogue.
// (unchanged from round 5)
// ---------------------------------------------------------------------------
__global__ __launch_bounds__(256, 1) void k_projT(
    const float* __restrict__ rgb, const float* __restrict__ depth,
    const float* __restrict__ bq, const float* __restrict__ bk,
    const float* __restrict__ bv)
{
    extern __shared__ __align__(1024) char sm[];
    const int b  = blockIdx.x / 80;
    const int hp = blockIdx.x % 80;
    const int t = threadIdx.x, lane = t & 31, wid = t >> 5;
    const int wm = wid & 1, wn = wid >> 1;
    const uint32_t su = smem_u32(sm);
    const uint32_t XB = su + 98304;
    float* const epi = (float*)(sm + 98304);

    for (int i = t; i < 96*32; i += 256) {
        int m = i >> 5, c = i & 31;
        uint4 v1 = *(const uint4*)((const char*)g_w_hi + m*512 + c*16);
        uint4 v2 = *(const uint4*)((const char*)g_w_mi + m*512 + c*16);
        int sw = (c ^ (m & 7)) * 16;
        *(uint4*)(sm + m*512 + sw)         = v1;
        *(uint4*)(sm + 49152 + m*512 + sw) = v2;
    }

    float bias_v[3][2];
#pragma unroll
    for (int mt = 0; mt < 3; mt++)
#pragma unroll
        for (int hh = 0; hh < 2; hh++) {
            int r = wm*48 + mt*16 + (lane >> 2) + hh*8;
            bias_v[mt][hh] = (r < 32) ? bq[r] : ((r < 64) ? bv[r-32] : bk[r-64]);
        }

    int cin_[10], c4_[10];
#pragma unroll
    for (int j = 0; j < 10; j++) {
        int ii = (t + j*256) % 1280;
        cin_[j] = ii / 40; c4_[j] = ii % 40;
    }
    __syncthreads();

    const float* dbase = depth + (size_t)b*CHN*HW;
    const float* rbase = rgb   + (size_t)b*CHN*HW;

    for (int sub = 0; sub < 2; sub++) {
        const int h  = hp*2 + sub;
        const int ip = h & 3, hn = h >> 2;
        const size_t rowoff = (size_t)h * 160;

        float4 rv[10];
        auto ldg_chunk = [&](int c) {
#pragma unroll
            for (int j = 0; j < 10; j++) {
                const float* bp = (j < 5) ? dbase : rbase;
                rv[j] = *(const float4*)(bp + (size_t)(c*32 + cin_[j])*HW + rowoff + c4_[j]*4);
            }
        };
        auto sts_chunk = [&](int s) {
            const int soff = 98304 + s*49152;
#pragma unroll
            for (int j = 0; j < 10; j++) {
                int pl = (j < 5) ? 0 : 24576;
                int row = cin_[j], c4 = c4_[j];
                int a = soff + pl + row*384 + (((c4 >> 1) ^ (row & 7)) * 16) + (c4 & 1)*8;
                uint32_t h01, m01, h23, m23;
                split2(rv[j].x, rv[j].y, h01, m01);
                split2(rv[j].z, rv[j].w, h23, m23);
                *(uint2*)(sm + a)         = make_uint2(h01, h23);
                *(uint2*)(sm + a + 12288) = make_uint2(m01, m23);
            }
        };

        float acc[3][5][4];
#pragma unroll
        for (int i = 0; i < 3; i++)
#pragma unroll
            for (int j = 0; j < 5; j++)
#pragma unroll
                for (int r = 0; r < 4; r++) acc[i][j][r] = 0.0f;

        ldg_chunk(0);
        sts_chunk(0);
        ldg_chunk(1);

        for (int c = 0; c < 8; c++) {
            __syncthreads();
            if (c + 1 < 8) sts_chunk((c + 1) & 1);
            if (c + 2 < 8) ldg_chunk(c + 2);
            __syncthreads();

            const uint32_t xs = XB + (c & 1)*49152;
#pragma unroll
            for (int kk = 0; kk < 2; kk++) {
                uint32_t ah[3][4], am[3][4];
#pragma unroll
                for (int mt = 0; mt < 3; mt++) {
                    int m = wm*48 + mt*16 + (lane & 15);
                    int ca = c*4 + kk*2 + (lane >> 4);
                    uint32_t addr = su + m*512 + (ca ^ (m & 7))*16;
                    ldsm4(ah[mt], addr);
                    ldsm4(am[mt], addr + 49152);
                }
                const int krow = kk*16 + (lane & 15);
                const int swz = krow & 7;
                const uint32_t rbase_a = xs + krow*384;
                uint32_t bdh[2][4], bdm[2][4], bdh2[2], bdm2[2];
#pragma unroll
                for (int tt = 0; tt < 2; tt++) {
                    int cc = wn*5 + tt*2 + (lane >> 4);
                    uint32_t addr = rbase_a + (cc ^ swz)*16;
                    ldsm4t(bdh[tt], addr);
                    ldsm4t(bdm[tt], addr + 12288);
                }
                {
                    int cc = wn*5 + 4;
                    uint32_t addr = rbase_a + (cc ^ swz)*16;
                    ldsm2t(bdh2, addr);
                    ldsm2t(bdm2, addr + 12288);
                }
                uint32_t brh[2][4], brm[2][4], brh2[2], brm2[2];
                if (wm == 1) {
#pragma unroll
                    for (int tt = 0; tt < 2; tt++) {
                        int cc = wn*5 + tt*2 + (lane >> 4);
                        uint32_t addr = rbase_a + 24576 + (cc ^ swz)*16;
                        ldsm4t(brh[tt], addr);
                        ldsm4t(brm[tt], addr + 12288);
                    }
                    int cc = wn*5 + 4;
                    uint32_t addr = rbase_a + 24576 + (cc ^ swz)*16;
                    ldsm2t(brh2, addr);
                    ldsm2t(brm2, addr + 12288);
                }
#pragma unroll
                for (int mt = 0; mt < 3; mt++) {
                    const bool dep = (wm*3 + mt) < 4;
#pragma unroll
                    for (int nt = 0; nt < 5; nt++) {
                        uint32_t b0h, b1h, b0m, b1m;
                        if (nt < 4) {
                            int g = nt >> 1, hf = nt & 1;
                            b0h = dep ? bdh[g][hf*2]   : brh[g][hf*2];
                            b1h = dep ? bdh[g][hf*2+1] : brh[g][hf*2+1];
                            b0m = dep ? bdm[g][hf*2]   : brm[g][hf*2];
                            b1m = dep ? bdm[g][hf*2+1] : brm[g][hf*2+1];
                        } else {
                            b0h = dep ? bdh2[0] : brh2[0];
                            b1h = dep ? bdh2[1] : brh2[1];
                            b0m = dep ? bdm2[0] : brm2[0];
                            b1m = dep ? bdm2[1] : brm2[1];
                        }
                        mma_bf16(acc[mt][nt], ah[mt], b0h, b1h);
                        mma_bf16(acc[mt][nt], ah[mt], b0m, b1m);
                        mma_bf16(acc[mt][nt], am[mt], b0h, b1h);
                    }
                }
            }
        }

        __syncthreads();
#pragma unroll
        for (int mt = 0; mt < 3; mt++) {
#pragma unroll
            for (int nt = 0; nt < 5; nt++) {
                int col0 = wn*40 + nt*8 + (lane & 3)*2;
                int nw = col0 >> 2, j0 = col0 & 3;
#pragma unroll
                for (int hh = 0; hh < 2; hh++) {
                    int r = wm*48 + mt*16 + (lane >> 2) + hh*8;
                    epi[(j0*96 + r)*42 + nw]     = acc[mt][nt][hh*2]   + bias_v[mt][hh];
                    epi[((j0+1)*96 + r)*42 + nw] = acc[mt][nt][hh*2+1] + bias_v[mt][hh];
                }
            }
        }
        __syncthreads();

        for (int tk = wid; tk < 416; tk += 8) {
            if (tk < 256) {
                if (lane < 20) {
                    int rr = tk >> 2, j = tk & 3;
                    int row = (rr < 32) ? rr : rr + 32;
                    float2 v = *(const float2*)&epi[(j*96 + row)*42 + lane*2];
                    uint32_t hi, mi;
                    split2(v.x, v.y, hi, mi);
                    int dd = (rr < 32) ? (rr*16 + ip*4 + j)
                                       : ((ip*4 + j)*32 + (rr - 32));
                    size_t base = ((size_t)(b*DD + dd))*NN + hn*40 + lane*2;
                    __nv_bfloat16* dh = (rr < 32) ? g_fq_hi : g_fk_hi;
                    __nv_bfloat16* dm = (rr < 32) ? g_fq_mi : g_fk_mi;
                    *(uint32_t*)(dh + base) = hi;
                    *(uint32_t*)(dm + base) = mi;
                }
            } else {
                if (lane < 16) {
                    int tv = tk - 256;
                    int nw = tv >> 2, j = tv & 3;
                    float v0 = epi[(j*96 + 32 + lane*2)*42 + nw];
                    float v1 = epi[(j*96 + 33 + lane*2)*42 + nw];
                    uint32_t hi, mi;
                    split2(v0, v1, hi, mi);
                    int n = hn*40 + nw;
                    size_t base = ((size_t)b*NNP + n)*DD + (ip*4 + j)*32 + lane*2;
                    *(uint32_t*)(g_fvT_hi + base) = hi;
                    *(uint32_t*)(g_fvT_mi + base) = mi;
                }
            }
        }
        __syncthreads();
    }
}

// ---------------------------------------------------------------------------
// Generic 128x64-tile mma.sync bf16-split3 GEMM (2 CTAs/SM). Unchanged.
// ---------------------------------------------------------------------------
template<int MODE>
__global__ __launch_bounds__(256, 2) void k_gemm()
{
    constexpr int K    = (MODE == 0) ? 1600 : 512;
    constexpr int LD   = (MODE == 0) ? 1600 : 512;
    constexpr int LDC  = (MODE == 0) ? 512  : 1600;
    constexpr long SA  = (MODE == 0) ? (long)DD*NN : (long)DD*DD;
    constexpr long SB  = (MODE == 0) ? (long)DD*NN : (long)NNP*DD;
    constexpr long SC  = (MODE == 0) ? (long)DD*DD : (long)DD*NN;
    constexpr int NCH  = K / 64;

    extern __shared__ __align__(1024) char dsm[];

    const int b  = blockIdx.z;
    const int m0 = blockIdx.y * 128;
    const int n0 = blockIdx.x * 64;
    const int t    = threadIdx.x;
    const int lane = t & 31;
    const int wid  = t >> 5;
    const int wm   = wid & 3;
    const int wn   = wid >> 2;

    const uint32_t smem_u = smem_u32(dsm);

    const __nv_bfloat16* Ahi = (MODE == 0 ? g_fq_hi : g_at_hi)  + b*SA + (long)m0*LD;
    const __nv_bfloat16* Ami = (MODE == 0 ? g_fq_mi : g_at_mi)  + b*SA + (long)m0*LD;
    const __nv_bfloat16* Bhi = (MODE == 0 ? g_fk_hi : g_fvT_hi) + b*SB + (long)n0*LD;
    const __nv_bfloat16* Bmi = (MODE == 0 ? g_fk_mi : g_fvT_mi) + b*SB + (long)n0*LD;
    float* C = (MODE == 0 ? g_sc : g_op) + b*SC;

    auto load_stage = [&](int s, int kc) {
        uint32_t base = smem_u + s*49152;
#pragma unroll
        for (int ii = 0; ii < 4; ii++) {
            int i = t + ii*256;
            int row = i >> 3, seg = i & 7;
            uint32_t off = row*128 + seg*16;
            uint32_t sw  = off ^ ((off >> 3) & 0x70);
            long go = (long)row*LD + kc;
            cpa16(base + sw,         (const char*)(Ahi + go) + seg*16);
            cpa16(base + 16384 + sw, (const char*)(Ami + go) + seg*16);
        }
#pragma unroll
        for (int ii = 0; ii < 2; ii++) {
            int i = t + ii*256;
            int row = i >> 3, seg = i & 7;
            uint32_t off = row*128 + seg*16;
            uint32_t sw  = off ^ ((off >> 3) & 0x70);
            long go = (long)row*LD + kc;
            cpa16(base + 32768 + sw, (const char*)(Bhi + go) + seg*16);
            cpa16(base + 40960 + sw, (const char*)(Bmi + go) + seg*16);
        }
        CPA_COMMIT();
    };

    float acc[2][4][4];
#pragma unroll
    for (int i = 0; i < 2; i++)
#pragma unroll
        for (int j = 0; j < 4; j++)
#pragma unroll
            for (int r = 0; r < 4; r++) acc[i][j][r] = 0.0f;

    load_stage(0, 0);
    load_stage(1, 64);

    const int lr = lane & 15;
    const int lc = lane >> 4;

    for (int c = 0; c < NCH; c++) {
        const int s = c & 1;
        if (c + 1 < NCH) asm volatile("cp.async.wait_group 1;" ::: "memory");
        else             asm volatile("cp.async.wait_group 0;" ::: "memory");
        __syncthreads();

        const uint32_t base = smem_u + s*49152;
#pragma unroll
        for (int kk = 0; kk < 4; kk++) {
            uint32_t a_hi[2][4], a_mi[2][4];
#pragma unroll
            for (int mt = 0; mt < 2; mt++) {
                int row = wm*32 + mt*16 + lr;
                uint32_t off = row*128 + kk*32 + lc*16;
                uint32_t sw  = off ^ ((off >> 3) & 0x70);
                ldsm4(a_hi[mt], base + sw);
                ldsm4(a_mi[mt], base + 16384 + sw);
            }
            uint32_t b_hi[2][4], b_mi[2][4];
#pragma unroll
            for (int bt = 0; bt < 2; bt++) {
                int row = wn*32 + bt*16 + lr;
                uint32_t off = row*128 + kk*32 + lc*16;
                uint32_t sw  = off ^ ((off >> 3) & 0x70);
                ldsm4(b_hi[bt], base + 32768 + sw);
                ldsm4(b_mi[bt], base + 40960 + sw);
            }
#pragma unroll
            for (int mt = 0; mt < 2; mt++) {
#pragma unroll
                for (int nt = 0; nt < 4; nt++) {
                    int bt = nt >> 1, hf = nt & 1;
                    mma_bf16(acc[mt][nt], a_hi[mt], b_hi[bt][hf], b_hi[bt][hf+2]);
                    mma_bf16(acc[mt][nt], a_hi[mt], b_mi[bt][hf], b_mi[bt][hf+2]);
                    mma_bf16(acc[mt][nt], a_mi[mt], b_hi[bt][hf], b_hi[bt][hf+2]);
                }
            }
        }
        __syncthreads();
        if (c + 2 < NCH) load_stage(s, (c + 2)*64);
    }

    const int rq = lane >> 2;
    const int cq = (lane & 3) * 2;
#pragma unroll
    for (int mt = 0; mt < 2; mt++) {
#pragma unroll
        for (int nt = 0; nt < 4; nt++) {
            int col = n0 + wn*32 + nt*8 + cq;
            int row = m0 + wm*32 + mt*16 + rq;
            float* p0 = C + (long)row*LDC + col;
            *(float2*)p0            = make_float2(acc[mt][nt][0], acc[mt][nt][1]);
            *(float2*)(p0 + 8L*LDC) = make_float2(acc[mt][nt][2], acc[mt][nt][3]);
        }
    }
}

// ---------------------------------------------------------------------------
// K3: softmax over rows of g_sc, writes attn as bf16 hi/mid split.
// ---------------------------------------------------------------------------
__global__ __launch_bounds__(128) void k_softmax()
{
    __shared__ float red[8];
    const size_t row = blockIdx.x;
    const float* s = g_sc + row * DD;
    const int t = threadIdx.x;

    float v0 = s[t], v1 = s[t+128], v2 = s[t+256], v3 = s[t+384];
    float m = fmaxf(fmaxf(v0, v1), fmaxf(v2, v3));
#pragma unroll
    for (int o = 16; o; o >>= 1) m = fmaxf(m, __shfl_xor_sync(0xffffffffu, m, o));
    if ((t & 31) == 0) red[t >> 5] = m;
    __syncthreads();
    m = fmaxf(fmaxf(red[0], red[1]), fmaxf(red[2], red[3]));

    const float inv = 0.04419417382415922f;  // 1/sqrt(512)
    float e0 = __expf((v0 - m) * inv);
    float e1 = __expf((v1 - m) * inv);
    float e2 = __expf((v2 - m) * inv);
    float e3 = __expf((v3 - m) * inv);
    float sum = e0 + e1 + e2 + e3;
#pragma unroll
    for (int o = 16; o; o >>= 1) sum += __shfl_xor_sync(0xffffffffu, sum, o);
    if ((t & 31) == 0) red[4 + (t >> 5)] = sum;
    __syncthreads();
    float r = 1.0f / (red[4] + red[5] + red[6] + red[7]);

    size_t base = row * DD;
    __nv_bfloat16 hi, mi;
    float a;
    a = e0 * r; split_bf16(a, hi, mi); g_at_hi[base + t]       = hi; g_at_mi[base + t]       = mi;
    a = e1 * r; split_bf16(a, hi, mi); g_at_hi[base + t + 128] = hi; g_at_mi[base + t + 128] = mi;
    a = e2 * r; split_bf16(a, hi, mi); g_at_hi[base + t + 256] = hi; g_at_mi[base + t + 256] = mi;
    a = e3 * r; split_bf16(a, hi, mi); g_at_hi[base + t + 384] = hi; g_at_mi[base + t + 384] = mi;
}

// ---------------------------------------------------------------------------
// K5: pixel_shuffle gather + final 1x1 conv (32 -> 256), split-3 mma.
// CTA = (wblk, hp, b): 2 h-rows (h=2hp, 2hp+1) x 32 w = 64 px, all 256 out ch.
// A = Wu split [256 ch][32 c] in smem @80B pitch (conflict-free ldsm, no swz).
// B = op gathered from g_op (L2-resident), split -> [32 c][64 px] swizzled.
// Warp tile 64ch x 32px; K=32 (2 k16); 3 passes.
// smem: A_hi @0 (20480), A_mi @20480, B_hi @40960 (4096), B_mi @45056. 48KB.
// ---------------------------------------------------------------------------
__global__ __launch_bounds__(256, 2) void k_final(
    const float* __restrict__ bu, float* __restrict__ out)
{
    extern __shared__ __align__(1024) char sm[];
    const uint32_t su = smem_u32(sm);

    const int wblk = blockIdx.x;       // 0..4
    const int hp   = blockIdx.y;       // 0..79
    const int b    = blockIdx.z;
    const int t = threadIdx.x, lane = t & 31, wid = t >> 5;
    const int wm = wid & 3, wn = wid >> 2;

    const int i0 = (2*hp) & 3;
    const int hn = hp >> 1;

    // ---- load Wu planes: thread t -> row t (64B), store at 80B pitch ----
    {
        const uint4* src_h = (const uint4*)((const char*)g_wu_hi + t*64);
        const uint4* src_m = (const uint4*)((const char*)g_wu_mi + t*64);
#pragma unroll
        for (int c = 0; c < 4; c++) {
            *(uint4*)(sm + t*80 + c*16)         = src_h[c];
            *(uint4*)(sm + 20480 + t*80 + c*16) = src_m[c];
        }
    }

    // ---- gather op, split, stage B [32 c][64 px] (128B rows, XOR swizzle) --
    {
        const int c  = t >> 3;
        const int ii = (t >> 2) & 1;
        const int j  = t & 3;
        const int d  = c*16 + (i0 + ii)*4 + j;
        const float* src = g_op + ((size_t)b*DD + d)*NN + hn*40 + wblk*8;
        float4 v0 = *(const float4*)src;
        float4 v1 = *(const float4*)(src + 4);
        float vv[8] = {v0.x, v0.y, v0.z, v0.w, v1.x, v1.y, v1.z, v1.w};
#pragma unroll
        for (int nw = 0; nw < 8; nw++) {
            int px = ii*32 + nw*4 + j;
            uint32_t a = 40960 + c*128 + (((px >> 3) ^ (c & 7))*16) + (px & 7)*2;
            __nv_bfloat16 h, m;
            uint32_t uv = __float_as_uint(vv[nw]);
            h = __ushort_as_bfloat16((unsigned short)(uv >> 16));          // truncation hi
            m = __float2bfloat16(vv[nw] - __uint_as_float(uv & 0xFFFF0000u));
            *(__nv_bfloat16*)(sm + a)        = h;
            *(__nv_bfloat16*)(sm + a + 4096) = m;
        }
    }
    __syncthreads();

    // ---- fragments + MMA ----
    float acc[4][4][4];
#pragma unroll
    for (int i = 0; i < 4; i++)
#pragma unroll
        for (int j = 0; j < 4; j++)
#pragma unroll
            for (int r = 0; r < 4; r++) acc[i][j][r] = 0.0f;

#pragma unroll
    for (int kk = 0; kk < 2; kk++) {
        uint32_t ah[4][4], am[4][4];
#pragma unroll
        for (int mt = 0; mt < 4; mt++) {
            int row = wm*64 + mt*16 + (lane & 15);
            uint32_t addr = su + row*80 + (kk*2 + (lane >> 4))*16;
            ldsm4(ah[mt], addr);
            ldsm4(am[mt], addr + 20480);
        }
        const int krow = kk*16 + (lane & 15);
        uint32_t bh[2][4], bm2[2][4];
#pragma unroll
        for (int tt = 0; tt < 2; tt++) {
            int cc = wn*4 + tt*2 + (lane >> 4);
            uint32_t addr = su + 40960 + krow*128 + ((cc ^ (krow & 7))*16);
            ldsm4t(bh[tt], addr);
            ldsm4t(bm2[tt], addr + 4096);
        }
#pragma unroll
        for (int mt = 0; mt < 4; mt++) {
#pragma unroll
            for (int nt = 0; nt < 4; nt++) {
                int tt = nt >> 1, hf = nt & 1;
                mma_bf16(acc[mt][nt], ah[mt], bh[tt][hf*2],  bh[tt][hf*2+1]);
                mma_bf16(acc[mt][nt], ah[mt], bm2[tt][hf*2], bm2[tt][hf*2+1]);
                mma_bf16(acc[mt][nt], am[mt], bh[tt][hf*2],  bh[tt][hf*2+1]);
            }
        }
    }

    // ---- epilogue: bias + float2 stores ----
    const int rq = lane >> 2;
    const int cq = (lane & 3) * 2;
    const int h  = hp*2 + wn;                 // px>>5 == wn for all this warp's cols
#pragma unroll
    for (int mt = 0; mt < 4; mt++) {
        int ch0 = wm*64 + mt*16 + rq;
        float bb0 = bu[ch0], bb1 = bu[ch0 + 8];
#pragma unroll
        for (int nt = 0; nt < 4; nt++) {
            int wl = nt*8 + cq;               // 0..30 within the 32-w block
            int w  = wblk*32 + wl;
            float* p0 = out + ((size_t)(b*CHN + ch0))*HW + (size_t)h*160 + w;
            *(float2*)p0            = make_float2(acc[mt][nt][0] + bb0, acc[mt][nt][1] + bb0);
            *(float2*)(p0 + 8*HW)   = make_float2(acc[mt][nt][2] + bb1, acc[mt][nt][3] + bb1);
        }
    }
}

// ---------------------------------------------------------------------------
extern "C" void kernel_launch(void* const* d_in, const int* in_sizes, int n_in,
                              void* d_out, int out_size)
{
    (void)in_sizes; (void)n_in; (void)out_size;
    const float* rgb   = (const float*)d_in[0];
    const float* depth = (const float*)d_in[1];
    const float* Wq    = (const float*)d_in[2];
    const float* bq    = (const float*)d_in[3];
    const float* Wk    = (const float*)d_in[4];
    const float* bk    = (const float*)d_in[5];
    const float* Wv    = (const float*)d_in[6];
    const float* bv    = (const float*)d_in[7];
    const float* Wu    = (const float*)d_in[8];
    const float* bu    = (const float*)d_in[9];
    float* out = (float*)d_out;

    cudaFuncSetAttribute(k_projT,   cudaFuncAttributeMaxDynamicSharedMemorySize, 196608);
    cudaFuncSetAttribute(k_gemm<0>, cudaFuncAttributeMaxDynamicSharedMemorySize, 98304);
    cudaFuncSetAttribute(k_gemm<1>, cudaFuncAttributeMaxDynamicSharedMemorySize, 98304);
    cudaFuncSetAttribute(k_final,   cudaFuncAttributeMaxDynamicSharedMemorySize, 49152);

    k_wsplit <<<96, 256>>>(Wq, Wv, Wk, Wu);
    k_projT  <<<NB*80, 256, 196608>>>(rgb, depth, bq, bk, bv);
    k_gemm<0><<<dim3(8, 4, NB), 256, 98304>>>();
    k_softmax<<<NB*DD, 128>>>();
    k_gemm<1><<<dim3(25, 4, NB), 256, 98304>>>();
    k_final  <<<dim3(5, 80, NB), 256, 49152>>>(bu, out);
}

// round 7
// speedup vs baseline: 2.3349x; 1.1339x over previous
#include <cuda_runtime.h>
#include <cuda_bf16.h>
#include <cstdint>

#define NB  8
#define CHN 256
#define HW  25600
#define DD  512
#define NN  1600
#define NNP 1664

// ---------------- scratch (__device__ globals; allocation-free) ------------
__device__ float g_sc[NB*DD*DD];    // scores fp32 [d][e']
__device__ float g_op[NB*DD*NN];    // attn@V output fp32 [d][n]
__device__ __align__(128) __nv_bfloat16 g_fq_hi[NB*DD*NN];   // [d][n]
__device__ __align__(128) __nv_bfloat16 g_fq_mi[NB*DD*NN];
__device__ __align__(128) __nv_bfloat16 g_fk_hi[NB*DD*NN];   // [e'][n], e' = (i*4+j)*32+c
__device__ __align__(128) __nv_bfloat16 g_fk_mi[NB*DD*NN];
__device__ __align__(128) __nv_bfloat16 g_fvT_hi[NB*NNP*DD]; // [n][e']
__device__ __align__(128) __nv_bfloat16 g_fvT_mi[NB*NNP*DD];
__device__ __align__(128) __nv_bfloat16 g_at_hi[NB*DD*DD];   // [d][e']
__device__ __align__(128) __nv_bfloat16 g_at_mi[NB*DD*DD];
__device__ __align__(128) __nv_bfloat16 g_w_hi[96*256];      // qkv weights split
__device__ __align__(128) __nv_bfloat16 g_w_mi[96*256];
__device__ __align__(128) __nv_bfloat16 g_wu_hi[256*32];     // Wu split
__device__ __align__(128) __nv_bfloat16 g_wu_mi[256*32];

typedef unsigned long long u64;

// ---------------- PTX helpers (baseline ISA only) ---------------------------
__device__ __forceinline__ uint32_t smem_u32(const void* p) {
    uint32_t a;
    asm("{ .reg .u64 t; cvta.to.shared.u64 t, %1; cvt.u32.u64 %0, t; }" : "=r"(a) : "l"(p));
    return a;
}
__device__ __forceinline__ void cpa16(uint32_t s, const void* g) {
    asm volatile("cp.async.cg.shared.global [%0], [%1], 16;" :: "r"(s), "l"(g));
}
#define CPA_COMMIT() asm volatile("cp.async.commit_group;" ::: "memory")

__device__ __forceinline__ void ldsm4(uint32_t* r, uint32_t a) {
    asm volatile("ldmatrix.sync.aligned.m8n8.x4.shared.b16 {%0,%1,%2,%3}, [%4];"
        : "=r"(r[0]), "=r"(r[1]), "=r"(r[2]), "=r"(r[3]) : "r"(a));
}
__device__ __forceinline__ void ldsm4t(uint32_t* r, uint32_t a) {
    asm volatile("ldmatrix.sync.aligned.m8n8.x4.trans.shared.b16 {%0,%1,%2,%3}, [%4];"
        : "=r"(r[0]), "=r"(r[1]), "=r"(r[2]), "=r"(r[3]) : "r"(a));
}
__device__ __forceinline__ void ldsm2t(uint32_t* r, uint32_t a) {
    asm volatile("ldmatrix.sync.aligned.m8n8.x2.trans.shared.b16 {%0,%1}, [%2];"
        : "=r"(r[0]), "=r"(r[1]) : "r"(a));
}
__device__ __forceinline__ void mma_bf16(float* d, const uint32_t* a, uint32_t b0, uint32_t b1) {
    asm volatile(
        "mma.sync.aligned.m16n8k16.row.col.f32.bf16.bf16.f32 "
        "{%0,%1,%2,%3},{%4,%5,%6,%7},{%8,%9},{%0,%1,%2,%3};"
        : "+f"(d[0]), "+f"(d[1]), "+f"(d[2]), "+f"(d[3])
        : "r"(a[0]), "r"(a[1]), "r"(a[2]), "r"(a[3]), "r"(b0), "r"(b1));
}

__device__ __forceinline__ void split_bf16(float v, __nv_bfloat16 &h, __nv_bfloat16 &m) {
    h = __float2bfloat16(v);
    m = __float2bfloat16(v - __bfloat162float(h));
}
// fast pair split: hi = bit-truncation (PRMT-packed), mi = rn of residuals.
__device__ __forceinline__ void split2(float a, float b, uint32_t &hi, uint32_t &mi) {
    uint32_t ua = __float_as_uint(a), ub = __float_as_uint(b);
    hi = __byte_perm(ua, ub, 0x7632);
    float ra = a - __uint_as_float(ua & 0xFFFF0000u);
    float rb = b - __uint_as_float(ub & 0xFFFF0000u);
    asm("cvt.rn.bf16x2.f32 %0, %1, %2;" : "=r"(mi) : "f"(rb), "f"(ra));
}

// ---------------------------------------------------------------------------
// K-1: split W q/v/k rows (0-31 q, 32-63 v, 64-95 k) into bf16 hi/mid planes,
// plus Wu [256][32].
// ---------------------------------------------------------------------------
__global__ __launch_bounds__(256) void k_wsplit(
    const float* __restrict__ Wq, const float* __restrict__ Wv, const float* __restrict__ Wk,
    const float* __restrict__ Wu)
{
    int i = blockIdx.x * 256 + threadIdx.x;
    if (i < 96*256) {
        int r = i >> 8, kk = i & 255;
        float v = (r < 32) ? Wq[r*256 + kk] : ((r < 64) ? Wv[(r-32)*256 + kk] : Wk[(r-64)*256 + kk]);
        __nv_bfloat16 h, m;
        split_bf16(v, h, m);
        g_w_hi[i] = h; g_w_mi[i] = m;
    }
    if (i < 256*32) {
        __nv_bfloat16 h, m;
        split_bf16(Wu[i], h, m);
        g_wu_hi[i] = h; g_wu_mi[i] = m;
    }
}

// ---------------------------------------------------------------------------
// K1: PERSISTENT tensor-core fused q/k/v 1x1 conv + pixel_unshuffle.
// Grid = 148 CTAs; 1280 work units (one h-row of 160 px, per batch).
// W planes loaded once per CTA; next unit's chunk-0 LDG prefetched during
// the current unit's tail so the load pipeline never drains.
// ---------------------------------------------------------------------------
__global__ __launch_bounds__(256, 1) void k_projT(
    const float* __restrict__ rgb, const float* __restrict__ depth,
    const float* __restrict__ bq, const float* __restrict__ bk,
    const float* __restrict__ bv)
{
    extern __shared__ __align__(1024) char sm[];
    const int t = threadIdx.x, lane = t & 31, wid = t >> 5;
    const int wm = wid & 1, wn = wid >> 1;
    const uint32_t su = smem_u32(sm);
    const uint32_t XB = su + 98304;
    float* const epi = (float*)(sm + 98304);

    // ---- W planes into smem (once per CTA) ----
    for (int i = t; i < 96*32; i += 256) {
        int m = i >> 5, c = i & 31;
        uint4 v1 = *(const uint4*)((const char*)g_w_hi + m*512 + c*16);
        uint4 v2 = *(const uint4*)((const char*)g_w_mi + m*512 + c*16);
        int sw = (c ^ (m & 7)) * 16;
        *(uint4*)(sm + m*512 + sw)         = v1;
        *(uint4*)(sm + 49152 + m*512 + sw) = v2;
    }

    float bias_v[3][2];
#pragma unroll
    for (int mt = 0; mt < 3; mt++)
#pragma unroll
        for (int hh = 0; hh < 2; hh++) {
            int r = wm*48 + mt*16 + (lane >> 2) + hh*8;
            bias_v[mt][hh] = (r < 32) ? bq[r] : ((r < 64) ? bv[r-32] : bk[r-64]);
        }

    int cin_[10], c4_[10];
#pragma unroll
    for (int j = 0; j < 10; j++) {
        int ii = (t + j*256) % 1280;
        cin_[j] = ii / 40; c4_[j] = ii % 40;
    }
    __syncthreads();

    const int cta = blockIdx.x;
    int u        = (1280 * cta) / 148;
    const int u1 = (1280 * (cta + 1)) / 148;

    int b = u / 160, h = u - b*160;
    const float* db = depth + (size_t)b*CHN*HW;
    const float* rb = rgb   + (size_t)b*CHN*HW;
    size_t rowoff = (size_t)h * 160;

    float4 rv[10];
    auto ldg_chunk = [&](int c, const float* dB, const float* rB, size_t ro) {
#pragma unroll
        for (int j = 0; j < 10; j++) {
            const float* bp = (j < 5) ? dB : rB;
            rv[j] = *(const float4*)(bp + (size_t)(c*32 + cin_[j])*HW + ro + c4_[j]*4);
        }
    };
    auto sts_chunk = [&](int s) {
        const int soff = 98304 + s*49152;
#pragma unroll
        for (int j = 0; j < 10; j++) {
            int pl = (j < 5) ? 0 : 24576;
            int row = cin_[j], c4 = c4_[j];
            int a = soff + pl + row*384 + (((c4 >> 1) ^ (row & 7)) * 16) + (c4 & 1)*8;
            uint32_t h01, m01, h23, m23;
            split2(rv[j].x, rv[j].y, h01, m01);
            split2(rv[j].z, rv[j].w, h23, m23);
            *(uint2*)(sm + a)         = make_uint2(h01, h23);
            *(uint2*)(sm + a + 12288) = make_uint2(m01, m23);
        }
    };

    ldg_chunk(0, db, rb, rowoff);

    for (; u < u1; u++) {
        const int ip = h & 3, hn = h >> 2, curb = b;

        // next-unit coordinates (for prefetch)
        int nb = b, nh = h + 1;
        if (nh == 160) { nh = 0; nb = b + 1; }
        const bool has_next = (u + 1 < u1);
        const float* ndb = depth + (size_t)nb*CHN*HW;
        const float* nrb = rgb   + (size_t)nb*CHN*HW;
        const size_t nro = (size_t)nh * 160;

        sts_chunk(0);
        ldg_chunk(1, db, rb, rowoff);

        float acc[3][5][4];
#pragma unroll
        for (int i = 0; i < 3; i++)
#pragma unroll
            for (int j = 0; j < 5; j++)
#pragma unroll
                for (int r = 0; r < 4; r++) acc[i][j][r] = 0.0f;

        for (int c = 0; c < 8; c++) {
            __syncthreads();
            if (c + 1 < 8) sts_chunk((c + 1) & 1);
            if (c + 2 < 8)                    ldg_chunk(c + 2, db, rb, rowoff);
            else if (c == 6 && has_next)      ldg_chunk(0, ndb, nrb, nro);
            __syncthreads();

            const uint32_t xs = XB + (c & 1)*49152;
#pragma unroll
            for (int kk = 0; kk < 2; kk++) {
                uint32_t ah[3][4], am[3][4];
#pragma unroll
                for (int mt = 0; mt < 3; mt++) {
                    int m = wm*48 + mt*16 + (lane & 15);
                    int ca = c*4 + kk*2 + (lane >> 4);
                    uint32_t addr = su + m*512 + (ca ^ (m & 7))*16;
                    ldsm4(ah[mt], addr);
                    ldsm4(am[mt], addr + 49152);
                }
                const int krow = kk*16 + (lane & 15);
                const int swz = krow & 7;
                const uint32_t rbase_a = xs + krow*384;
                uint32_t bdh[2][4], bdm[2][4], bdh2[2], bdm2[2];
#pragma unroll
                for (int tt = 0; tt < 2; tt++) {
                    int cc = wn*5 + tt*2 + (lane >> 4);
                    uint32_t addr = rbase_a + (cc ^ swz)*16;
                    ldsm4t(bdh[tt], addr);
                    ldsm4t(bdm[tt], addr + 12288);
                }
                {
                    int cc = wn*5 + 4;
                    uint32_t addr = rbase_a + (cc ^ swz)*16;
                    ldsm2t(bdh2, addr);
                    ldsm2t(bdm2, addr + 12288);
                }
                uint32_t brh[2][4], brm[2][4], brh2[2], brm2[2];
                if (wm == 1) {
#pragma unroll
                    for (int tt = 0; tt < 2; tt++) {
                        int cc = wn*5 + tt*2 + (lane >> 4);
                        uint32_t addr = rbase_a + 24576 + (cc ^ swz)*16;
                        ldsm4t(brh[tt], addr);
                        ldsm4t(brm[tt], addr + 12288);
                    }
                    int cc = wn*5 + 4;
                    uint32_t addr = rbase_a + 24576 + (cc ^ swz)*16;
                    ldsm2t(brh2, addr);
                    ldsm2t(brm2, addr + 12288);
                }
#pragma unroll
                for (int mt = 0; mt < 3; mt++) {
                    const bool dep = (wm*3 + mt) < 4;
#pragma unroll
                    for (int nt = 0; nt < 5; nt++) {
                        uint32_t b0h, b1h, b0m, b1m;
                        if (nt < 4) {
                            int g = nt >> 1, hf = nt & 1;
                            b0h = dep ? bdh[g][hf*2]   : brh[g][hf*2];
                            b1h = dep ? bdh[g][hf*2+1] : brh[g][hf*2+1];
                            b0m = dep ? bdm[g][hf*2]   : brm[g][hf*2];
                            b1m = dep ? bdm[g][hf*2+1] : brm[g][hf*2+1];
                        } else {
                            b0h = dep ? bdh2[0] : brh2[0];
                            b1h = dep ? bdh2[1] : brh2[1];
                            b0m = dep ? bdm2[0] : brm2[0];
                            b1m = dep ? bdm2[1] : brm2[1];
                        }
                        mma_bf16(acc[mt][nt], ah[mt], b0h, b1h);
                        mma_bf16(acc[mt][nt], ah[mt], b0m, b1m);
                        mma_bf16(acc[mt][nt], am[mt], b0h, b1h);
                    }
                }
            }
        }

        // ---- epilogue: stage into epi, coalesced drain ----
        __syncthreads();
#pragma unroll
        for (int mt = 0; mt < 3; mt++) {
#pragma unroll
            for (int nt = 0; nt < 5; nt++) {
                int col0 = wn*40 + nt*8 + (lane & 3)*2;
                int nw = col0 >> 2, j0 = col0 & 3;
#pragma unroll
                for (int hh = 0; hh < 2; hh++) {
                    int r = wm*48 + mt*16 + (lane >> 2) + hh*8;
                    epi[(j0*96 + r)*42 + nw]     = acc[mt][nt][hh*2]   + bias_v[mt][hh];
                    epi[((j0+1)*96 + r)*42 + nw] = acc[mt][nt][hh*2+1] + bias_v[mt][hh];
                }
            }
        }
        __syncthreads();

        for (int tk = wid; tk < 416; tk += 8) {
            if (tk < 256) {
                if (lane < 20) {
                    int rr = tk >> 2, j = tk & 3;
                    int row = (rr < 32) ? rr : rr + 32;
                    float2 v = *(const float2*)&epi[(j*96 + row)*42 + lane*2];
                    uint32_t hi, mi;
                    split2(v.x, v.y, hi, mi);
                    int dd = (rr < 32) ? (rr*16 + ip*4 + j)
                                       : ((ip*4 + j)*32 + (rr - 32));
                    size_t base = ((size_t)(curb*DD + dd))*NN + hn*40 + lane*2;
                    __nv_bfloat16* dh = (rr < 32) ? g_fq_hi : g_fk_hi;
                    __nv_bfloat16* dm = (rr < 32) ? g_fq_mi : g_fk_mi;
                    *(uint32_t*)(dh + base) = hi;
                    *(uint32_t*)(dm + base) = mi;
                }
            } else {
                if (lane < 16) {
                    int tv = tk - 256;
                    int nw = tv >> 2, j = tv & 3;
                    float v0 = epi[(j*96 + 32 + lane*2)*42 + nw];
                    float v1 = epi[(j*96 + 33 + lane*2)*42 + nw];
                    uint32_t hi, mi;
                    split2(v0, v1, hi, mi);
                    int n = hn*40 + nw;
                    size_t base = ((size_t)curb*NNP + n)*DD + (ip*4 + j)*32 + lane*2;
                    *(uint32_t*)(g_fvT_hi + base) = hi;
                    *(uint32_t*)(g_fvT_mi + base) = mi;
                }
            }
        }
        __syncthreads();   // epi region reused as x stages next unit

        b = nb; h = nh; db = ndb; rb = nrb; rowoff = nro;
    }
}

// ---------------------------------------------------------------------------
// Generic 128x64-tile mma.sync bf16-split3 GEMM (2 CTAs/SM). Unchanged.
// ---------------------------------------------------------------------------
template<int MODE>
__global__ __launch_bounds__(256, 2) void k_gemm()
{
    constexpr int K    = (MODE == 0) ? 1600 : 512;
    constexpr int LD   = (MODE == 0) ? 1600 : 512;
    constexpr int LDC  = (MODE == 0) ? 512  : 1600;
    constexpr long SA  = (MODE == 0) ? (long)DD*NN : (long)DD*DD;
    constexpr long SB  = (MODE == 0) ? (long)DD*NN : (long)NNP*DD;
    constexpr long SC  = (MODE == 0) ? (long)DD*DD : (long)DD*NN;
    constexpr int NCH  = K / 64;

    extern __shared__ __align__(1024) char dsm[];

    const int b  = blockIdx.z;
    const int m0 = blockIdx.y * 128;
    const int n0 = blockIdx.x * 64;
    const int t    = threadIdx.x;
    const int lane = t & 31;
    const int wid  = t >> 5;
    const int wm   = wid & 3;
    const int wn   = wid >> 2;

    const uint32_t smem_u = smem_u32(dsm);

    const __nv_bfloat16* Ahi = (MODE == 0 ? g_fq_hi : g_at_hi)  + b*SA + (long)m0*LD;
    const __nv_bfloat16* Ami = (MODE == 0 ? g_fq_mi : g_at_mi)  + b*SA + (long)m0*LD;
    const __nv_bfloat16* Bhi = (MODE == 0 ? g_fk_hi : g_fvT_hi) + b*SB + (long)n0*LD;
    const __nv_bfloat16* Bmi = (MODE == 0 ? g_fk_mi : g_fvT_mi) + b*SB + (long)n0*LD;
    float* C = (MODE == 0 ? g_sc : g_op) + b*SC;

    auto load_stage = [&](int s, int kc) {
        uint32_t base = smem_u + s*49152;
#pragma unroll
        for (int ii = 0; ii < 4; ii++) {
            int i = t + ii*256;
            int row = i >> 3, seg = i & 7;
            uint32_t off = row*128 + seg*16;
            uint32_t sw  = off ^ ((off >> 3) & 0x70);
            long go = (long)row*LD + kc;
            cpa16(base + sw,         (const char*)(Ahi + go) + seg*16);
            cpa16(base + 16384 + sw, (const char*)(Ami + go) + seg*16);
        }
#pragma unroll
        for (int ii = 0; ii < 2; ii++) {
            int i = t + ii*256;
            int row = i >> 3, seg = i & 7;
            uint32_t off = row*128 + seg*16;
            uint32_t sw  = off ^ ((off >> 3) & 0x70);
            long go = (long)row*LD + kc;
            cpa16(base + 32768 + sw, (const char*)(Bhi + go) + seg*16);
            cpa16(base + 40960 + sw, (const char*)(Bmi + go) + seg*16);
        }
        CPA_COMMIT();
    };

    float acc[2][4][4];
#pragma unroll
    for (int i = 0; i < 2; i++)
#pragma unroll
        for (int j = 0; j < 4; j++)
#pragma unroll
            for (int r = 0; r < 4; r++) acc[i][j][r] = 0.0f;

    load_stage(0, 0);
    load_stage(1, 64);

    const int lr = lane & 15;
    const int lc = lane >> 4;

    for (int c = 0; c < NCH; c++) {
        const int s = c & 1;
        if (c + 1 < NCH) asm volatile("cp.async.wait_group 1;" ::: "memory");
        else             asm volatile("cp.async.wait_group 0;" ::: "memory");
        __syncthreads();

        const uint32_t base = smem_u + s*49152;
#pragma unroll
        for (int kk = 0; kk < 4; kk++) {
            uint32_t a_hi[2][4], a_mi[2][4];
#pragma unroll
            for (int mt = 0; mt < 2; mt++) {
                int row = wm*32 + mt*16 + lr;
                uint32_t off = row*128 + kk*32 + lc*16;
                uint32_t sw  = off ^ ((off >> 3) & 0x70);
                ldsm4(a_hi[mt], base + sw);
                ldsm4(a_mi[mt], base + 16384 + sw);
            }
            uint32_t b_hi[2][4], b_mi[2][4];
#pragma unroll
            for (int bt = 0; bt < 2; bt++) {
                int row = wn*32 + bt*16 + lr;
                uint32_t off = row*128 + kk*32 + lc*16;
                uint32_t sw  = off ^ ((off >> 3) & 0x70);
                ldsm4(b_hi[bt], base + 32768 + sw);
                ldsm4(b_mi[bt], base + 40960 + sw);
            }
#pragma unroll
            for (int mt = 0; mt < 2; mt++) {
#pragma unroll
                for (int nt = 0; nt < 4; nt++) {
                    int bt = nt >> 1, hf = nt & 1;
                    mma_bf16(acc[mt][nt], a_hi[mt], b_hi[bt][hf], b_hi[bt][hf+2]);
                    mma_bf16(acc[mt][nt], a_hi[mt], b_mi[bt][hf], b_mi[bt][hf+2]);
                    mma_bf16(acc[mt][nt], a_mi[mt], b_hi[bt][hf], b_hi[bt][hf+2]);
                }
            }
        }
        __syncthreads();
        if (c + 2 < NCH) load_stage(s, (c + 2)*64);
    }

    const int rq = lane >> 2;
    const int cq = (lane & 3) * 2;
#pragma unroll
    for (int mt = 0; mt < 2; mt++) {
#pragma unroll
        for (int nt = 0; nt < 4; nt++) {
            int col = n0 + wn*32 + nt*8 + cq;
            int row = m0 + wm*32 + mt*16 + rq;
            float* p0 = C + (long)row*LDC + col;
            *(float2*)p0            = make_float2(acc[mt][nt][0], acc[mt][nt][1]);
            *(float2*)(p0 + 8L*LDC) = make_float2(acc[mt][nt][2], acc[mt][nt][3]);
        }
    }
}

// ---------------------------------------------------------------------------
// K3: softmax over rows of g_sc, writes attn as bf16 hi/mid split.
// ---------------------------------------------------------------------------
__global__ __launch_bounds__(128) void k_softmax()
{
    __shared__ float red[8];
    const size_t row = blockIdx.x;
    const float* s = g_sc + row * DD;
    const int t = threadIdx.x;

    float v0 = s[t], v1 = s[t+128], v2 = s[t+256], v3 = s[t+384];
    float m = fmaxf(fmaxf(v0, v1), fmaxf(v2, v3));
#pragma unroll
    for (int o = 16; o; o >>= 1) m = fmaxf(m, __shfl_xor_sync(0xffffffffu, m, o));
    if ((t & 31) == 0) red[t >> 5] = m;
    __syncthreads();
    m = fmaxf(fmaxf(red[0], red[1]), fmaxf(red[2], red[3]));

    const float inv = 0.04419417382415922f;  // 1/sqrt(512)
    float e0 = __expf((v0 - m) * inv);
    float e1 = __expf((v1 - m) * inv);
    float e2 = __expf((v2 - m) * inv);
    float e3 = __expf((v3 - m) * inv);
    float sum = e0 + e1 + e2 + e3;
#pragma unroll
    for (int o = 16; o; o >>= 1) sum += __shfl_xor_sync(0xffffffffu, sum, o);
    if ((t & 31) == 0) red[4 + (t >> 5)] = sum;
    __syncthreads();
    float r = 1.0f / (red[4] + red[5] + red[6] + red[7]);

    size_t base = row * DD;
    __nv_bfloat16 hi, mi;
    float a;
    a = e0 * r; split_bf16(a, hi, mi); g_at_hi[base + t]       = hi; g_at_mi[base + t]       = mi;
    a = e1 * r; split_bf16(a, hi, mi); g_at_hi[base + t + 128] = hi; g_at_mi[base + t + 128] = mi;
    a = e2 * r; split_bf16(a, hi, mi); g_at_hi[base + t + 256] = hi; g_at_mi[base + t + 256] = mi;
    a = e3 * r; split_bf16(a, hi, mi); g_at_hi[base + t + 384] = hi; g_at_mi[base + t + 384] = mi;
}

// ---------------------------------------------------------------------------
// K5: PERSISTENT pixel_shuffle gather + final 1x1 conv (32 -> 256), split-3.
// Grid = 296 CTAs (2/SM); 3200 units (wblk, hp, b). Wu loaded once per CTA.
// B stage double-buffered (2 x 8KB); next unit's op-gather LDG overlaps MMA.
// smem: Wu_hi @0 (20480), Wu_mi @20480; B stages @40960 + s*8192
//       (hi at +0, mi at +4096). Total 57344.
// ---------------------------------------------------------------------------
__global__ __launch_bounds__(256, 2) void k_final(
    const float* __restrict__ bu, float* __restrict__ out)
{
    extern __shared__ __align__(1024) char sm[];
    const uint32_t su = smem_u32(sm);
    const int t = threadIdx.x, lane = t & 31, wid = t >> 5;
    const int wm = wid & 3, wn = wid >> 2;
    const int rq = lane >> 2, cq = (lane & 3) * 2;

    // ---- load Wu planes once: row t at 80B pitch ----
    {
        const uint4* src_h = (const uint4*)((const char*)g_wu_hi + t*64);
        const uint4* src_m = (const uint4*)((const char*)g_wu_mi + t*64);
#pragma unroll
        for (int c = 0; c < 4; c++) {
            *(uint4*)(sm + t*80 + c*16)         = src_h[c];
            *(uint4*)(sm + 20480 + t*80 + c*16) = src_m[c];
        }
    }

    // ---- bias preload (unit-independent) ----
    float bb[4][2];
#pragma unroll
    for (int mt = 0; mt < 4; mt++) {
        int ch0 = wm*64 + mt*16 + rq;
        bb[mt][0] = bu[ch0];
        bb[mt][1] = bu[ch0 + 8];
    }

    const int gc = t >> 3;          // gather channel 0..31
    const int ii = (t >> 2) & 1;
    const int gj = t & 3;

    const int cta = blockIdx.x;
    int u        = (3200 * cta) / 296;
    const int u1 = (3200 * (cta + 1)) / 296;

    float4 v0, v1;
    auto prefetch = [&](int uu) {
        int pb = uu / 400, r = uu - pb*400;
        int php = r / 5, pwb = r - (r/5)*5;
        int i0 = (2*php) & 3, hn = php >> 1;
        int d  = gc*16 + (i0 + ii)*4 + gj;
        const float* src = g_op + ((size_t)(pb*DD + d))*NN + hn*40 + pwb*8;
        v0 = *(const float4*)src;
        v1 = *(const float4*)(src + 4);
    };
    if (u < u1) prefetch(u);

    for (; u < u1; u++) {
        const int s = u & 1;
        const int b = u / 400, r = u - b*400;
        const int hp = r / 5, wblk = r - (r/5)*5;

        __syncthreads();   // stage s free (MMA of u-2 done); Wu visible on 1st iter

        // ---- stage B from regs ----
        {
            float vv[8] = {v0.x, v0.y, v0.z, v0.w, v1.x, v1.y, v1.z, v1.w};
#pragma unroll
            for (int nw = 0; nw < 8; nw++) {
                int px = ii*32 + nw*4 + gj;
                uint32_t a = 40960 + s*8192 + gc*128 + (((px >> 3) ^ (gc & 7))*16) + (px & 7)*2;
                uint32_t uv = __float_as_uint(vv[nw]);
                __nv_bfloat16 h = __ushort_as_bfloat16((unsigned short)(uv >> 16));
                __nv_bfloat16 m = __float2bfloat16(vv[nw] - __uint_as_float(uv & 0xFFFF0000u));
                *(__nv_bfloat16*)(sm + a)        = h;
                *(__nv_bfloat16*)(sm + a + 4096) = m;
            }
        }
        if (u + 1 < u1) prefetch(u + 1);   // overlap next gather with MMA
        __syncthreads();

        // ---- MMA (stage s) ----
        float acc[4][4][4];
#pragma unroll
        for (int i = 0; i < 4; i++)
#pragma unroll
            for (int j = 0; j < 4; j++)
#pragma unroll
                for (int rr = 0; rr < 4; rr++) acc[i][j][rr] = 0.0f;

#pragma unroll
        for (int kk = 0; kk < 2; kk++) {
            uint32_t ah[4][4], am[4][4];
#pragma unroll
            for (int mt = 0; mt < 4; mt++) {
                int row = wm*64 + mt*16 + (lane & 15);
                uint32_t addr = su + row*80 + (kk*2 + (lane >> 4))*16;
                ldsm4(ah[mt], addr);
                ldsm4(am[mt], addr + 20480);
            }
            const int krow = kk*16 + (lane & 15);
            uint32_t bh[2][4], bm2[2][4];
#pragma unroll
            for (int tt = 0; tt < 2; tt++) {
                int cc = wn*4 + tt*2 + (lane >> 4);
                uint32_t addr = su + 40960 + s*8192 + krow*128 + ((cc ^ (krow & 7))*16);
                ldsm4t(bh[tt], addr);
                ldsm4t(bm2[tt], addr + 4096);
            }
#pragma unroll
            for (int mt = 0; mt < 4; mt++) {
#pragma unroll
                for (int nt = 0; nt < 4; nt++) {
                    int tt = nt >> 1, hf = nt & 1;
                    mma_bf16(acc[mt][nt], ah[mt], bh[tt][hf*2],  bh[tt][hf*2+1]);
                    mma_bf16(acc[mt][nt], ah[mt], bm2[tt][hf*2], bm2[tt][hf*2+1]);
                    mma_bf16(acc[mt][nt], am[mt], bh[tt][hf*2],  bh[tt][hf*2+1]);
                }
            }
        }

        // ---- epilogue: bias + float2 stores ----
        const int h = hp*2 + wn;
#pragma unroll
        for (int mt = 0; mt < 4; mt++) {
            int ch0 = wm*64 + mt*16 + rq;
#pragma unroll
            for (int nt = 0; nt < 4; nt++) {
                int w = wblk*32 + nt*8 + cq;
                float* p0 = out + ((size_t)(b*CHN + ch0))*HW + (size_t)h*160 + w;
                *(float2*)p0          = make_float2(acc[mt][nt][0] + bb[mt][0], acc[mt][nt][1] + bb[mt][0]);
                *(float2*)(p0 + 8*HW) = make_float2(acc[mt][nt][2] + bb[mt][1], acc[mt][nt][3] + bb[mt][1]);
            }
        }
    }
}

// ---------------------------------------------------------------------------
extern "C" void kernel_launch(void* const* d_in, const int* in_sizes, int n_in,
                              void* d_out, int out_size)
{
    (void)in_sizes; (void)n_in; (void)out_size;
    const float* rgb   = (const float*)d_in[0];
    const float* depth = (const float*)d_in[1];
    const float* Wq    = (const float*)d_in[2];
    const float* bq    = (const float*)d_in[3];
    const float* Wk    = (const float*)d_in[4];
    const float* bk    = (const float*)d_in[5];
    const float* Wv    = (const float*)d_in[6];
    const float* bv    = (const float*)d_in[7];
    const float* Wu    = (const float*)d_in[8];
    const float* bu    = (const float*)d_in[9];
    float* out = (float*)d_out;

    cudaFuncSetAttribute(k_projT,   cudaFuncAttributeMaxDynamicSharedMemorySize, 196608);
    cudaFuncSetAttribute(k_gemm<0>, cudaFuncAttributeMaxDynamicSharedMemorySize, 98304);
    cudaFuncSetAttribute(k_gemm<1>, cudaFuncAttributeMaxDynamicSharedMemorySize, 98304);
    cudaFuncSetAttribute(k_final,   cudaFuncAttributeMaxDynamicSharedMemorySize, 57344);

    k_wsplit <<<96, 256>>>(Wq, Wv, Wk, Wu);
    k_projT  <<<148, 256, 196608>>>(rgb, depth, bq, bk, bv);
    k_gemm<0><<<dim3(8, 4, NB), 256, 98304>>>();
    k_softmax<<<NB*DD, 128>>>();
    k_gemm<1><<<dim3(25, 4, NB), 256, 98304>>>();
    k_final  <<<296, 256, 57344>>>(bu, out);
}

// round 8
// speedup vs baseline: 2.5429x; 1.0891x over previous
#include <cuda_runtime.h>
#include <cuda_bf16.h>
#include <cstdint>

#define NB  8
#define CHN 256
#define HW  25600
#define DD  512
#define NN  1600
#define NNP 1664

// ---------------- scratch (__device__ globals; allocation-free) ------------
__device__ float g_sc[NB*DD*DD];    // scores fp32 [d][e']
__device__ float g_op[NB*DD*NN];    // attn@V output fp32 [d][n]
__device__ __align__(128) __nv_bfloat16 g_fq_hi[NB*DD*NN];   // [d][n]
__device__ __align__(128) __nv_bfloat16 g_fq_mi[NB*DD*NN];
__device__ __align__(128) __nv_bfloat16 g_fk_hi[NB*DD*NN];   // [e'][n], e' = (i*4+j)*32+c
__device__ __align__(128) __nv_bfloat16 g_fk_mi[NB*DD*NN];
__device__ __align__(128) __nv_bfloat16 g_fvT_hi[NB*NNP*DD]; // [n][e']
__device__ __align__(128) __nv_bfloat16 g_fvT_mi[NB*NNP*DD];
__device__ __align__(128) __nv_bfloat16 g_at_hi[NB*DD*DD];   // [d][e']
__device__ __align__(128) __nv_bfloat16 g_at_mi[NB*DD*DD];
__device__ __align__(128) __nv_bfloat16 g_w_hi[96*256];      // qkv weights split
__device__ __align__(128) __nv_bfloat16 g_w_mi[96*256];
__device__ __align__(128) __nv_bfloat16 g_wu_hi[256*32];     // Wu split
__device__ __align__(128) __nv_bfloat16 g_wu_mi[256*32];

typedef unsigned long long u64;

// ---------------- PTX helpers (baseline ISA only) ---------------------------
__device__ __forceinline__ uint32_t smem_u32(const void* p) {
    uint32_t a;
    asm("{ .reg .u64 t; cvta.to.shared.u64 t, %1; cvt.u32.u64 %0, t; }" : "=r"(a) : "l"(p));
    return a;
}
__device__ __forceinline__ void cpa16(uint32_t s, const void* g) {
    asm volatile("cp.async.cg.shared.global [%0], [%1], 16;" :: "r"(s), "l"(g));
}
#define CPA_COMMIT() asm volatile("cp.async.commit_group;" ::: "memory")

__device__ __forceinline__ void ldsm4(uint32_t* r, uint32_t a) {
    asm volatile("ldmatrix.sync.aligned.m8n8.x4.shared.b16 {%0,%1,%2,%3}, [%4];"
        : "=r"(r[0]), "=r"(r[1]), "=r"(r[2]), "=r"(r[3]) : "r"(a));
}
__device__ __forceinline__ void ldsm4t(uint32_t* r, uint32_t a) {
    asm volatile("ldmatrix.sync.aligned.m8n8.x4.trans.shared.b16 {%0,%1,%2,%3}, [%4];"
        : "=r"(r[0]), "=r"(r[1]), "=r"(r[2]), "=r"(r[3]) : "r"(a));
}
__device__ __forceinline__ void ldsm2t(uint32_t* r, uint32_t a) {
    asm volatile("ldmatrix.sync.aligned.m8n8.x2.trans.shared.b16 {%0,%1}, [%2];"
        : "=r"(r[0]), "=r"(r[1]) : "r"(a));
}
__device__ __forceinline__ void mma_bf16(float* d, const uint32_t* a, uint32_t b0, uint32_t b1) {
    asm volatile(
        "mma.sync.aligned.m16n8k16.row.col.f32.bf16.bf16.f32 "
        "{%0,%1,%2,%3},{%4,%5,%6,%7},{%8,%9},{%0,%1,%2,%3};"
        : "+f"(d[0]), "+f"(d[1]), "+f"(d[2]), "+f"(d[3])
        : "r"(a[0]), "r"(a[1]), "r"(a[2]), "r"(a[3]), "r"(b0), "r"(b1));
}

__device__ __forceinline__ void split_bf16(float v, __nv_bfloat16 &h, __nv_bfloat16 &m) {
    h = __float2bfloat16(v);
    m = __float2bfloat16(v - __bfloat162float(h));
}
// fast pair split: hi = bit-truncation (PRMT-packed), mi = rn of residuals.
__device__ __forceinline__ void split2(float a, float b, uint32_t &hi, uint32_t &mi) {
    uint32_t ua = __float_as_uint(a), ub = __float_as_uint(b);
    hi = __byte_perm(ua, ub, 0x7632);
    float ra = a - __uint_as_float(ua & 0xFFFF0000u);
    float rb = b - __uint_as_float(ub & 0xFFFF0000u);
    asm("cvt.rn.bf16x2.f32 %0, %1, %2;" : "=r"(mi) : "f"(rb), "f"(ra));
}

// ---------------------------------------------------------------------------
// K-1: split W q/v/k rows (0-31 q, 32-63 v, 64-95 k) into bf16 hi/mid planes,
// plus Wu [256][32].
// ---------------------------------------------------------------------------
__global__ __launch_bounds__(256) void k_wsplit(
    const float* __restrict__ Wq, const float* __restrict__ Wv, const float* __restrict__ Wk,
    const float* __restrict__ Wu)
{
    int i = blockIdx.x * 256 + threadIdx.x;
    if (i < 96*256) {
        int r = i >> 8, kk = i & 255;
        float v = (r < 32) ? Wq[r*256 + kk] : ((r < 64) ? Wv[(r-32)*256 + kk] : Wk[(r-64)*256 + kk]);
        __nv_bfloat16 h, m;
        split_bf16(v, h, m);
        g_w_hi[i] = h; g_w_mi[i] = m;
    }
    if (i < 256*32) {
        __nv_bfloat16 h, m;
        split_bf16(Wu[i], h, m);
        g_wu_hi[i] = h; g_wu_mi[i] = m;
    }
}

// ---------------------------------------------------------------------------
// K1: PERSISTENT tensor-core fused q/k/v 1x1 conv + pixel_unshuffle.
// 384 threads / 12 warps (3 per SMSP), warp grid 3m x 4n, warp tile 32x40.
// Each warp's 32 rows use ONE source: wm=0 q(depth), wm=1 v(depth), wm=2 k(rgb).
// Grid = 148 CTAs; 1280 units (one h-row of 160 px per batch). W loaded once.
// ---------------------------------------------------------------------------
__global__ __launch_bounds__(384, 1) void k_projT(
    const float* __restrict__ rgb, const float* __restrict__ depth,
    const float* __restrict__ bq, const float* __restrict__ bk,
    const float* __restrict__ bv)
{
    extern __shared__ __align__(1024) char sm[];
    const int t = threadIdx.x, lane = t & 31, wid = t >> 5;
    const int wn = wid & 3, wm = wid >> 2;       // wm 0..2, wn 0..3
    const uint32_t su = smem_u32(sm);
    const uint32_t XB = su + 98304;
    float* const epi = (float*)(sm + 98304);

    // ---- W planes into smem (once per CTA) ----
    for (int i = t; i < 96*32; i += 384) {
        int m = i >> 5, c = i & 31;
        uint4 v1 = *(const uint4*)((const char*)g_w_hi + m*512 + c*16);
        uint4 v2 = *(const uint4*)((const char*)g_w_mi + m*512 + c*16);
        int sw = (c ^ (m & 7)) * 16;
        *(uint4*)(sm + m*512 + sw)         = v1;
        *(uint4*)(sm + 49152 + m*512 + sw) = v2;
    }

    float bias_v[2][2];
#pragma unroll
    for (int mt = 0; mt < 2; mt++)
#pragma unroll
        for (int hh = 0; hh < 2; hh++) {
            int r = wm*32 + mt*16 + (lane >> 2) + hh*8;
            bias_v[mt][hh] = (r < 32) ? bq[r] : ((r < 64) ? bv[r-32] : bk[r-64]);
        }

    // per-thread ldg mapping: 2560 float4 items (src x 32 cin x 40 c4)
    int cin_[7], c4_[7], pl_[7];
    bool val_[7];
#pragma unroll
    for (int j = 0; j < 7; j++) {
        int item = t + j*384;
        val_[j] = item < 2560;
        int it2 = val_[j] ? item : 0;
        int src = (it2 >= 1280) ? 1 : 0;
        int rem = it2 - src*1280;
        cin_[j] = rem / 40; c4_[j] = rem % 40;
        pl_[j]  = src ? 24576 : 0;
    }
    __syncthreads();

    const int cta = blockIdx.x;
    int u        = (1280 * cta) / 148;
    const int u1 = (1280 * (cta + 1)) / 148;

    int b = u / 160, h = u - b*160;
    const float* db = depth + (size_t)b*CHN*HW;
    const float* rb = rgb   + (size_t)b*CHN*HW;
    size_t rowoff = (size_t)h * 160;

    float4 rv[7];
    auto ldg_chunk = [&](int c, const float* dB, const float* rB, size_t ro) {
#pragma unroll
        for (int j = 0; j < 7; j++) {
            if (val_[j]) {
                const float* bp = pl_[j] ? rB : dB;
                rv[j] = *(const float4*)(bp + (size_t)(c*32 + cin_[j])*HW + ro + c4_[j]*4);
            }
        }
    };
    auto sts_chunk = [&](int s) {
        const int soff = 98304 + s*49152;
#pragma unroll
        for (int j = 0; j < 7; j++) {
            if (val_[j]) {
                int row = cin_[j], c4 = c4_[j];
                int a = soff + pl_[j] + row*384 + (((c4 >> 1) ^ (row & 7)) * 16) + (c4 & 1)*8;
                uint32_t h01, m01, h23, m23;
                split2(rv[j].x, rv[j].y, h01, m01);
                split2(rv[j].z, rv[j].w, h23, m23);
                *(uint2*)(sm + a)         = make_uint2(h01, h23);
                *(uint2*)(sm + a + 12288) = make_uint2(m01, m23);
            }
        }
    };

    ldg_chunk(0, db, rb, rowoff);

    for (; u < u1; u++) {
        const int ip = h & 3, hn = h >> 2, curb = b;

        int nb = b, nh = h + 1;
        if (nh == 160) { nh = 0; nb = b + 1; }
        const bool has_next = (u + 1 < u1);
        const float* ndb = depth + (size_t)nb*CHN*HW;
        const float* nrb = rgb   + (size_t)nb*CHN*HW;
        const size_t nro = (size_t)nh * 160;

        sts_chunk(0);
        ldg_chunk(1, db, rb, rowoff);

        float acc[2][5][4];
#pragma unroll
        for (int i = 0; i < 2; i++)
#pragma unroll
            for (int j = 0; j < 5; j++)
#pragma unroll
                for (int r = 0; r < 4; r++) acc[i][j][r] = 0.0f;

        const int pls = (wm == 2) ? 24576 : 0;   // this warp's source plane

        for (int c = 0; c < 8; c++) {
            __syncthreads();
            if (c + 1 < 8) sts_chunk((c + 1) & 1);
            if (c + 2 < 8)                    ldg_chunk(c + 2, db, rb, rowoff);
            else if (c == 6 && has_next)      ldg_chunk(0, ndb, nrb, nro);
            __syncthreads();

            const uint32_t xs = XB + (c & 1)*49152;
#pragma unroll
            for (int kk = 0; kk < 2; kk++) {
                uint32_t ah[2][4], am[2][4];
#pragma unroll
                for (int mt = 0; mt < 2; mt++) {
                    int m = wm*32 + mt*16 + (lane & 15);
                    int ca = c*4 + kk*2 + (lane >> 4);
                    uint32_t addr = su + m*512 + (ca ^ (m & 7))*16;
                    ldsm4(ah[mt], addr);
                    ldsm4(am[mt], addr + 49152);
                }
                const int krow = kk*16 + (lane & 15);
                const int swz = krow & 7;
                const uint32_t rbase_a = xs + pls + krow*384;
                uint32_t bh[2][4], bm[2][4], bh2[2], bm2[2];
#pragma unroll
                for (int tt = 0; tt < 2; tt++) {
                    int cc = wn*5 + tt*2 + (lane >> 4);
                    uint32_t addr = rbase_a + (cc ^ swz)*16;
                    ldsm4t(bh[tt], addr);
                    ldsm4t(bm[tt], addr + 12288);
                }
                {
                    int cc = wn*5 + 4;
                    uint32_t addr = rbase_a + (cc ^ swz)*16;
                    ldsm2t(bh2, addr);
                    ldsm2t(bm2, addr + 12288);
                }
#pragma unroll
                for (int mt = 0; mt < 2; mt++) {
#pragma unroll
                    for (int nt = 0; nt < 5; nt++) {
                        uint32_t b0h, b1h, b0m, b1m;
                        if (nt < 4) {
                            int g = nt >> 1, hf = nt & 1;
                            b0h = bh[g][hf*2];  b1h = bh[g][hf*2+1];
                            b0m = bm[g][hf*2];  b1m = bm[g][hf*2+1];
                        } else {
                            b0h = bh2[0]; b1h = bh2[1];
                            b0m = bm2[0]; b1m = bm2[1];
                        }
                        mma_bf16(acc[mt][nt], ah[mt], b0h, b1h);
                        mma_bf16(acc[mt][nt], ah[mt], b0m, b1m);
                        mma_bf16(acc[mt][nt], am[mt], b0h, b1h);
                    }
                }
            }
        }

        // ---- epilogue: stage into epi, coalesced drain ----
        __syncthreads();
#pragma unroll
        for (int mt = 0; mt < 2; mt++) {
#pragma unroll
            for (int nt = 0; nt < 5; nt++) {
                int col0 = wn*40 + nt*8 + (lane & 3)*2;
                int nw = col0 >> 2, j0 = col0 & 3;
#pragma unroll
                for (int hh = 0; hh < 2; hh++) {
                    int r = wm*32 + mt*16 + (lane >> 2) + hh*8;
                    epi[(j0*96 + r)*42 + nw]     = acc[mt][nt][hh*2]   + bias_v[mt][hh];
                    epi[((j0+1)*96 + r)*42 + nw] = acc[mt][nt][hh*2+1] + bias_v[mt][hh];
                }
            }
        }
        __syncthreads();

        for (int tk = wid; tk < 416; tk += 12) {
            if (tk < 256) {
                if (lane < 20) {
                    int rr = tk >> 2, j = tk & 3;
                    int row = (rr < 32) ? rr : rr + 32;
                    float2 v = *(const float2*)&epi[(j*96 + row)*42 + lane*2];
                    uint32_t hi, mi;
                    split2(v.x, v.y, hi, mi);
                    int dd = (rr < 32) ? (rr*16 + ip*4 + j)
                                       : ((ip*4 + j)*32 + (rr - 32));
                    size_t base = ((size_t)(curb*DD + dd))*NN + hn*40 + lane*2;
                    __nv_bfloat16* dh = (rr < 32) ? g_fq_hi : g_fk_hi;
                    __nv_bfloat16* dm = (rr < 32) ? g_fq_mi : g_fk_mi;
                    *(uint32_t*)(dh + base) = hi;
                    *(uint32_t*)(dm + base) = mi;
                }
            } else {
                if (lane < 16) {
                    int tv = tk - 256;
                    int nw = tv >> 2, j = tv & 3;
                    float v0 = epi[(j*96 + 32 + lane*2)*42 + nw];
                    float v1 = epi[(j*96 + 33 + lane*2)*42 + nw];
                    uint32_t hi, mi;
                    split2(v0, v1, hi, mi);
                    int n = hn*40 + nw;
                    size_t base = ((size_t)curb*NNP + n)*DD + (ip*4 + j)*32 + lane*2;
                    *(uint32_t*)(g_fvT_hi + base) = hi;
                    *(uint32_t*)(g_fvT_mi + base) = mi;
                }
            }
        }
        __syncthreads();   // epi region reused as x stages next unit

        b = nb; h = nh; db = ndb; rb = nrb; rowoff = nro;
    }
}

// ---------------------------------------------------------------------------
// Generic 128x64-tile mma.sync bf16-split3 GEMM (2 CTAs/SM). Unchanged.
// ---------------------------------------------------------------------------
template<int MODE>
__global__ __launch_bounds__(256, 2) void k_gemm()
{
    constexpr int K    = (MODE == 0) ? 1600 : 512;
    constexpr int LD   = (MODE == 0) ? 1600 : 512;
    constexpr int LDC  = (MODE == 0) ? 512  : 1600;
    constexpr long SA  = (MODE == 0) ? (long)DD*NN : (long)DD*DD;
    constexpr long SB  = (MODE == 0) ? (long)DD*NN : (long)NNP*DD;
    constexpr long SC  = (MODE == 0) ? (long)DD*DD : (long)DD*NN;
    constexpr int NCH  = K / 64;

    extern __shared__ __align__(1024) char dsm[];

    const int b  = blockIdx.z;
    const int m0 = blockIdx.y * 128;
    const int n0 = blockIdx.x * 64;
    const int t    = threadIdx.x;
    const int lane = t & 31;
    const int wid  = t >> 5;
    const int wm   = wid & 3;
    const int wn   = wid >> 2;

    const uint32_t smem_u = smem_u32(dsm);

    const __nv_bfloat16* Ahi = (MODE == 0 ? g_fq_hi : g_at_hi)  + b*SA + (long)m0*LD;
    const __nv_bfloat16* Ami = (MODE == 0 ? g_fq_mi : g_at_mi)  + b*SA + (long)m0*LD;
    const __nv_bfloat16* Bhi = (MODE == 0 ? g_fk_hi : g_fvT_hi) + b*SB + (long)n0*LD;
    const __nv_bfloat16* Bmi = (MODE == 0 ? g_fk_mi : g_fvT_mi) + b*SB + (long)n0*LD;
    float* C = (MODE == 0 ? g_sc : g_op) + b*SC;

    auto load_stage = [&](int s, int kc) {
        uint32_t base = smem_u + s*49152;
#pragma unroll
        for (int ii = 0; ii < 4; ii++) {
            int i = t + ii*256;
            int row = i >> 3, seg = i & 7;
            uint32_t off = row*128 + seg*16;
            uint32_t sw  = off ^ ((off >> 3) & 0x70);
            long go = (long)row*LD + kc;
            cpa16(base + sw,         (const char*)(Ahi + go) + seg*16);
            cpa16(base + 16384 + sw, (const char*)(Ami + go) + seg*16);
        }
#pragma unroll
        for (int ii = 0; ii < 2; ii++) {
            int i = t + ii*256;
            int row = i >> 3, seg = i & 7;
            uint32_t off = row*128 + seg*16;
            uint32_t sw  = off ^ ((off >> 3) & 0x70);
            long go = (long)row*LD + kc;
            cpa16(base + 32768 + sw, (const char*)(Bhi + go) + seg*16);
            cpa16(base + 40960 + sw, (const char*)(Bmi + go) + seg*16);
        }
        CPA_COMMIT();
    };

    float acc[2][4][4];
#pragma unroll
    for (int i = 0; i < 2; i++)
#pragma unroll
        for (int j = 0; j < 4; j++)
#pragma unroll
            for (int r = 0; r < 4; r++) acc[i][j][r] = 0.0f;

    load_stage(0, 0);
    load_stage(1, 64);

    const int lr = lane & 15;
    const int lc = lane >> 4;

    for (int c = 0; c < NCH; c++) {
        const int s = c & 1;
        if (c + 1 < NCH) asm volatile("cp.async.wait_group 1;" ::: "memory");
        else             asm volatile("cp.async.wait_group 0;" ::: "memory");
        __syncthreads();

        const uint32_t base = smem_u + s*49152;
#pragma unroll
        for (int kk = 0; kk < 4; kk++) {
            uint32_t a_hi[2][4], a_mi[2][4];
#pragma unroll
            for (int mt = 0; mt < 2; mt++) {
                int row = wm*32 + mt*16 + lr;
                uint32_t off = row*128 + kk*32 + lc*16;
                uint32_t sw  = off ^ ((off >> 3) & 0x70);
                ldsm4(a_hi[mt], base + sw);
                ldsm4(a_mi[mt], base + 16384 + sw);
            }
            uint32_t b_hi[2][4], b_mi[2][4];
#pragma unroll
            for (int bt = 0; bt < 2; bt++) {
                int row = wn*32 + bt*16 + lr;
                uint32_t off = row*128 + kk*32 + lc*16;
                uint32_t sw  = off ^ ((off >> 3) & 0x70);
                ldsm4(b_hi[bt], base + 32768 + sw);
                ldsm4(b_mi[bt], base + 40960 + sw);
            }
#pragma unroll
            for (int mt = 0; mt < 2; mt++) {
#pragma unroll
                for (int nt = 0; nt < 4; nt++) {
                    int bt = nt >> 1, hf = nt & 1;
                    mma_bf16(acc[mt][nt], a_hi[mt], b_hi[bt][hf], b_hi[bt][hf+2]);
                    mma_bf16(acc[mt][nt], a_hi[mt], b_mi[bt][hf], b_mi[bt][hf+2]);
                    mma_bf16(acc[mt][nt], a_mi[mt], b_hi[bt][hf], b_hi[bt][hf+2]);
                }
            }
        }
        __syncthreads();
        if (c + 2 < NCH) load_stage(s, (c + 2)*64);
    }

    const int rq = lane >> 2;
    const int cq = (lane & 3) * 2;
#pragma unroll
    for (int mt = 0; mt < 2; mt++) {
#pragma unroll
        for (int nt = 0; nt < 4; nt++) {
            int col = n0 + wn*32 + nt*8 + cq;
            int row = m0 + wm*32 + mt*16 + rq;
            float* p0 = C + (long)row*LDC + col;
            *(float2*)p0            = make_float2(acc[mt][nt][0], acc[mt][nt][1]);
            *(float2*)(p0 + 8L*LDC) = make_float2(acc[mt][nt][2], acc[mt][nt][3]);
        }
    }
}

// ---------------------------------------------------------------------------
// K3: softmax over rows of g_sc, writes attn as bf16 hi/mid split.
// ---------------------------------------------------------------------------
__global__ __launch_bounds__(128) void k_softmax()
{
    __shared__ float red[8];
    const size_t row = blockIdx.x;
    const float* s = g_sc + row * DD;
    const int t = threadIdx.x;

    float v0 = s[t], v1 = s[t+128], v2 = s[t+256], v3 = s[t+384];
    float m = fmaxf(fmaxf(v0, v1), fmaxf(v2, v3));
#pragma unroll
    for (int o = 16; o; o >>= 1) m = fmaxf(m, __shfl_xor_sync(0xffffffffu, m, o));
    if ((t & 31) == 0) red[t >> 5] = m;
    __syncthreads();
    m = fmaxf(fmaxf(red[0], red[1]), fmaxf(red[2], red[3]));

    const float inv = 0.04419417382415922f;  // 1/sqrt(512)
    float e0 = __expf((v0 - m) * inv);
    float e1 = __expf((v1 - m) * inv);
    float e2 = __expf((v2 - m) * inv);
    float e3 = __expf((v3 - m) * inv);
    float sum = e0 + e1 + e2 + e3;
#pragma unroll
    for (int o = 16; o; o >>= 1) sum += __shfl_xor_sync(0xffffffffu, sum, o);
    if ((t & 31) == 0) red[4 + (t >> 5)] = sum;
    __syncthreads();
    float r = 1.0f / (red[4] + red[5] + red[6] + red[7]);

    size_t base = row * DD;
    __nv_bfloat16 hi, mi;
    float a;
    a = e0 * r; split_bf16(a, hi, mi); g_at_hi[base + t]       = hi; g_at_mi[base + t]       = mi;
    a = e1 * r; split_bf16(a, hi, mi); g_at_hi[base + t + 128] = hi; g_at_mi[base + t + 128] = mi;
    a = e2 * r; split_bf16(a, hi, mi); g_at_hi[base + t + 256] = hi; g_at_mi[base + t + 256] = mi;
    a = e3 * r; split_bf16(a, hi, mi); g_at_hi[base + t + 384] = hi; g_at_mi[base + t + 384] = mi;
}

// ---------------------------------------------------------------------------
// K5: PERSISTENT pixel_shuffle gather + final 1x1 conv (32 -> 256), split-3.
// Unchanged from round 7.
// ---------------------------------------------------------------------------
__global__ __launch_bounds__(256, 2) void k_final(
    const float* __restrict__ bu, float* __restrict__ out)
{
    extern __shared__ __align__(1024) char sm[];
    const uint32_t su = smem_u32(sm);
    const int t = threadIdx.x, lane = t & 31, wid = t >> 5;
    const int wm = wid & 3, wn = wid >> 2;
    const int rq = lane >> 2, cq = (lane & 3) * 2;

    // ---- load Wu planes once: row t at 80B pitch ----
    {
        const uint4* src_h = (const uint4*)((const char*)g_wu_hi + t*64);
        const uint4* src_m = (const uint4*)((const char*)g_wu_mi + t*64);
#pragma unroll
        for (int c = 0; c < 4; c++) {
            *(uint4*)(sm + t*80 + c*16)         = src_h[c];
            *(uint4*)(sm + 20480 + t*80 + c*16) = src_m[c];
        }
    }

    float bb[4][2];
#pragma unroll
    for (int mt = 0; mt < 4; mt++) {
        int ch0 = wm*64 + mt*16 + rq;
        bb[mt][0] = bu[ch0];
        bb[mt][1] = bu[ch0 + 8];
    }

    const int gc = t >> 3;
    const int ii = (t >> 2) & 1;
    const int gj = t & 3;

    const int cta = blockIdx.x;
    int u        = (3200 * cta) / 296;
    const int u1 = (3200 * (cta + 1)) / 296;

    float4 v0, v1;
    auto prefetch = [&](int uu) {
        int pb = uu / 400, r = uu - pb*400;
        int php = r / 5, pwb = r - (r/5)*5;
        int i0 = (2*php) & 3, hn = php >> 1;
        int d  = gc*16 + (i0 + ii)*4 + gj;
        const float* src = g_op + ((size_t)(pb*DD + d))*NN + hn*40 + pwb*8;
        v0 = *(const float4*)src;
        v1 = *(const float4*)(src + 4);
    };
    if (u < u1) prefetch(u);

    for (; u < u1; u++) {
        const int s = u & 1;
        const int b = u / 400, r = u - b*400;
        const int hp = r / 5, wblk = r - (r/5)*5;

        __syncthreads();

        {
            float vv[8] = {v0.x, v0.y, v0.z, v0.w, v1.x, v1.y, v1.z, v1.w};
#pragma unroll
            for (int nw = 0; nw < 8; nw++) {
                int px = ii*32 + nw*4 + gj;
                uint32_t a = 40960 + s*8192 + gc*128 + (((px >> 3) ^ (gc & 7))*16) + (px & 7)*2;
                uint32_t uv = __float_as_uint(vv[nw]);
                __nv_bfloat16 h = __ushort_as_bfloat16((unsigned short)(uv >> 16));
                __nv_bfloat16 m = __float2bfloat16(vv[nw] - __uint_as_float(uv & 0xFFFF0000u));
                *(__nv_bfloat16*)(sm + a)        = h;
                *(__nv_bfloat16*)(sm + a + 4096) = m;
            }
        }
        if (u + 1 < u1) prefetch(u + 1);
        __syncthreads();

        float acc[4][4][4];
#pragma unroll
        for (int i = 0; i < 4; i++)
#pragma unroll
            for (int j = 0; j < 4; j++)
#pragma unroll
                for (int rr = 0; rr < 4; rr++) acc[i][j][rr] = 0.0f;

#pragma unroll
        for (int kk = 0; kk < 2; kk++) {
            uint32_t ah[4][4], am[4][4];
#pragma unroll
            for (int mt = 0; mt < 4; mt++) {
                int row = wm*64 + mt*16 + (lane & 15);
                uint32_t addr = su + row*80 + (kk*2 + (lane >> 4))*16;
                ldsm4(ah[mt], addr);
                ldsm4(am[mt], addr + 20480);
            }
            const int krow = kk*16 + (lane & 15);
            uint32_t bh[2][4], bm2[2][4];
#pragma unroll
            for (int tt = 0; tt < 2; tt++) {
                int cc = wn*4 + tt*2 + (lane >> 4);
                uint32_t addr = su + 40960 + s*8192 + krow*128 + ((cc ^ (krow & 7))*16);
                ldsm4t(bh[tt], addr);
                ldsm4t(bm2[tt], addr + 4096);
            }
#pragma unroll
            for (int mt = 0; mt < 4; mt++) {
#pragma unroll
                for (int nt = 0; nt < 4; nt++) {
                    int tt = nt >> 1, hf = nt & 1;
                    mma_bf16(acc[mt][nt], ah[mt], bh[tt][hf*2],  bh[tt][hf*2+1]);
                    mma_bf16(acc[mt][nt], ah[mt], bm2[tt][hf*2], bm2[tt][hf*2+1]);
                    mma_bf16(acc[mt][nt], am[mt], bh[tt][hf*2],  bh[tt][hf*2+1]);
                }
            }
        }

        const int h = hp*2 + wn;
#pragma unroll
        for (int mt = 0; mt < 4; mt++) {
            int ch0 = wm*64 + mt*16 + rq;
#pragma unroll
            for (int nt = 0; nt < 4; nt++) {
                int w = wblk*32 + nt*8 + cq;
                float* p0 = out + ((size_t)(b*CHN + ch0))*HW + (size_t)h*160 + w;
                *(float2*)p0          = make_float2(acc[mt][nt][0] + bb[mt][0], acc[mt][nt][1] + bb[mt][0]);
                *(float2*)(p0 + 8*HW) = make_float2(acc[mt][nt][2] + bb[mt][1], acc[mt][nt][3] + bb[mt][1]);
            }
        }
    }
}

// ---------------------------------------------------------------------------
extern "C" void kernel_launch(void* const* d_in, const int* in_sizes, int n_in,
                              void* d_out, int out_size)
{
    (void)in_sizes; (void)n_in; (void)out_size;
    const float* rgb   = (const float*)d_in[0];
    const float* depth = (const float*)d_in[1];
    const float* Wq    = (const float*)d_in[2];
    const float* bq    = (const float*)d_in[3];
    const float* Wk    = (const float*)d_in[4];
    const float* bk    = (const float*)d_in[5];
    const float* Wv    = (const float*)d_in[6];
    const float* bv    = (const float*)d_in[7];
    const float* Wu    = (const float*)d_in[8];
    const float* bu    = (const float*)d_in[9];
    float* out = (float*)d_out;

    cudaFuncSetAttribute(k_projT,   cudaFuncAttributeMaxDynamicSharedMemorySize, 196608);
    cudaFuncSetAttribute(k_gemm<0>, cudaFuncAttributeMaxDynamicSharedMemorySize, 98304);
    cudaFuncSetAttribute(k_gemm<1>, cudaFuncAttributeMaxDynamicSharedMemorySize, 98304);
    cudaFuncSetAttribute(k_final,   cudaFuncAttributeMaxDynamicSharedMemorySize, 57344);

    k_wsplit <<<96, 256>>>(Wq, Wv, Wk, Wu);
    k_projT  <<<148, 384, 196608>>>(rgb, depth, bq, bk, bv);
    k_gemm<0><<<dim3(8, 4, NB), 256, 98304>>>();
    k_softmax<<<NB*DD, 128>>>();
    k_gemm<1><<<dim3(25, 4, NB), 256, 98304>>>();
    k_final  <<<296, 256, 57344>>>(bu, out);
}

// round 9
// speedup vs baseline: 2.9672x; 1.1669x over previous
#include <cuda_runtime.h>
#include <cuda_bf16.h>
#include <cuda_fp16.h>
#include <cstdint>

#define NB  8
#define CHN 256
#define HW  25600
#define DD  512
#define NN  1600
#define NNP 1664

// ---------------- scratch (__device__ globals; allocation-free) ------------
__device__ float g_sc[NB*DD*DD];    // scores fp32 [d][e']
__device__ float g_op[NB*DD*NN];    // attn@V output fp32 [d][n]
__device__ __align__(128) __half g_fq_hi[NB*DD*NN];   // [d][n] (2 planes)
__device__ __align__(128) __half g_fq_mi[NB*DD*NN];
__device__ __align__(128) __half g_fk_hi[NB*DD*NN];   // [e'][n] single plane
__device__ __align__(128) __half g_fvT_hi[NB*NNP*DD]; // [n][e'] single plane
__device__ __align__(128) __half g_at_hi[NB*DD*DD];   // [d][e'] (2 planes)
__device__ __align__(128) __half g_at_mi[NB*DD*DD];
__device__ __align__(128) __half g_w_hi[96*256];      // qkv weights (2 planes)
__device__ __align__(128) __half g_w_mi[96*256];
__device__ __align__(128) __nv_bfloat16 g_wu_hi[256*32];  // Wu split (bf16, k_final)
__device__ __align__(128) __nv_bfloat16 g_wu_mi[256*32];

typedef unsigned long long u64;

// ---------------- PTX helpers (baseline ISA only) ---------------------------
__device__ __forceinline__ uint32_t smem_u32(const void* p) {
    uint32_t a;
    asm("{ .reg .u64 t; cvta.to.shared.u64 t, %1; cvt.u32.u64 %0, t; }" : "=r"(a) : "l"(p));
    return a;
}
__device__ __forceinline__ void cpa16(uint32_t s, const void* g) {
    asm volatile("cp.async.cg.shared.global [%0], [%1], 16;" :: "r"(s), "l"(g));
}
#define CPA_COMMIT() asm volatile("cp.async.commit_group;" ::: "memory")

__device__ __forceinline__ void ldsm4(uint32_t* r, uint32_t a) {
    asm volatile("ldmatrix.sync.aligned.m8n8.x4.shared.b16 {%0,%1,%2,%3}, [%4];"
        : "=r"(r[0]), "=r"(r[1]), "=r"(r[2]), "=r"(r[3]) : "r"(a));
}
__device__ __forceinline__ void ldsm4t(uint32_t* r, uint32_t a) {
    asm volatile("ldmatrix.sync.aligned.m8n8.x4.trans.shared.b16 {%0,%1,%2,%3}, [%4];"
        : "=r"(r[0]), "=r"(r[1]), "=r"(r[2]), "=r"(r[3]) : "r"(a));
}
__device__ __forceinline__ void ldsm2t(uint32_t* r, uint32_t a) {
    asm volatile("ldmatrix.sync.aligned.m8n8.x2.trans.shared.b16 {%0,%1}, [%2];"
        : "=r"(r[0]), "=r"(r[1]) : "r"(a));
}
// fp16 mma (f32 accum)
__device__ __forceinline__ void mma_f16(float* d, const uint32_t* a, uint32_t b0, uint32_t b1) {
    asm volatile(
        "mma.sync.aligned.m16n8k16.row.col.f32.f16.f16.f32 "
        "{%0,%1,%2,%3},{%4,%5,%6,%7},{%8,%9},{%0,%1,%2,%3};"
        : "+f"(d[0]), "+f"(d[1]), "+f"(d[2]), "+f"(d[3])
        : "r"(a[0]), "r"(a[1]), "r"(a[2]), "r"(a[3]), "r"(b0), "r"(b1));
}
// bf16 mma (k_final)
__device__ __forceinline__ void mma_bf16(float* d, const uint32_t* a, uint32_t b0, uint32_t b1) {
    asm volatile(
        "mma.sync.aligned.m16n8k16.row.col.f32.bf16.bf16.f32 "
        "{%0,%1,%2,%3},{%4,%5,%6,%7},{%8,%9},{%0,%1,%2,%3};"
        : "+f"(d[0]), "+f"(d[1]), "+f"(d[2]), "+f"(d[3])
        : "r"(a[0]), "r"(a[1]), "r"(a[2]), "r"(a[3]), "r"(b0), "r"(b1));
}

__device__ __forceinline__ void split_bf16(float v, __nv_bfloat16 &h, __nv_bfloat16 &m) {
    h = __float2bfloat16(v);
    m = __float2bfloat16(v - __bfloat162float(h));
}
// pack 2 floats -> fp16x2 (lo=a, hi=b)
__device__ __forceinline__ uint32_t pack_h2(float a, float b) {
    uint32_t r;
    asm("cvt.rn.f16x2.f32 %0, %1, %2;" : "=r"(r) : "f"(b), "f"(a));
    return r;
}
// fp16 hi/mi pair split
__device__ __forceinline__ void split2h(float a, float b, uint32_t &hi, uint32_t &mi) {
    hi = pack_h2(a, b);
    __half2 h2 = *(__half2*)&hi;
    mi = pack_h2(a - __low2float(h2), b - __high2float(h2));
}

// ---------------------------------------------------------------------------
// K-1: split W q/v/k rows into fp16 hi/mid planes, Wu into bf16 planes.
// ---------------------------------------------------------------------------
__global__ __launch_bounds__(256) void k_wsplit(
    const float* __restrict__ Wq, const float* __restrict__ Wv, const float* __restrict__ Wk,
    const float* __restrict__ Wu)
{
    int i = blockIdx.x * 256 + threadIdx.x;
    if (i < 96*256) {
        int r = i >> 8, kk = i & 255;
        float v = (r < 32) ? Wq[r*256 + kk] : ((r < 64) ? Wv[(r-32)*256 + kk] : Wk[(r-64)*256 + kk]);
        __half h = __float2half_rn(v);
        g_w_hi[i] = h;
        g_w_mi[i] = __float2half_rn(v - __half2float(h));
    }
    if (i < 256*32) {
        __nv_bfloat16 h, m;
        split_bf16(Wu[i], h, m);
        g_wu_hi[i] = h; g_wu_mi[i] = m;
    }
}

// ---------------------------------------------------------------------------
// K1: PERSISTENT tensor-core fused q/k/v 1x1 conv + pixel_unshuffle.
// 384 threads / 12 warps (3/SMSP), warp grid 3m x 4n, warp tile 32x40.
// fp16 2-pass: W (2 planes, smem-resident) x x (SINGLE fp16 plane per source).
// smem: W_hi @0 (48K), W_mi @49152 (48K); x stages @98304 + s*24576
//   (depth plane @0, rgb plane @12288; [32 cin][384B rows], XOR-16B swizzle).
// epi buffer overlays x region: [4 j][96 r][42 nw] f32 (64512 B).
// ---------------------------------------------------------------------------
__global__ __launch_bounds__(384, 1) void k_projT(
    const float* __restrict__ rgb, const float* __restrict__ depth,
    const float* __restrict__ bq, const float* __restrict__ bk,
    const float* __restrict__ bv)
{
    extern __shared__ __align__(1024) char sm[];
    const int t = threadIdx.x, lane = t & 31, wid = t >> 5;
    const int wn = wid & 3, wm = wid >> 2;       // wm 0..2, wn 0..3
    const uint32_t su = smem_u32(sm);
    const uint32_t XB = su + 98304;
    float* const epi = (float*)(sm + 98304);

    // ---- W planes into smem (once per CTA) ----
    for (int i = t; i < 96*32; i += 384) {
        int m = i >> 5, c = i & 31;
        uint4 v1 = *(const uint4*)((const char*)g_w_hi + m*512 + c*16);
        uint4 v2 = *(const uint4*)((const char*)g_w_mi + m*512 + c*16);
        int sw = (c ^ (m & 7)) * 16;
        *(uint4*)(sm + m*512 + sw)         = v1;
        *(uint4*)(sm + 49152 + m*512 + sw) = v2;
    }

    float bias_v[2][2];
#pragma unroll
    for (int mt = 0; mt < 2; mt++)
#pragma unroll
        for (int hh = 0; hh < 2; hh++) {
            int r = wm*32 + mt*16 + (lane >> 2) + hh*8;
            bias_v[mt][hh] = (r < 32) ? bq[r] : ((r < 64) ? bv[r-32] : bk[r-64]);
        }

    // per-thread ldg mapping: 2560 float4 items (src x 32 cin x 40 c4)
    int cin_[7], c4_[7], pl_[7];
    bool val_[7];
#pragma unroll
    for (int j = 0; j < 7; j++) {
        int item = t + j*384;
        val_[j] = item < 2560;
        int it2 = val_[j] ? item : 0;
        int src = (it2 >= 1280) ? 1 : 0;
        int rem = it2 - src*1280;
        cin_[j] = rem / 40; c4_[j] = rem % 40;
        pl_[j]  = src ? 12288 : 0;
    }
    __syncthreads();

    const int cta = blockIdx.x;
    int u        = (1280 * cta) / 148;
    const int u1 = (1280 * (cta + 1)) / 148;

    int b = u / 160, h = u - b*160;
    const float* db = depth + (size_t)b*CHN*HW;
    const float* rb = rgb   + (size_t)b*CHN*HW;
    size_t rowoff = (size_t)h * 160;

    float4 rv[7];
    auto ldg_chunk = [&](int c, const float* dB, const float* rB, size_t ro) {
#pragma unroll
        for (int j = 0; j < 7; j++) {
            if (val_[j]) {
                const float* bp = pl_[j] ? rB : dB;
                rv[j] = *(const float4*)(bp + (size_t)(c*32 + cin_[j])*HW + ro + c4_[j]*4);
            }
        }
    };
    auto sts_chunk = [&](int s) {
        const int soff = 98304 + s*24576;
#pragma unroll
        for (int j = 0; j < 7; j++) {
            if (val_[j]) {
                int row = cin_[j], c4 = c4_[j];
                int a = soff + pl_[j] + row*384 + (((c4 >> 1) ^ (row & 7)) * 16) + (c4 & 1)*8;
                uint32_t h01 = pack_h2(rv[j].x, rv[j].y);
                uint32_t h23 = pack_h2(rv[j].z, rv[j].w);
                *(uint2*)(sm + a) = make_uint2(h01, h23);
            }
        }
    };

    ldg_chunk(0, db, rb, rowoff);

    for (; u < u1; u++) {
        const int ip = h & 3, hn = h >> 2, curb = b;

        int nb = b, nh = h + 1;
        if (nh == 160) { nh = 0; nb = b + 1; }
        const bool has_next = (u + 1 < u1);
        const float* ndb = depth + (size_t)nb*CHN*HW;
        const float* nrb = rgb   + (size_t)nb*CHN*HW;
        const size_t nro = (size_t)nh * 160;

        sts_chunk(0);
        ldg_chunk(1, db, rb, rowoff);

        float acc[2][5][4];
#pragma unroll
        for (int i = 0; i < 2; i++)
#pragma unroll
            for (int j = 0; j < 5; j++)
#pragma unroll
                for (int r = 0; r < 4; r++) acc[i][j][r] = 0.0f;

        const int pls = (wm == 2) ? 12288 : 0;   // this warp's source plane

        for (int c = 0; c < 8; c++) {
            __syncthreads();
            if (c + 1 < 8) sts_chunk((c + 1) & 1);
            if (c + 2 < 8)                    ldg_chunk(c + 2, db, rb, rowoff);
            else if (c == 6 && has_next)      ldg_chunk(0, ndb, nrb, nro);
            __syncthreads();

            const uint32_t xs = XB + (c & 1)*24576;
#pragma unroll
            for (int kk = 0; kk < 2; kk++) {
                uint32_t ah[2][4], am[2][4];
#pragma unroll
                for (int mt = 0; mt < 2; mt++) {
                    int m = wm*32 + mt*16 + (lane & 15);
                    int ca = c*4 + kk*2 + (lane >> 4);
                    uint32_t addr = su + m*512 + (ca ^ (m & 7))*16;
                    ldsm4(ah[mt], addr);
                    ldsm4(am[mt], addr + 49152);
                }
                const int krow = kk*16 + (lane & 15);
                const int swz = krow & 7;
                const uint32_t rbase_a = xs + pls + krow*384;
                uint32_t bh[2][4], bh2[2];
#pragma unroll
                for (int tt = 0; tt < 2; tt++) {
                    int cc = wn*5 + tt*2 + (lane >> 4);
                    ldsm4t(bh[tt], rbase_a + (cc ^ swz)*16);
                }
                {
                    int cc = wn*5 + 4;
                    ldsm2t(bh2, rbase_a + (cc ^ swz)*16);
                }
#pragma unroll
                for (int mt = 0; mt < 2; mt++) {
#pragma unroll
                    for (int nt = 0; nt < 5; nt++) {
                        uint32_t b0, b1;
                        if (nt < 4) {
                            int g = nt >> 1, hf = nt & 1;
                            b0 = bh[g][hf*2]; b1 = bh[g][hf*2+1];
                        } else {
                            b0 = bh2[0]; b1 = bh2[1];
                        }
                        mma_f16(acc[mt][nt], ah[mt], b0, b1);
                        mma_f16(acc[mt][nt], am[mt], b0, b1);
                    }
                }
            }
        }

        // ---- epilogue: stage into epi, coalesced drain ----
        __syncthreads();
#pragma unroll
        for (int mt = 0; mt < 2; mt++) {
#pragma unroll
            for (int nt = 0; nt < 5; nt++) {
                int col0 = wn*40 + nt*8 + (lane & 3)*2;
                int nw = col0 >> 2, j0 = col0 & 3;
#pragma unroll
                for (int hh = 0; hh < 2; hh++) {
                    int r = wm*32 + mt*16 + (lane >> 2) + hh*8;
                    epi[(j0*96 + r)*42 + nw]     = acc[mt][nt][hh*2]   + bias_v[mt][hh];
                    epi[((j0+1)*96 + r)*42 + nw] = acc[mt][nt][hh*2+1] + bias_v[mt][hh];
                }
            }
        }
        __syncthreads();

        for (int tk = wid; tk < 416; tk += 12) {
            if (tk < 256) {
                if (lane < 20) {
                    int rr = tk >> 2, j = tk & 3;
                    int row = (rr < 32) ? rr : rr + 32;
                    float2 v = *(const float2*)&epi[(j*96 + row)*42 + lane*2];
                    if (rr < 32) {
                        // q: hi + mi planes
                        uint32_t hi, mi;
                        split2h(v.x, v.y, hi, mi);
                        int dd = rr*16 + ip*4 + j;
                        size_t base = ((size_t)(curb*DD + dd))*NN + hn*40 + lane*2;
                        *(uint32_t*)(g_fq_hi + base) = hi;
                        *(uint32_t*)(g_fq_mi + base) = mi;
                    } else {
                        // k: hi plane only
                        uint32_t hi = pack_h2(v.x, v.y);
                        int dd = (ip*4 + j)*32 + (rr - 32);
                        size_t base = ((size_t)(curb*DD + dd))*NN + hn*40 + lane*2;
                        *(uint32_t*)(g_fk_hi + base) = hi;
                    }
                }
            } else {
                if (lane < 16) {
                    int tv = tk - 256;
                    int nw = tv >> 2, j = tv & 3;
                    float v0 = epi[(j*96 + 32 + lane*2)*42 + nw];
                    float v1 = epi[(j*96 + 33 + lane*2)*42 + nw];
                    uint32_t hi = pack_h2(v0, v1);
                    int n = hn*40 + nw;
                    size_t base = ((size_t)curb*NNP + n)*DD + (ip*4 + j)*32 + lane*2;
                    *(uint32_t*)(g_fvT_hi + base) = hi;
                }
            }
        }
        __syncthreads();   // epi region reused as x stages next unit

        b = nb; h = nh; db = ndb; rb = nrb; rowoff = nro;
    }
}

// ---------------------------------------------------------------------------
// Generic 128x64-tile mma.sync fp16 2-pass GEMM (2 CTAs/SM):
//   C[b, m, n] = sum_k (Ahi+Ami)[m,k] * Bhi[n,k]
// MODE 0: scores (A=fq 2-plane, B=fk_hi, K=1600, C=g_sc [512x512])
// MODE 1: attn@V (A=attn 2-plane, B=fvT_hi, K=512, C=g_op [512x1600])
// stage: Ahi 16K | Ami 16K | Bhi 8K ; stride 40960; 2 stages = 80KB.
// ---------------------------------------------------------------------------
template<int MODE>
__global__ __launch_bounds__(256, 2) void k_gemm()
{
    constexpr int K    = (MODE == 0) ? 1600 : 512;
    constexpr int LD   = (MODE == 0) ? 1600 : 512;
    constexpr int LDC  = (MODE == 0) ? 512  : 1600;
    constexpr long SA  = (MODE == 0) ? (long)DD*NN : (long)DD*DD;
    constexpr long SB  = (MODE == 0) ? (long)DD*NN : (long)NNP*DD;
    constexpr long SC  = (MODE == 0) ? (long)DD*DD : (long)DD*NN;
    constexpr int NCH  = K / 64;

    extern __shared__ __align__(1024) char dsm[];

    const int b  = blockIdx.z;
    const int m0 = blockIdx.y * 128;
    const int n0 = blockIdx.x * 64;
    const int t    = threadIdx.x;
    const int lane = t & 31;
    const int wid  = t >> 5;
    const int wm   = wid & 3;
    const int wn   = wid >> 2;

    const uint32_t smem_u = smem_u32(dsm);

    const __half* Ahi = (MODE == 0 ? g_fq_hi : g_at_hi)  + b*SA + (long)m0*LD;
    const __half* Ami = (MODE == 0 ? g_fq_mi : g_at_mi)  + b*SA + (long)m0*LD;
    const __half* Bhi = (MODE == 0 ? g_fk_hi : g_fvT_hi) + b*SB + (long)n0*LD;
    float* C = (MODE == 0 ? g_sc : g_op) + b*SC;

    auto load_stage = [&](int s, int kc) {
        uint32_t base = smem_u + s*40960;
#pragma unroll
        for (int ii = 0; ii < 4; ii++) {
            int i = t + ii*256;
            int row = i >> 3, seg = i & 7;
            uint32_t off = row*128 + seg*16;
            uint32_t sw  = off ^ ((off >> 3) & 0x70);
            long go = (long)row*LD + kc;
            cpa16(base + sw,         (const char*)(Ahi + go) + seg*16);
            cpa16(base + 16384 + sw, (const char*)(Ami + go) + seg*16);
        }
#pragma unroll
        for (int ii = 0; ii < 2; ii++) {
            int i = t + ii*256;
            int row = i >> 3, seg = i & 7;
            uint32_t off = row*128 + seg*16;
            uint32_t sw  = off ^ ((off >> 3) & 0x70);
            long go = (long)row*LD + kc;
            cpa16(base + 32768 + sw, (const char*)(Bhi + go) + seg*16);
        }
        CPA_COMMIT();
    };

    float acc[2][4][4];
#pragma unroll
    for (int i = 0; i < 2; i++)
#pragma unroll
        for (int j = 0; j < 4; j++)
#pragma unroll
            for (int r = 0; r < 4; r++) acc[i][j][r] = 0.0f;

    load_stage(0, 0);
    load_stage(1, 64);

    const int lr = lane & 15;
    const int lc = lane >> 4;

    for (int c = 0; c < NCH; c++) {
        const int s = c & 1;
        if (c + 1 < NCH) asm volatile("cp.async.wait_group 1;" ::: "memory");
        else             asm volatile("cp.async.wait_group 0;" ::: "memory");
        __syncthreads();

        const uint32_t base = smem_u + s*40960;
#pragma unroll
        for (int kk = 0; kk < 4; kk++) {
            uint32_t a_hi[2][4], a_mi[2][4];
#pragma unroll
            for (int mt = 0; mt < 2; mt++) {
                int row = wm*32 + mt*16 + lr;
                uint32_t off = row*128 + kk*32 + lc*16;
                uint32_t sw  = off ^ ((off >> 3) & 0x70);
                ldsm4(a_hi[mt], base + sw);
                ldsm4(a_mi[mt], base + 16384 + sw);
            }
            uint32_t b_hi[2][4];
#pragma unroll
            for (int bt = 0; bt < 2; bt++) {
                int row = wn*32 + bt*16 + lr;
                uint32_t off = row*128 + kk*32 + lc*16;
                uint32_t sw  = off ^ ((off >> 3) & 0x70);
                ldsm4(b_hi[bt], base + 32768 + sw);
            }
#pragma unroll
            for (int mt = 0; mt < 2; mt++) {
#pragma unroll
                for (int nt = 0; nt < 4; nt++) {
                    int bt = nt >> 1, hf = nt & 1;
                    mma_f16(acc[mt][nt], a_hi[mt], b_hi[bt][hf], b_hi[bt][hf+2]);
                    mma_f16(acc[mt][nt], a_mi[mt], b_hi[bt][hf], b_hi[bt][hf+2]);
                }
            }
        }
        __syncthreads();
        if (c + 2 < NCH) load_stage(s, (c + 2)*64);
    }

    const int rq = lane >> 2;
    const int cq = (lane & 3) * 2;
#pragma unroll
    for (int mt = 0; mt < 2; mt++) {
#pragma unroll
        for (int nt = 0; nt < 4; nt++) {
            int col = n0 + wn*32 + nt*8 + cq;
            int row = m0 + wm*32 + mt*16 + rq;
            float* p0 = C + (long)row*LDC + col;
            *(float2*)p0            = make_float2(acc[mt][nt][0], acc[mt][nt][1]);
            *(float2*)(p0 + 8L*LDC) = make_float2(acc[mt][nt][2], acc[mt][nt][3]);
        }
    }
}

// ---------------------------------------------------------------------------
// K3: softmax over rows of g_sc, writes attn as fp16 hi/mid split.
// ---------------------------------------------------------------------------
__global__ __launch_bounds__(128) void k_softmax()
{
    __shared__ float red[8];
    const size_t row = blockIdx.x;
    const float* s = g_sc + row * DD;
    const int t = threadIdx.x;

    float v0 = s[t], v1 = s[t+128], v2 = s[t+256], v3 = s[t+384];
    float m = fmaxf(fmaxf(v0, v1), fmaxf(v2, v3));
#pragma unroll
    for (int o = 16; o; o >>= 1) m = fmaxf(m, __shfl_xor_sync(0xffffffffu, m, o));
    if ((t & 31) == 0) red[t >> 5] = m;
    __syncthreads();
    m = fmaxf(fmaxf(red[0], red[1]), fmaxf(red[2], red[3]));

    const float inv = 0.04419417382415922f;  // 1/sqrt(512)
    float e0 = __expf((v0 - m) * inv);
    float e1 = __expf((v1 - m) * inv);
    float e2 = __expf((v2 - m) * inv);
    float e3 = __expf((v3 - m) * inv);
    float sum = e0 + e1 + e2 + e3;
#pragma unroll
    for (int o = 16; o; o >>= 1) sum += __shfl_xor_sync(0xffffffffu, sum, o);
    if ((t & 31) == 0) red[4 + (t >> 5)] = sum;
    __syncthreads();
    float r = 1.0f / (red[4] + red[5] + red[6] + red[7]);

    size_t base = row * DD;
#pragma unroll
    for (int q = 0; q < 4; q++) {
        float a = ((q == 0) ? e0 : (q == 1) ? e1 : (q == 2) ? e2 : e3) * r;
        __half hi = __float2half_rn(a);
        size_t idx = base + t + q*128;
        g_at_hi[idx] = hi;
        g_at_mi[idx] = __float2half_rn(a - __half2float(hi));
    }
}

// ---------------------------------------------------------------------------
// K5: PERSISTENT pixel_shuffle gather + final 1x1 conv (32 -> 256).
// bf16 split-3 (unchanged — store-bound; keeps error slack).
// ---------------------------------------------------------------------------
__global__ __launch_bounds__(256, 2) void k_final(
    const float* __restrict__ bu, float* __restrict__ out)
{
    extern __shared__ __align__(1024) char sm[];
    const uint32_t su = smem_u32(sm);
    const int t = threadIdx.x, lane = t & 31, wid = t >> 5;
    const int wm = wid & 3, wn = wid >> 2;
    const int rq = lane >> 2, cq = (lane & 3) * 2;

    {
        const uint4* src_h = (const uint4*)((const char*)g_wu_hi + t*64);
        const uint4* src_m = (const uint4*)((const char*)g_wu_mi + t*64);
#pragma unroll
        for (int c = 0; c < 4; c++) {
            *(uint4*)(sm + t*80 + c*16)         = src_h[c];
            *(uint4*)(sm + 20480 + t*80 + c*16) = src_m[c];
        }
    }

    float bb[4][2];
#pragma unroll
    for (int mt = 0; mt < 4; mt++) {
        int ch0 = wm*64 + mt*16 + rq;
        bb[mt][0] = bu[ch0];
        bb[mt][1] = bu[ch0 + 8];
    }

    const int gc = t >> 3;
    const int ii = (t >> 2) & 1;
    const int gj = t & 3;

    const int cta = blockIdx.x;
    int u        = (3200 * cta) / 296;
    const int u1 = (3200 * (cta + 1)) / 296;

    float4 v0, v1;
    auto prefetch = [&](int uu) {
        int pb = uu / 400, r = uu - pb*400;
        int php = r / 5, pwb = r - (r/5)*5;
        int i0 = (2*php) & 3, hn = php >> 1;
        int d  = gc*16 + (i0 + ii)*4 + gj;
        const float* src = g_op + ((size_t)(pb*DD + d))*NN + hn*40 + pwb*8;
        v0 = *(const float4*)src;
        v1 = *(const float4*)(src + 4);
    };
    if (u < u1) prefetch(u);

    for (; u < u1; u++) {
        const int s = u & 1;
        const int b = u / 400, r = u - b*400;
        const int hp = r / 5, wblk = r - (r/5)*5;

        __syncthreads();

        {
            float vv[8] = {v0.x, v0.y, v0.z, v0.w, v1.x, v1.y, v1.z, v1.w};
#pragma unroll
            for (int nw = 0; nw < 8; nw++) {
                int px = ii*32 + nw*4 + gj;
                uint32_t a = 40960 + s*8192 + gc*128 + (((px >> 3) ^ (gc & 7))*16) + (px & 7)*2;
                uint32_t uv = __float_as_uint(vv[nw]);
                __nv_bfloat16 h = __ushort_as_bfloat16((unsigned short)(uv >> 16));
                __nv_bfloat16 m = __float2bfloat16(vv[nw] - __uint_as_float(uv & 0xFFFF0000u));
                *(__nv_bfloat16*)(sm + a)        = h;
                *(__nv_bfloat16*)(sm + a + 4096) = m;
            }
        }
        if (u + 1 < u1) prefetch(u + 1);
        __syncthreads();

        float acc[4][4][4];
#pragma unroll
        for (int i = 0; i < 4; i++)
#pragma unroll
            for (int j = 0; j < 4; j++)
#pragma unroll
                for (int rr = 0; rr < 4; rr++) acc[i][j][rr] = 0.0f;

#pragma unroll
        for (int kk = 0; kk < 2; kk++) {
            uint32_t ah[4][4], am[4][4];
#pragma unroll
            for (int mt = 0; mt < 4; mt++) {
                int row = wm*64 + mt*16 + (lane & 15);
                uint32_t addr = su + row*80 + (kk*2 + (lane >> 4))*16;
                ldsm4(ah[mt], addr);
                ldsm4(am[mt], addr + 20480);
            }
            const int krow = kk*16 + (lane & 15);
            uint32_t bh[2][4], bm2[2][4];
#pragma unroll
            for (int tt = 0; tt < 2; tt++) {
                int cc = wn*4 + tt*2 + (lane >> 4);
                uint32_t addr = su + 40960 + s*8192 + krow*128 + ((cc ^ (krow & 7))*16);
                ldsm4t(bh[tt], addr);
                ldsm4t(bm2[tt], addr + 4096);
            }
#pragma unroll
            for (int mt = 0; mt < 4; mt++) {
#pragma unroll
                for (int nt = 0; nt < 4; nt++) {
                    int tt = nt >> 1, hf = nt & 1;
                    mma_bf16(acc[mt][nt], ah[mt], bh[tt][hf*2],  bh[tt][hf*2+1]);
                    mma_bf16(acc[mt][nt], ah[mt], bm2[tt][hf*2], bm2[tt][hf*2+1]);
                    mma_bf16(acc[mt][nt], am[mt], bh[tt][hf*2],  bh[tt][hf*2+1]);
                }
            }
        }

        const int h = hp*2 + wn;
#pragma unroll
        for (int mt = 0; mt < 4; mt++) {
            int ch0 = wm*64 + mt*16 + rq;
#pragma unroll
            for (int nt = 0; nt < 4; nt++) {
                int w = wblk*32 + nt*8 + cq;
                float* p0 = out + ((size_t)(b*CHN + ch0))*HW + (size_t)h*160 + w;
                *(float2*)p0          = make_float2(acc[mt][nt][0] + bb[mt][0], acc[mt][nt][1] + bb[mt][0]);
                *(float2*)(p0 + 8*HW) = make_float2(acc[mt][nt][2] + bb[mt][1], acc[mt][nt][3] + bb[mt][1]);
            }
        }
    }
}

// ---------------------------------------------------------------------------
extern "C" void kernel_launch(void* const* d_in, const int* in_sizes, int n_in,
                              void* d_out, int out_size)
{
    (void)in_sizes; (void)n_in; (void)out_size;
    const float* rgb   = (const float*)d_in[0];
    const float* depth = (const float*)d_in[1];
    const float* Wq    = (const float*)d_in[2];
    const float* bq    = (const float*)d_in[3];
    const float* Wk    = (const float*)d_in[4];
    const float* bk    = (const float*)d_in[5];
    const float* Wv    = (const float*)d_in[6];
    const float* bv    = (const float*)d_in[7];
    const float* Wu    = (const float*)d_in[8];
    const float* bu    = (const float*)d_in[9];
    float* out = (float*)d_out;

    cudaFuncSetAttribute(k_projT,   cudaFuncAttributeMaxDynamicSharedMemorySize, 163840);
    cudaFuncSetAttribute(k_gemm<0>, cudaFuncAttributeMaxDynamicSharedMemorySize, 81920);
    cudaFuncSetAttribute(k_gemm<1>, cudaFuncAttributeMaxDynamicSharedMemorySize, 81920);
    cudaFuncSetAttribute(k_final,   cudaFuncAttributeMaxDynamicSharedMemorySize, 57344);

    k_wsplit <<<96, 256>>>(Wq, Wv, Wk, Wu);
    k_projT  <<<148, 384, 163840>>>(rgb, depth, bq, bk, bv);
    k_gemm<0><<<dim3(8, 4, NB), 256, 81920>>>();
    k_softmax<<<NB*DD, 128>>>();
    k_gemm<1><<<dim3(25, 4, NB), 256, 81920>>>();
    k_final  <<<296, 256, 57344>>>(bu, out);
}

// round 10
// speedup vs baseline: 3.4805x; 1.1730x over previous
#include <cuda_runtime.h>
#include <cuda_bf16.h>
#include <cuda_fp16.h>
#include <cstdint>

#define NB  8
#define CHN 256
#define HW  25600
#define DD  512
#define NN  1600
#define NNP 1664

// ---------------- scratch (__device__ globals; allocation-free) ------------
__device__ float g_sc[NB*DD*DD];    // scores fp32 [d][e']
__device__ float g_op[NB*DD*NN];    // attn@V output fp32 [d][n]
__device__ __align__(128) __half g_fq_hi[NB*DD*NN];   // [d][n] single plane
__device__ __align__(128) __half g_fk_hi[NB*DD*NN];   // [e'][n] single plane
__device__ __align__(128) __half g_fvT_hi[NB*NNP*DD]; // [n][e'] single plane
__device__ __align__(128) __half g_at_hi[NB*DD*DD];   // [d][e'] single plane
__device__ __align__(128) __half g_w_hi[96*256];      // qkv weights (2 planes)
__device__ __align__(128) __half g_w_mi[96*256];
__device__ __align__(128) __nv_bfloat16 g_wu_hi[256*32];  // Wu split (bf16, k_final)
__device__ __align__(128) __nv_bfloat16 g_wu_mi[256*32];

typedef unsigned long long u64;

// ---------------- PTX helpers (baseline ISA only) ---------------------------
__device__ __forceinline__ uint32_t smem_u32(const void* p) {
    uint32_t a;
    asm("{ .reg .u64 t; cvta.to.shared.u64 t, %1; cvt.u32.u64 %0, t; }" : "=r"(a) : "l"(p));
    return a;
}
__device__ __forceinline__ void cpa16(uint32_t s, const void* g) {
    asm volatile("cp.async.cg.shared.global [%0], [%1], 16;" :: "r"(s), "l"(g));
}
#define CPA_COMMIT() asm volatile("cp.async.commit_group;" ::: "memory")

__device__ __forceinline__ void ldsm4(uint32_t* r, uint32_t a) {
    asm volatile("ldmatrix.sync.aligned.m8n8.x4.shared.b16 {%0,%1,%2,%3}, [%4];"
        : "=r"(r[0]), "=r"(r[1]), "=r"(r[2]), "=r"(r[3]) : "r"(a));
}
__device__ __forceinline__ void ldsm4t(uint32_t* r, uint32_t a) {
    asm volatile("ldmatrix.sync.aligned.m8n8.x4.trans.shared.b16 {%0,%1,%2,%3}, [%4];"
        : "=r"(r[0]), "=r"(r[1]), "=r"(r[2]), "=r"(r[3]) : "r"(a));
}
__device__ __forceinline__ void ldsm2t(uint32_t* r, uint32_t a) {
    asm volatile("ldmatrix.sync.aligned.m8n8.x2.trans.shared.b16 {%0,%1}, [%2];"
        : "=r"(r[0]), "=r"(r[1]) : "r"(a));
}
// fp16 mma (f32 accum)
__device__ __forceinline__ void mma_f16(float* d, const uint32_t* a, uint32_t b0, uint32_t b1) {
    asm volatile(
        "mma.sync.aligned.m16n8k16.row.col.f32.f16.f16.f32 "
        "{%0,%1,%2,%3},{%4,%5,%6,%7},{%8,%9},{%0,%1,%2,%3};"
        : "+f"(d[0]), "+f"(d[1]), "+f"(d[2]), "+f"(d[3])
        : "r"(a[0]), "r"(a[1]), "r"(a[2]), "r"(a[3]), "r"(b0), "r"(b1));
}
// bf16 mma (k_final)
__device__ __forceinline__ void mma_bf16(float* d, const uint32_t* a, uint32_t b0, uint32_t b1) {
    asm volatile(
        "mma.sync.aligned.m16n8k16.row.col.f32.bf16.bf16.f32 "
        "{%0,%1,%2,%3},{%4,%5,%6,%7},{%8,%9},{%0,%1,%2,%3};"
        : "+f"(d[0]), "+f"(d[1]), "+f"(d[2]), "+f"(d[3])
        : "r"(a[0]), "r"(a[1]), "r"(a[2]), "r"(a[3]), "r"(b0), "r"(b1));
}

__device__ __forceinline__ void split_bf16(float v, __nv_bfloat16 &h, __nv_bfloat16 &m) {
    h = __float2bfloat16(v);
    m = __float2bfloat16(v - __bfloat162float(h));
}
// pack 2 floats -> fp16x2 (lo=a, hi=b)
__device__ __forceinline__ uint32_t pack_h2(float a, float b) {
    uint32_t r;
    asm("cvt.rn.f16x2.f32 %0, %1, %2;" : "=r"(r) : "f"(b), "f"(a));
    return r;
}

// ---------------------------------------------------------------------------
// K-1: split W q/v/k rows into fp16 hi/mid planes, Wu into bf16 planes.
// ---------------------------------------------------------------------------
__global__ __launch_bounds__(256) void k_wsplit(
    const float* __restrict__ Wq, const float* __restrict__ Wv, const float* __restrict__ Wk,
    const float* __restrict__ Wu)
{
    int i = blockIdx.x * 256 + threadIdx.x;
    if (i < 96*256) {
        int r = i >> 8, kk = i & 255;
        float v = (r < 32) ? Wq[r*256 + kk] : ((r < 64) ? Wv[(r-32)*256 + kk] : Wk[(r-64)*256 + kk]);
        __half h = __float2half_rn(v);
        g_w_hi[i] = h;
        g_w_mi[i] = __float2half_rn(v - __half2float(h));
    }
    if (i < 256*32) {
        __nv_bfloat16 h, m;
        split_bf16(Wu[i], h, m);
        g_wu_hi[i] = h; g_wu_mi[i] = m;
    }
}

// ---------------------------------------------------------------------------
// K1: PERSISTENT tensor-core fused q/k/v 1x1 conv + pixel_unshuffle.
// 384 threads / 12 warps (3/SMSP), warp grid 3m x 4n, warp tile 32x40.
// fp16 2-pass: W (2 planes, smem-resident) x x (SINGLE fp16 plane per source).
// Outputs: fq/fk/fvT all SINGLE fp16 plane.
// ---------------------------------------------------------------------------
__global__ __launch_bounds__(384, 1) void k_projT(
    const float* __restrict__ rgb, const float* __restrict__ depth,
    const float* __restrict__ bq, const float* __restrict__ bk,
    const float* __restrict__ bv)
{
    extern __shared__ __align__(1024) char sm[];
    const int t = threadIdx.x, lane = t & 31, wid = t >> 5;
    const int wn = wid & 3, wm = wid >> 2;       // wm 0..2, wn 0..3
    const uint32_t su = smem_u32(sm);
    const uint32_t XB = su + 98304;
    float* const epi = (float*)(sm + 98304);

    // ---- W planes into smem (once per CTA) ----
    for (int i = t; i < 96*32; i += 384) {
        int m = i >> 5, c = i & 31;
        uint4 v1 = *(const uint4*)((const char*)g_w_hi + m*512 + c*16);
        uint4 v2 = *(const uint4*)((const char*)g_w_mi + m*512 + c*16);
        int sw = (c ^ (m & 7)) * 16;
        *(uint4*)(sm + m*512 + sw)         = v1;
        *(uint4*)(sm + 49152 + m*512 + sw) = v2;
    }

    float bias_v[2][2];
#pragma unroll
    for (int mt = 0; mt < 2; mt++)
#pragma unroll
        for (int hh = 0; hh < 2; hh++) {
            int r = wm*32 + mt*16 + (lane >> 2) + hh*8;
            bias_v[mt][hh] = (r < 32) ? bq[r] : ((r < 64) ? bv[r-32] : bk[r-64]);
        }

    // per-thread ldg mapping: 2560 float4 items (src x 32 cin x 40 c4)
    int cin_[7], c4_[7], pl_[7];
    bool val_[7];
#pragma unroll
    for (int j = 0; j < 7; j++) {
        int item = t + j*384;
        val_[j] = item < 2560;
        int it2 = val_[j] ? item : 0;
        int src = (it2 >= 1280) ? 1 : 0;
        int rem = it2 - src*1280;
        cin_[j] = rem / 40; c4_[j] = rem % 40;
        pl_[j]  = src ? 12288 : 0;
    }
    __syncthreads();

    const int cta = blockIdx.x;
    int u        = (1280 * cta) / 148;
    const int u1 = (1280 * (cta + 1)) / 148;

    int b = u / 160, h = u - b*160;
    const float* db = depth + (size_t)b*CHN*HW;
    const float* rb = rgb   + (size_t)b*CHN*HW;
    size_t rowoff = (size_t)h * 160;

    float4 rv[7];
    auto ldg_chunk = [&](int c, const float* dB, const float* rB, size_t ro) {
#pragma unroll
        for (int j = 0; j < 7; j++) {
            if (val_[j]) {
                const float* bp = pl_[j] ? rB : dB;
                rv[j] = *(const float4*)(bp + (size_t)(c*32 + cin_[j])*HW + ro + c4_[j]*4);
            }
        }
    };
    auto sts_chunk = [&](int s) {
        const int soff = 98304 + s*24576;
#pragma unroll
        for (int j = 0; j < 7; j++) {
            if (val_[j]) {
                int row = cin_[j], c4 = c4_[j];
                int a = soff + pl_[j] + row*384 + (((c4 >> 1) ^ (row & 7)) * 16) + (c4 & 1)*8;
                uint32_t h01 = pack_h2(rv[j].x, rv[j].y);
                uint32_t h23 = pack_h2(rv[j].z, rv[j].w);
                *(uint2*)(sm + a) = make_uint2(h01, h23);
            }
        }
    };

    ldg_chunk(0, db, rb, rowoff);

    for (; u < u1; u++) {
        const int ip = h & 3, hn = h >> 2, curb = b;

        int nb = b, nh = h + 1;
        if (nh == 160) { nh = 0; nb = b + 1; }
        const bool has_next = (u + 1 < u1);
        const float* ndb = depth + (size_t)nb*CHN*HW;
        const float* nrb = rgb   + (size_t)nb*CHN*HW;
        const size_t nro = (size_t)nh * 160;

        sts_chunk(0);
        ldg_chunk(1, db, rb, rowoff);

        float acc[2][5][4];
#pragma unroll
        for (int i = 0; i < 2; i++)
#pragma unroll
            for (int j = 0; j < 5; j++)
#pragma unroll
                for (int r = 0; r < 4; r++) acc[i][j][r] = 0.0f;

        const int pls = (wm == 2) ? 12288 : 0;   // this warp's source plane

        for (int c = 0; c < 8; c++) {
            __syncthreads();
            if (c + 1 < 8) sts_chunk((c + 1) & 1);
            if (c + 2 < 8)                    ldg_chunk(c + 2, db, rb, rowoff);
            else if (c == 6 && has_next)      ldg_chunk(0, ndb, nrb, nro);
            __syncthreads();

            const uint32_t xs = XB + (c & 1)*24576;
#pragma unroll
            for (int kk = 0; kk < 2; kk++) {
                uint32_t ah[2][4], am[2][4];
#pragma unroll
                for (int mt = 0; mt < 2; mt++) {
                    int m = wm*32 + mt*16 + (lane & 15);
                    int ca = c*4 + kk*2 + (lane >> 4);
                    uint32_t addr = su + m*512 + (ca ^ (m & 7))*16;
                    ldsm4(ah[mt], addr);
                    ldsm4(am[mt], addr + 49152);
                }
                const int krow = kk*16 + (lane & 15);
                const int swz = krow & 7;
                const uint32_t rbase_a = xs + pls + krow*384;
                uint32_t bh[2][4], bh2[2];
#pragma unroll
                for (int tt = 0; tt < 2; tt++) {
                    int cc = wn*5 + tt*2 + (lane >> 4);
                    ldsm4t(bh[tt], rbase_a + (cc ^ swz)*16);
                }
                {
                    int cc = wn*5 + 4;
                    ldsm2t(bh2, rbase_a + (cc ^ swz)*16);
                }
#pragma unroll
                for (int mt = 0; mt < 2; mt++) {
#pragma unroll
                    for (int nt = 0; nt < 5; nt++) {
                        uint32_t b0, b1;
                        if (nt < 4) {
                            int g = nt >> 1, hf = nt & 1;
                            b0 = bh[g][hf*2]; b1 = bh[g][hf*2+1];
                        } else {
                            b0 = bh2[0]; b1 = bh2[1];
                        }
                        mma_f16(acc[mt][nt], ah[mt], b0, b1);
                        mma_f16(acc[mt][nt], am[mt], b0, b1);
                    }
                }
            }
        }

        // ---- epilogue: stage into epi, coalesced drain ----
        __syncthreads();
#pragma unroll
        for (int mt = 0; mt < 2; mt++) {
#pragma unroll
            for (int nt = 0; nt < 5; nt++) {
                int col0 = wn*40 + nt*8 + (lane & 3)*2;
                int nw = col0 >> 2, j0 = col0 & 3;
#pragma unroll
                for (int hh = 0; hh < 2; hh++) {
                    int r = wm*32 + mt*16 + (lane >> 2) + hh*8;
                    epi[(j0*96 + r)*42 + nw]     = acc[mt][nt][hh*2]   + bias_v[mt][hh];
                    epi[((j0+1)*96 + r)*42 + nw] = acc[mt][nt][hh*2+1] + bias_v[mt][hh];
                }
            }
        }
        __syncthreads();

        for (int tk = wid; tk < 416; tk += 12) {
            if (tk < 256) {
                if (lane < 20) {
                    int rr = tk >> 2, j = tk & 3;
                    int row = (rr < 32) ? rr : rr + 32;
                    float2 v = *(const float2*)&epi[(j*96 + row)*42 + lane*2];
                    uint32_t hi = pack_h2(v.x, v.y);
                    int dd = (rr < 32) ? (rr*16 + ip*4 + j)
                                       : ((ip*4 + j)*32 + (rr - 32));
                    size_t base = ((size_t)(curb*DD + dd))*NN + hn*40 + lane*2;
                    __half* dh = (rr < 32) ? g_fq_hi : g_fk_hi;
                    *(uint32_t*)(dh + base) = hi;
                }
            } else {
                if (lane < 16) {
                    int tv = tk - 256;
                    int nw = tv >> 2, j = tv & 3;
                    float v0 = epi[(j*96 + 32 + lane*2)*42 + nw];
                    float v1 = epi[(j*96 + 33 + lane*2)*42 + nw];
                    uint32_t hi = pack_h2(v0, v1);
                    int n = hn*40 + nw;
                    size_t base = ((size_t)curb*NNP + n)*DD + (ip*4 + j)*32 + lane*2;
                    *(uint32_t*)(g_fvT_hi + base) = hi;
                }
            }
        }
        __syncthreads();   // epi region reused as x stages next unit

        b = nb; h = nh; db = ndb; rb = nrb; rowoff = nro;
    }
}

// ---------------------------------------------------------------------------
// Generic 128x64-tile mma.sync single-pass fp16 GEMM (2 CTAs/SM, 3 stages):
//   C[b, m, n] = sum_k Ahi[m,k] * Bhi[n,k]
// MODE 0: scores (A=fq_hi, B=fk_hi, K=1600, C=g_sc [512x512])
// MODE 1: attn@V (A=at_hi, B=fvT_hi, K=512, C=g_op [512x1600])
// stage: Ahi 16K | Bhi 8K ; stride 24576; 3 stages = 72KB.
// ---------------------------------------------------------------------------
template<int MODE>
__global__ __launch_bounds__(256, 2) void k_gemm()
{
    constexpr int K    = (MODE == 0) ? 1600 : 512;
    constexpr int LD   = (MODE == 0) ? 1600 : 512;
    constexpr int LDC  = (MODE == 0) ? 512  : 1600;
    constexpr long SA  = (MODE == 0) ? (long)DD*NN : (long)DD*DD;
    constexpr long SB  = (MODE == 0) ? (long)DD*NN : (long)NNP*DD;
    constexpr long SC  = (MODE == 0) ? (long)DD*DD : (long)DD*NN;
    constexpr int NCH  = K / 64;

    extern __shared__ __align__(1024) char dsm[];

    const int b  = blockIdx.z;
    const int m0 = blockIdx.y * 128;
    const int n0 = blockIdx.x * 64;
    const int t    = threadIdx.x;
    const int lane = t & 31;
    const int wid  = t >> 5;
    const int wm   = wid & 3;
    const int wn   = wid >> 2;

    const uint32_t smem_u = smem_u32(dsm);

    const __half* Ahi = (MODE == 0 ? g_fq_hi : g_at_hi)  + b*SA + (long)m0*LD;
    const __half* Bhi = (MODE == 0 ? g_fk_hi : g_fvT_hi) + b*SB + (long)n0*LD;
    float* C = (MODE == 0 ? g_sc : g_op) + b*SC;

    auto load_stage = [&](int s, int kc) {
        uint32_t base = smem_u + s*24576;
#pragma unroll
        for (int ii = 0; ii < 4; ii++) {
            int i = t + ii*256;
            int row = i >> 3, seg = i & 7;
            uint32_t off = row*128 + seg*16;
            uint32_t sw  = off ^ ((off >> 3) & 0x70);
            long go = (long)row*LD + kc;
            cpa16(base + sw, (const char*)(Ahi + go) + seg*16);
        }
#pragma unroll
        for (int ii = 0; ii < 2; ii++) {
            int i = t + ii*256;
            int row = i >> 3, seg = i & 7;
            uint32_t off = row*128 + seg*16;
            uint32_t sw  = off ^ ((off >> 3) & 0x70);
            long go = (long)row*LD + kc;
            cpa16(base + 16384 + sw, (const char*)(Bhi + go) + seg*16);
        }
        CPA_COMMIT();
    };

    float acc[2][4][4];
#pragma unroll
    for (int i = 0; i < 2; i++)
#pragma unroll
        for (int j = 0; j < 4; j++)
#pragma unroll
            for (int r = 0; r < 4; r++) acc[i][j][r] = 0.0f;

    load_stage(0, 0);
    load_stage(1, 64);
    load_stage(2, 128);   // NCH >= 8 in both modes

    const int lr = lane & 15;
    const int lc = lane >> 4;

    for (int c = 0; c < NCH; c++) {
        const int s = c - (c/3)*3;
        if (c + 2 < NCH)      asm volatile("cp.async.wait_group 2;" ::: "memory");
        else if (c + 1 < NCH) asm volatile("cp.async.wait_group 1;" ::: "memory");
        else                  asm volatile("cp.async.wait_group 0;" ::: "memory");
        __syncthreads();

        const uint32_t base = smem_u + s*24576;
#pragma unroll
        for (int kk = 0; kk < 4; kk++) {
            uint32_t a_hi[2][4];
#pragma unroll
            for (int mt = 0; mt < 2; mt++) {
                int row = wm*32 + mt*16 + lr;
                uint32_t off = row*128 + kk*32 + lc*16;
                uint32_t sw  = off ^ ((off >> 3) & 0x70);
                ldsm4(a_hi[mt], base + sw);
            }
            uint32_t b_hi[2][4];
#pragma unroll
            for (int bt = 0; bt < 2; bt++) {
                int row = wn*32 + bt*16 + lr;
                uint32_t off = row*128 + kk*32 + lc*16;
                uint32_t sw  = off ^ ((off >> 3) & 0x70);
                ldsm4(b_hi[bt], base + 16384 + sw);
            }
#pragma unroll
            for (int mt = 0; mt < 2; mt++) {
#pragma unroll
                for (int nt = 0; nt < 4; nt++) {
                    int bt = nt >> 1, hf = nt & 1;
                    mma_f16(acc[mt][nt], a_hi[mt], b_hi[bt][hf], b_hi[bt][hf+2]);
                }
            }
        }
        __syncthreads();
        if (c + 3 < NCH) load_stage(s, (c + 3)*64);
    }

    const int rq = lane >> 2;
    const int cq = (lane & 3) * 2;
#pragma unroll
    for (int mt = 0; mt < 2; mt++) {
#pragma unroll
        for (int nt = 0; nt < 4; nt++) {
            int col = n0 + wn*32 + nt*8 + cq;
            int row = m0 + wm*32 + mt*16 + rq;
            float* p0 = C + (long)row*LDC + col;
            *(float2*)p0            = make_float2(acc[mt][nt][0], acc[mt][nt][1]);
            *(float2*)(p0 + 8L*LDC) = make_float2(acc[mt][nt][2], acc[mt][nt][3]);
        }
    }
}

// ---------------------------------------------------------------------------
// K3: softmax over rows of g_sc, writes attn as single fp16 plane.
// ---------------------------------------------------------------------------
__global__ __launch_bounds__(128) void k_softmax()
{
    __shared__ float red[8];
    const size_t row = blockIdx.x;
    const float* s = g_sc + row * DD;
    const int t = threadIdx.x;

    float v0 = s[t], v1 = s[t+128], v2 = s[t+256], v3 = s[t+384];
    float m = fmaxf(fmaxf(v0, v1), fmaxf(v2, v3));
#pragma unroll
    for (int o = 16; o; o >>= 1) m = fmaxf(m, __shfl_xor_sync(0xffffffffu, m, o));
    if ((t & 31) == 0) red[t >> 5] = m;
    __syncthreads();
    m = fmaxf(fmaxf(red[0], red[1]), fmaxf(red[2], red[3]));

    const float inv = 0.04419417382415922f;  // 1/sqrt(512)
    float e0 = __expf((v0 - m) * inv);
    float e1 = __expf((v1 - m) * inv);
    float e2 = __expf((v2 - m) * inv);
    float e3 = __expf((v3 - m) * inv);
    float sum = e0 + e1 + e2 + e3;
#pragma unroll
    for (int o = 16; o; o >>= 1) sum += __shfl_xor_sync(0xffffffffu, sum, o);
    if ((t & 31) == 0) red[4 + (t >> 5)] = sum;
    __syncthreads();
    float r = 1.0f / (red[4] + red[5] + red[6] + red[7]);

    size_t base = row * DD;
    g_at_hi[base + t]       = __float2half_rn(e0 * r);
    g_at_hi[base + t + 128] = __float2half_rn(e1 * r);
    g_at_hi[base + t + 256] = __float2half_rn(e2 * r);
    g_at_hi[base + t + 384] = __float2half_rn(e3 * r);
}

// ---------------------------------------------------------------------------
// K5: PERSISTENT pixel_shuffle gather + final 1x1 conv (32 -> 256).
// bf16 split-3 (unchanged — store-bound; keeps error slack).
// ---------------------------------------------------------------------------
__global__ __launch_bounds__(256, 2) void k_final(
    const float* __restrict__ bu, float* __restrict__ out)
{
    extern __shared__ __align__(1024) char sm[];
    const uint32_t su = smem_u32(sm);
    const int t = threadIdx.x, lane = t & 31, wid = t >> 5;
    const int wm = wid & 3, wn = wid >> 2;
    const int rq = lane >> 2, cq = (lane & 3) * 2;

    {
        const uint4* src_h = (const uint4*)((const char*)g_wu_hi + t*64);
        const uint4* src_m = (const uint4*)((const char*)g_wu_mi + t*64);
#pragma unroll
        for (int c = 0; c < 4; c++) {
            *(uint4*)(sm + t*80 + c*16)         = src_h[c];
            *(uint4*)(sm + 20480 + t*80 + c*16) = src_m[c];
        }
    }

    float bb[4][2];
#pragma unroll
    for (int mt = 0; mt < 4; mt++) {
        int ch0 = wm*64 + mt*16 + rq;
        bb[mt][0] = bu[ch0];
        bb[mt][1] = bu[ch0 + 8];
    }

    const int gc = t >> 3;
    const int ii = (t >> 2) & 1;
    const int gj = t & 3;

    const int cta = blockIdx.x;
    int u        = (3200 * cta) / 296;
    const int u1 = (3200 * (cta + 1)) / 296;

    float4 v0, v1;
    auto prefetch = [&](int uu) {
        int pb = uu / 400, r = uu - pb*400;
        int php = r / 5, pwb = r - (r/5)*5;
        int i0 = (2*php) & 3, hn = php >> 1;
        int d  = gc*16 + (i0 + ii)*4 + gj;
        const float* src = g_op + ((size_t)(pb*DD + d))*NN + hn*40 + pwb*8;
        v0 = *(const float4*)src;
        v1 = *(const float4*)(src + 4);
    };
    if (u < u1) prefetch(u);

    for (; u < u1; u++) {
        const int s = u & 1;
        const int b = u / 400, r = u - b*400;
        const int hp = r / 5, wblk = r - (r/5)*5;

        __syncthreads();

        {
            float vv[8] = {v0.x, v0.y, v0.z, v0.w, v1.x, v1.y, v1.z, v1.w};
#pragma unroll
            for (int nw = 0; nw < 8; nw++) {
                int px = ii*32 + nw*4 + gj;
                uint32_t a = 40960 + s*8192 + gc*128 + (((px >> 3) ^ (gc & 7))*16) + (px & 7)*2;
                uint32_t uv = __float_as_uint(vv[nw]);
                __nv_bfloat16 h = __ushort_as_bfloat16((unsigned short)(uv >> 16));
                __nv_bfloat16 m = __float2bfloat16(vv[nw] - __uint_as_float(uv & 0xFFFF0000u));
                *(__nv_bfloat16*)(sm + a)        = h;
                *(__nv_bfloat16*)(sm + a + 4096) = m;
            }
        }
        if (u + 1 < u1) prefetch(u + 1);
        __syncthreads();

        float acc[4][4][4];
#pragma unroll
        for (int i = 0; i < 4; i++)
#pragma unroll
            for (int j = 0; j < 4; j++)
#pragma unroll
                for (int rr = 0; rr < 4; rr++) acc[i][j][rr] = 0.0f;

#pragma unroll
        for (int kk = 0; kk < 2; kk++) {
            uint32_t ah[4][4], am[4][4];
#pragma unroll
            for (int mt = 0; mt < 4; mt++) {
                int row = wm*64 + mt*16 + (lane & 15);
                uint32_t addr = su + row*80 + (kk*2 + (lane >> 4))*16;
                ldsm4(ah[mt], addr);
                ldsm4(am[mt], addr + 20480);
            }
            const int krow = kk*16 + (lane & 15);
            uint32_t bh[2][4], bm2[2][4];
#pragma unroll
            for (int tt = 0; tt < 2; tt++) {
                int cc = wn*4 + tt*2 + (lane >> 4);
                uint32_t addr = su + 40960 + s*8192 + krow*128 + ((cc ^ (krow & 7))*16);
                ldsm4t(bh[tt], addr);
                ldsm4t(bm2[tt], addr + 4096);
            }
#pragma unroll
            for (int mt = 0; mt < 4; mt++) {
#pragma unroll
                for (int nt = 0; nt < 4; nt++) {
                    int tt = nt >> 1, hf = nt & 1;
                    mma_bf16(acc[mt][nt], ah[mt], bh[tt][hf*2],  bh[tt][hf*2+1]);
                    mma_bf16(acc[mt][nt], ah[mt], bm2[tt][hf*2], bm2[tt][hf*2+1]);
                    mma_bf16(acc[mt][nt], am[mt], bh[tt][hf*2],  bh[tt][hf*2+1]);
                }
            }
        }

        const int h = hp*2 + wn;
#pragma unroll
        for (int mt = 0; mt < 4; mt++) {
            int ch0 = wm*64 + mt*16 + rq;
#pragma unroll
            for (int nt = 0; nt < 4; nt++) {
                int w = wblk*32 + nt*8 + cq;
                float* p0 = out + ((size_t)(b*CHN + ch0))*HW + (size_t)h*160 + w;
                *(float2*)p0          = make_float2(acc[mt][nt][0] + bb[mt][0], acc[mt][nt][1] + bb[mt][0]);
                *(float2*)(p0 + 8*HW) = make_float2(acc[mt][nt][2] + bb[mt][1], acc[mt][nt][3] + bb[mt][1]);
            }
        }
    }
}

// ---------------------------------------------------------------------------
extern "C" void kernel_launch(void* const* d_in, const int* in_sizes, int n_in,
                              void* d_out, int out_size)
{
    (void)in_sizes; (void)n_in; (void)out_size;
    const float* rgb   = (const float*)d_in[0];
    const float* depth = (const float*)d_in[1];
    const float* Wq    = (const float*)d_in[2];
    const float* bq    = (const float*)d_in[3];
    const float* Wk    = (const float*)d_in[4];
    const float* bk    = (const float*)d_in[5];
    const float* Wv    = (const float*)d_in[6];
    const float* bv    = (const float*)d_in[7];
    const float* Wu    = (const float*)d_in[8];
    const float* bu    = (const float*)d_in[9];
    float* out = (float*)d_out;

    cudaFuncSetAttribute(k_projT,   cudaFuncAttributeMaxDynamicSharedMemorySize, 163840);
    cudaFuncSetAttribute(k_gemm<0>, cudaFuncAttributeMaxDynamicSharedMemorySize, 73728);
    cudaFuncSetAttribute(k_gemm<1>, cudaFuncAttributeMaxDynamicSharedMemorySize, 73728);
    cudaFuncSetAttribute(k_final,   cudaFuncAttributeMaxDynamicSharedMemorySize, 57344);

    k_wsplit <<<96, 256>>>(Wq, Wv, Wk, Wu);
    k_projT  <<<148, 384, 163840>>>(rgb, depth, bq, bk, bv);
    k_gemm<0><<<dim3(8, 4, NB), 256, 73728>>>();
    k_softmax<<<NB*DD, 128>>>();
    k_gemm<1><<<dim3(25, 4, NB), 256, 73728>>>();
    k_final  <<<296, 256, 57344>>>(bu, out);
}

// round 11
// speedup vs baseline: 3.6840x; 1.0585x over previous
#include <cuda_runtime.h>
#include <cuda_fp16.h>
#include <cstdint>

#define NB  8
#define CHN 256
#define HW  25600
#define DD  512
#define NN  1600
#define NNP 1664

// ---------------- scratch (__device__ globals; allocation-free) ------------
__device__ float g_sc[NB*DD*DD];    // scores fp32 [d][e']
__device__ __align__(128) __half g_oph[NB*DD*NN];     // attn@V output fp16 [d][n]
__device__ __align__(128) __half g_fq_hi[NB*DD*NN];   // [d][n] single plane
__device__ __align__(128) __half g_fk_hi[NB*DD*NN];   // [e'][n] single plane
__device__ __align__(128) __half g_fvT_hi[NB*NNP*DD]; // [n][e'] single plane
__device__ __align__(128) __half g_at_hi[NB*DD*DD];   // [d][e'] single plane
__device__ __align__(128) __half g_w_hi[96*256];      // qkv weights single plane
__device__ __align__(128) __half g_wu_hi[256*32];     // Wu fp16 hi/mi planes
__device__ __align__(128) __half g_wu_mi[256*32];

typedef unsigned long long u64;

// ---------------- PTX helpers (baseline ISA only) ---------------------------
__device__ __forceinline__ uint32_t smem_u32(const void* p) {
    uint32_t a;
    asm("{ .reg .u64 t; cvta.to.shared.u64 t, %1; cvt.u32.u64 %0, t; }" : "=r"(a) : "l"(p));
    return a;
}
__device__ __forceinline__ void cpa16(uint32_t s, const void* g) {
    asm volatile("cp.async.cg.shared.global [%0], [%1], 16;" :: "r"(s), "l"(g));
}
#define CPA_COMMIT() asm volatile("cp.async.commit_group;" ::: "memory")

__device__ __forceinline__ void ldsm4(uint32_t* r, uint32_t a) {
    asm volatile("ldmatrix.sync.aligned.m8n8.x4.shared.b16 {%0,%1,%2,%3}, [%4];"
        : "=r"(r[0]), "=r"(r[1]), "=r"(r[2]), "=r"(r[3]) : "r"(a));
}
__device__ __forceinline__ void ldsm4t(uint32_t* r, uint32_t a) {
    asm volatile("ldmatrix.sync.aligned.m8n8.x4.trans.shared.b16 {%0,%1,%2,%3}, [%4];"
        : "=r"(r[0]), "=r"(r[1]), "=r"(r[2]), "=r"(r[3]) : "r"(a));
}
__device__ __forceinline__ void ldsm2t(uint32_t* r, uint32_t a) {
    asm volatile("ldmatrix.sync.aligned.m8n8.x2.trans.shared.b16 {%0,%1}, [%2];"
        : "=r"(r[0]), "=r"(r[1]) : "r"(a));
}
__device__ __forceinline__ void mma_f16(float* d, const uint32_t* a, uint32_t b0, uint32_t b1) {
    asm volatile(
        "mma.sync.aligned.m16n8k16.row.col.f32.f16.f16.f32 "
        "{%0,%1,%2,%3},{%4,%5,%6,%7},{%8,%9},{%0,%1,%2,%3};"
        : "+f"(d[0]), "+f"(d[1]), "+f"(d[2]), "+f"(d[3])
        : "r"(a[0]), "r"(a[1]), "r"(a[2]), "r"(a[3]), "r"(b0), "r"(b1));
}

// pack 2 floats -> fp16x2 (lo=a, hi=b)
__device__ __forceinline__ uint32_t pack_h2(float a, float b) {
    uint32_t r;
    asm("cvt.rn.f16x2.f32 %0, %1, %2;" : "=r"(r) : "f"(b), "f"(a));
    return r;
}

// ---------------------------------------------------------------------------
// K-1: W q/v/k rows -> single fp16 plane; Wu -> fp16 hi/mi planes.
// ---------------------------------------------------------------------------
__global__ __launch_bounds__(256) void k_wsplit(
    const float* __restrict__ Wq, const float* __restrict__ Wv, const float* __restrict__ Wk,
    const float* __restrict__ Wu)
{
    int i = blockIdx.x * 256 + threadIdx.x;
    if (i < 96*256) {
        int r = i >> 8, kk = i & 255;
        float v = (r < 32) ? Wq[r*256 + kk] : ((r < 64) ? Wv[(r-32)*256 + kk] : Wk[(r-64)*256 + kk]);
        g_w_hi[i] = __float2half_rn(v);
    }
    if (i < 256*32) {
        float v = Wu[i];
        __half h = __float2half_rn(v);
        g_wu_hi[i] = h;
        g_wu_mi[i] = __float2half_rn(v - __half2float(h));
    }
}

// ---------------------------------------------------------------------------
// K1: PERSISTENT tensor-core fused q/k/v 1x1 conv + pixel_unshuffle.
// 384 threads / 12 warps (3/SMSP), warp grid 3m x 4n, warp tile 32x40.
// Single-pass fp16: W (1 plane, smem-resident) x x (1 fp16 plane per source).
// smem: W_hi @0 (48K); x stages @49152 + s*24576 (depth @0, rgb @12288).
// epi buffer overlays stage region @49152 (64512 B). Total 114688.
// ---------------------------------------------------------------------------
__global__ __launch_bounds__(384, 1) void k_projT(
    const float* __restrict__ rgb, const float* __restrict__ depth,
    const float* __restrict__ bq, const float* __restrict__ bk,
    const float* __restrict__ bv)
{
    extern __shared__ __align__(1024) char sm[];
    const int t = threadIdx.x, lane = t & 31, wid = t >> 5;
    const int wn = wid & 3, wm = wid >> 2;       // wm 0..2, wn 0..3
    const uint32_t su = smem_u32(sm);
    const uint32_t XB = su + 49152;
    float* const epi = (float*)(sm + 49152);

    // ---- W plane into smem (once per CTA) ----
    for (int i = t; i < 96*32; i += 384) {
        int m = i >> 5, c = i & 31;
        uint4 v1 = *(const uint4*)((const char*)g_w_hi + m*512 + c*16);
        int sw = (c ^ (m & 7)) * 16;
        *(uint4*)(sm + m*512 + sw) = v1;
    }

    float bias_v[2][2];
#pragma unroll
    for (int mt = 0; mt < 2; mt++)
#pragma unroll
        for (int hh = 0; hh < 2; hh++) {
            int r = wm*32 + mt*16 + (lane >> 2) + hh*8;
            bias_v[mt][hh] = (r < 32) ? bq[r] : ((r < 64) ? bv[r-32] : bk[r-64]);
        }

    // per-thread ldg mapping: 2560 float4 items (src x 32 cin x 40 c4)
    int cin_[7], c4_[7], pl_[7];
    bool val_[7];
#pragma unroll
    for (int j = 0; j < 7; j++) {
        int item = t + j*384;
        val_[j] = item < 2560;
        int it2 = val_[j] ? item : 0;
        int src = (it2 >= 1280) ? 1 : 0;
        int rem = it2 - src*1280;
        cin_[j] = rem / 40; c4_[j] = rem % 40;
        pl_[j]  = src ? 12288 : 0;
    }
    __syncthreads();

    const int cta = blockIdx.x;
    int u        = (1280 * cta) / 148;
    const int u1 = (1280 * (cta + 1)) / 148;

    int b = u / 160, h = u - b*160;
    const float* db = depth + (size_t)b*CHN*HW;
    const float* rb = rgb   + (size_t)b*CHN*HW;
    size_t rowoff = (size_t)h * 160;

    float4 rv[7];
    auto ldg_chunk = [&](int c, const float* dB, const float* rB, size_t ro) {
#pragma unroll
        for (int j = 0; j < 7; j++) {
            if (val_[j]) {
                const float* bp = pl_[j] ? rB : dB;
                rv[j] = *(const float4*)(bp + (size_t)(c*32 + cin_[j])*HW + ro + c4_[j]*4);
            }
        }
    };
    auto sts_chunk = [&](int s) {
        const int soff = 49152 + s*24576;
#pragma unroll
        for (int j = 0; j < 7; j++) {
            if (val_[j]) {
                int row = cin_[j], c4 = c4_[j];
                int a = soff + pl_[j] + row*384 + (((c4 >> 1) ^ (row & 7)) * 16) + (c4 & 1)*8;
                uint32_t h01 = pack_h2(rv[j].x, rv[j].y);
                uint32_t h23 = pack_h2(rv[j].z, rv[j].w);
                *(uint2*)(sm + a) = make_uint2(h01, h23);
            }
        }
    };

    ldg_chunk(0, db, rb, rowoff);

    for (; u < u1; u++) {
        const int ip = h & 3, hn = h >> 2, curb = b;

        int nb = b, nh = h + 1;
        if (nh == 160) { nh = 0; nb = b + 1; }
        const bool has_next = (u + 1 < u1);
        const float* ndb = depth + (size_t)nb*CHN*HW;
        const float* nrb = rgb   + (size_t)nb*CHN*HW;
        const size_t nro = (size_t)nh * 160;

        sts_chunk(0);
        ldg_chunk(1, db, rb, rowoff);

        float acc[2][5][4];
#pragma unroll
        for (int i = 0; i < 2; i++)
#pragma unroll
            for (int j = 0; j < 5; j++)
#pragma unroll
                for (int r = 0; r < 4; r++) acc[i][j][r] = 0.0f;

        const int pls = (wm == 2) ? 12288 : 0;   // this warp's source plane

        for (int c = 0; c < 8; c++) {
            __syncthreads();
            if (c + 1 < 8) sts_chunk((c + 1) & 1);
            if (c + 2 < 8)                    ldg_chunk(c + 2, db, rb, rowoff);
            else if (c == 6 && has_next)      ldg_chunk(0, ndb, nrb, nro);
            __syncthreads();

            const uint32_t xs = XB + (c & 1)*24576;
#pragma unroll
            for (int kk = 0; kk < 2; kk++) {
                uint32_t ah[2][4];
#pragma unroll
                for (int mt = 0; mt < 2; mt++) {
                    int m = wm*32 + mt*16 + (lane & 15);
                    int ca = c*4 + kk*2 + (lane >> 4);
                    uint32_t addr = su + m*512 + (ca ^ (m & 7))*16;
                    ldsm4(ah[mt], addr);
                }
                const int krow = kk*16 + (lane & 15);
                const int swz = krow & 7;
                const uint32_t rbase_a = xs + pls + krow*384;
                uint32_t bh[2][4], bh2[2];
#pragma unroll
                for (int tt = 0; tt < 2; tt++) {
                    int cc = wn*5 + tt*2 + (lane >> 4);
                    ldsm4t(bh[tt], rbase_a + (cc ^ swz)*16);
                }
                {
                    int cc = wn*5 + 4;
                    ldsm2t(bh2, rbase_a + (cc ^ swz)*16);
                }
#pragma unroll
                for (int mt = 0; mt < 2; mt++) {
#pragma unroll
                    for (int nt = 0; nt < 5; nt++) {
                        uint32_t b0, b1;
                        if (nt < 4) {
                            int g = nt >> 1, hf = nt & 1;
                            b0 = bh[g][hf*2]; b1 = bh[g][hf*2+1];
                        } else {
                            b0 = bh2[0]; b1 = bh2[1];
                        }
                        mma_f16(acc[mt][nt], ah[mt], b0, b1);
                    }
                }
            }
        }

        // ---- epilogue: stage into epi, coalesced drain ----
        __syncthreads();
#pragma unroll
        for (int mt = 0; mt < 2; mt++) {
#pragma unroll
            for (int nt = 0; nt < 5; nt++) {
                int col0 = wn*40 + nt*8 + (lane & 3)*2;
                int nw = col0 >> 2, j0 = col0 & 3;
#pragma unroll
                for (int hh = 0; hh < 2; hh++) {
                    int r = wm*32 + mt*16 + (lane >> 2) + hh*8;
                    epi[(j0*96 + r)*42 + nw]     = acc[mt][nt][hh*2]   + bias_v[mt][hh];
                    epi[((j0+1)*96 + r)*42 + nw] = acc[mt][nt][hh*2+1] + bias_v[mt][hh];
                }
            }
        }
        __syncthreads();

        for (int tk = wid; tk < 416; tk += 12) {
            if (tk < 256) {
                if (lane < 20) {
                    int rr = tk >> 2, j = tk & 3;
                    int row = (rr < 32) ? rr : rr + 32;
                    float2 v = *(const float2*)&epi[(j*96 + row)*42 + lane*2];
                    uint32_t hi = pack_h2(v.x, v.y);
                    int dd = (rr < 32) ? (rr*16 + ip*4 + j)
                                       : ((ip*4 + j)*32 + (rr - 32));
                    size_t base = ((size_t)(curb*DD + dd))*NN + hn*40 + lane*2;
                    __half* dh = (rr < 32) ? g_fq_hi : g_fk_hi;
                    *(uint32_t*)(dh + base) = hi;
                }
            } else {
                if (lane < 16) {
                    int tv = tk - 256;
                    int nw = tv >> 2, j = tv & 3;
                    float v0 = epi[(j*96 + 32 + lane*2)*42 + nw];
                    float v1 = epi[(j*96 + 33 + lane*2)*42 + nw];
                    uint32_t hi = pack_h2(v0, v1);
                    int n = hn*40 + nw;
                    size_t base = ((size_t)curb*NNP + n)*DD + (ip*4 + j)*32 + lane*2;
                    *(uint32_t*)(g_fvT_hi + base) = hi;
                }
            }
        }
        __syncthreads();   // epi region reused as x stages next unit

        b = nb; h = nh; db = ndb; rb = nrb; rowoff = nro;
    }
}

// ---------------------------------------------------------------------------
// Generic 128x64-tile mma.sync single-pass fp16 GEMM (2 CTAs/SM, 3 stages):
// MODE 0: scores (A=fq_hi, B=fk_hi, K=1600, C=g_sc fp32 [512x512])
// MODE 1: attn@V (A=at_hi, B=fvT_hi, K=512, C=g_oph fp16 [512x1600])
// stage: Ahi 16K | Bhi 8K ; stride 24576; 3 stages = 72KB.
// ---------------------------------------------------------------------------
template<int MODE>
__global__ __launch_bounds__(256, 2) void k_gemm()
{
    constexpr int K    = (MODE == 0) ? 1600 : 512;
    constexpr int LD   = (MODE == 0) ? 1600 : 512;
    constexpr int LDC  = (MODE == 0) ? 512  : 1600;
    constexpr long SA  = (MODE == 0) ? (long)DD*NN : (long)DD*DD;
    constexpr long SB  = (MODE == 0) ? (long)DD*NN : (long)NNP*DD;
    constexpr int NCH  = K / 64;

    extern __shared__ __align__(1024) char dsm[];

    const int b  = blockIdx.z;
    const int m0 = blockIdx.y * 128;
    const int n0 = blockIdx.x * 64;
    const int t    = threadIdx.x;
    const int lane = t & 31;
    const int wid  = t >> 5;
    const int wm   = wid & 3;
    const int wn   = wid >> 2;

    const uint32_t smem_u = smem_u32(dsm);

    const __half* Ahi = (MODE == 0 ? g_fq_hi : g_at_hi)  + b*SA + (long)m0*LD;
    const __half* Bhi = (MODE == 0 ? g_fk_hi : g_fvT_hi) + b*SB + (long)n0*LD;

    auto load_stage = [&](int s, int kc) {
        uint32_t base = smem_u + s*24576;
#pragma unroll
        for (int ii = 0; ii < 4; ii++) {
            int i = t + ii*256;
            int row = i >> 3, seg = i & 7;
            uint32_t off = row*128 + seg*16;
            uint32_t sw  = off ^ ((off >> 3) & 0x70);
            long go = (long)row*LD + kc;
            cpa16(base + sw, (const char*)(Ahi + go) + seg*16);
        }
#pragma unroll
        for (int ii = 0; ii < 2; ii++) {
            int i = t + ii*256;
            int row = i >> 3, seg = i & 7;
            uint32_t off = row*128 + seg*16;
            uint32_t sw  = off ^ ((off >> 3) & 0x70);
            long go = (long)row*LD + kc;
            cpa16(base + 16384 + sw, (const char*)(Bhi + go) + seg*16);
        }
        CPA_COMMIT();
    };

    float acc[2][4][4];
#pragma unroll
    for (int i = 0; i < 2; i++)
#pragma unroll
        for (int j = 0; j < 4; j++)
#pragma unroll
            for (int r = 0; r < 4; r++) acc[i][j][r] = 0.0f;

    load_stage(0, 0);
    load_stage(1, 64);
    load_stage(2, 128);   // NCH >= 8 in both modes

    const int lr = lane & 15;
    const int lc = lane >> 4;

    for (int c = 0; c < NCH; c++) {
        const int s = c - (c/3)*3;
        if (c + 2 < NCH)      asm volatile("cp.async.wait_group 2;" ::: "memory");
        else if (c + 1 < NCH) asm volatile("cp.async.wait_group 1;" ::: "memory");
        else                  asm volatile("cp.async.wait_group 0;" ::: "memory");
        __syncthreads();

        const uint32_t base = smem_u + s*24576;
#pragma unroll
        for (int kk = 0; kk < 4; kk++) {
            uint32_t a_hi[2][4];
#pragma unroll
            for (int mt = 0; mt < 2; mt++) {
                int row = wm*32 + mt*16 + lr;
                uint32_t off = row*128 + kk*32 + lc*16;
                uint32_t sw  = off ^ ((off >> 3) & 0x70);
                ldsm4(a_hi[mt], base + sw);
            }
            uint32_t b_hi[2][4];
#pragma unroll
            for (int bt = 0; bt < 2; bt++) {
                int row = wn*32 + bt*16 + lr;
                uint32_t off = row*128 + kk*32 + lc*16;
                uint32_t sw  = off ^ ((off >> 3) & 0x70);
                ldsm4(b_hi[bt], base + 16384 + sw);
            }
#pragma unroll
            for (int mt = 0; mt < 2; mt++) {
#pragma unroll
                for (int nt = 0; nt < 4; nt++) {
                    int bt = nt >> 1, hf = nt & 1;
                    mma_f16(acc[mt][nt], a_hi[mt], b_hi[bt][hf], b_hi[bt][hf+2]);
                }
            }
        }
        __syncthreads();
        if (c + 3 < NCH) load_stage(s, (c + 3)*64);
    }

    const int rq = lane >> 2;
    const int cq = (lane & 3) * 2;
#pragma unroll
    for (int mt = 0; mt < 2; mt++) {
#pragma unroll
        for (int nt = 0; nt < 4; nt++) {
            int col = n0 + wn*32 + nt*8 + cq;
            int row = m0 + wm*32 + mt*16 + rq;
            if (MODE == 0) {
                float* p0 = g_sc + (long)b*DD*DD + (long)row*LDC + col;
                *(float2*)p0            = make_float2(acc[mt][nt][0], acc[mt][nt][1]);
                *(float2*)(p0 + 8L*LDC) = make_float2(acc[mt][nt][2], acc[mt][nt][3]);
            } else {
                __half* p0 = g_oph + (long)b*DD*NN + (long)row*LDC + col;
                *(uint32_t*)p0            = pack_h2(acc[mt][nt][0], acc[mt][nt][1]);
                *(uint32_t*)(p0 + 8L*LDC) = pack_h2(acc[mt][nt][2], acc[mt][nt][3]);
            }
        }
    }
}

// ---------------------------------------------------------------------------
// K3: softmax over rows of g_sc, writes attn as single fp16 plane.
// ---------------------------------------------------------------------------
__global__ __launch_bounds__(128) void k_softmax()
{
    __shared__ float red[8];
    const size_t row = blockIdx.x;
    const float* s = g_sc + row * DD;
    const int t = threadIdx.x;

    float v0 = s[t], v1 = s[t+128], v2 = s[t+256], v3 = s[t+384];
    float m = fmaxf(fmaxf(v0, v1), fmaxf(v2, v3));
#pragma unroll
    for (int o = 16; o; o >>= 1) m = fmaxf(m, __shfl_xor_sync(0xffffffffu, m, o));
    if ((t & 31) == 0) red[t >> 5] = m;
    __syncthreads();
    m = fmaxf(fmaxf(red[0], red[1]), fmaxf(red[2], red[3]));

    const float inv = 0.04419417382415922f;  // 1/sqrt(512)
    float e0 = __expf((v0 - m) * inv);
    float e1 = __expf((v1 - m) * inv);
    float e2 = __expf((v2 - m) * inv);
    float e3 = __expf((v3 - m) * inv);
    float sum = e0 + e1 + e2 + e3;
#pragma unroll
    for (int o = 16; o; o >>= 1) sum += __shfl_xor_sync(0xffffffffu, sum, o);
    if ((t & 31) == 0) red[4 + (t >> 5)] = sum;
    __syncthreads();
    float r = 1.0f / (red[4] + red[5] + red[6] + red[7]);

    size_t base = row * DD;
    g_at_hi[base + t]       = __float2half_rn(e0 * r);
    g_at_hi[base + t + 128] = __float2half_rn(e1 * r);
    g_at_hi[base + t + 256] = __float2half_rn(e2 * r);
    g_at_hi[base + t + 384] = __float2half_rn(e3 * r);
}

// ---------------------------------------------------------------------------
// K5: PERSISTENT pixel_shuffle gather + final 1x1 conv (32 -> 256).
// fp16 2-pass: Wu (hi/mi fp16 planes) x op (1 fp16 plane).
// smem: Wu_hi @0 (20480), Wu_mi @20480; B stages @40960 + s*4096. 49152 B.
// ---------------------------------------------------------------------------
__global__ __launch_bounds__(256, 2) void k_final(
    const float* __restrict__ bu, float* __restrict__ out)
{
    extern __shared__ __align__(1024) char sm[];
    const uint32_t su = smem_u32(sm);
    const int t = threadIdx.x, lane = t & 31, wid = t >> 5;
    const int wm = wid & 3, wn = wid >> 2;
    const int rq = lane >> 2, cq = (lane & 3) * 2;

    // ---- load Wu planes once: row t at 80B pitch ----
    {
        const uint4* src_h = (const uint4*)((const char*)g_wu_hi + t*64);
        const uint4* src_m = (const uint4*)((const char*)g_wu_mi + t*64);
#pragma unroll
        for (int c = 0; c < 4; c++) {
            *(uint4*)(sm + t*80 + c*16)         = src_h[c];
            *(uint4*)(sm + 20480 + t*80 + c*16) = src_m[c];
        }
    }

    float bb[4][2];
#pragma unroll
    for (int mt = 0; mt < 4; mt++) {
        int ch0 = wm*64 + mt*16 + rq;
        bb[mt][0] = bu[ch0];
        bb[mt][1] = bu[ch0 + 8];
    }

    const int gc = t >> 3;
    const int ii = (t >> 2) & 1;
    const int gj = t & 3;

    const int cta = blockIdx.x;
    int u        = (3200 * cta) / 296;
    const int u1 = (3200 * (cta + 1)) / 296;

    uint4 hv;   // 8 fp16 values
    auto prefetch = [&](int uu) {
        int pb = uu / 400, r = uu - pb*400;
        int php = r / 5, pwb = r - (r/5)*5;
        int i0 = (2*php) & 3, hn = php >> 1;
        int d  = gc*16 + (i0 + ii)*4 + gj;
        hv = *(const uint4*)(g_oph + ((size_t)(pb*DD + d))*NN + hn*40 + pwb*8);
    };
    if (u < u1) prefetch(u);

    for (; u < u1; u++) {
        const int s = u & 1;
        const int b = u / 400, r = u - b*400;
        const int hp = r / 5, wblk = r - (r/5)*5;

        __syncthreads();   // stage s free; Wu visible on first iter

        // ---- stage B (already fp16; scatter into swizzled [32 c][64 px]) ----
        {
            const __half* hvals = (const __half*)&hv;
#pragma unroll
            for (int nw = 0; nw < 8; nw++) {
                int px = ii*32 + nw*4 + gj;
                uint32_t a = 40960 + s*4096 + gc*128 + (((px >> 3) ^ (gc & 7))*16) + (px & 7)*2;
                *(__half*)(sm + a) = hvals[nw];
            }
        }
        if (u + 1 < u1) prefetch(u + 1);   // overlap next gather with MMA
        __syncthreads();

        // ---- MMA (stage s): 2 passes (Wu_hi + Wu_mi) x op ----
        float acc[4][4][4];
#pragma unroll
        for (int i = 0; i < 4; i++)
#pragma unroll
            for (int j = 0; j < 4; j++)
#pragma unroll
                for (int rr = 0; rr < 4; rr++) acc[i][j][rr] = 0.0f;

#pragma unroll
        for (int kk = 0; kk < 2; kk++) {
            uint32_t ah[4][4], am[4][4];
#pragma unroll
            for (int mt = 0; mt < 4; mt++) {
                int row = wm*64 + mt*16 + (lane & 15);
                uint32_t addr = su + row*80 + (kk*2 + (lane >> 4))*16;
                ldsm4(ah[mt], addr);
                ldsm4(am[mt], addr + 20480);
            }
            const int krow = kk*16 + (lane & 15);
            uint32_t bh[2][4];
#pragma unroll
            for (int tt = 0; tt < 2; tt++) {
                int cc = wn*4 + tt*2 + (lane >> 4);
                uint32_t addr = su + 40960 + s*4096 + krow*128 + ((cc ^ (krow & 7))*16);
                ldsm4t(bh[tt], addr);
            }
#pragma unroll
            for (int mt = 0; mt < 4; mt++) {
#pragma unroll
                for (int nt = 0; nt < 4; nt++) {
                    int tt = nt >> 1, hf = nt & 1;
                    mma_f16(acc[mt][nt], ah[mt], bh[tt][hf*2], bh[tt][hf*2+1]);
                    mma_f16(acc[mt][nt], am[mt], bh[tt][hf*2], bh[tt][hf*2+1]);
                }
            }
        }

        // ---- epilogue: bias + float2 stores ----
        const int h = hp*2 + wn;
#pragma unroll
        for (int mt = 0; mt < 4; mt++) {
            int ch0 = wm*64 + mt*16 + rq;
#pragma unroll
            for (int nt = 0; nt < 4; nt++) {
                int w = wblk*32 + nt*8 + cq;
                float* p0 = out + ((size_t)(b*CHN + ch0))*HW + (size_t)h*160 + w;
                *(float2*)p0          = make_float2(acc[mt][nt][0] + bb[mt][0], acc[mt][nt][1] + bb[mt][0]);
                *(float2*)(p0 + 8*HW) = make_float2(acc[mt][nt][2] + bb[mt][1], acc[mt][nt][3] + bb[mt][1]);
            }
        }
    }
}

// ---------------------------------------------------------------------------
extern "C" void kernel_launch(void* const* d_in, const int* in_sizes, int n_in,
                              void* d_out, int out_size)
{
    (void)in_sizes; (void)n_in; (void)out_size;
    const float* rgb   = (const float*)d_in[0];
    const float* depth = (const float*)d_in[1];
    const float* Wq    = (const float*)d_in[2];
    const float* bq    = (const float*)d_in[3];
    const float* Wk    = (const float*)d_in[4];
    const float* bk    = (const float*)d_in[5];
    const float* Wv    = (const float*)d_in[6];
    const float* bv    = (const float*)d_in[7];
    const float* Wu    = (const float*)d_in[8];
    const float* bu    = (const float*)d_in[9];
    float* out = (float*)d_out;

    cudaFuncSetAttribute(k_projT,   cudaFuncAttributeMaxDynamicSharedMemorySize, 114688);
    cudaFuncSetAttribute(k_gemm<0>, cudaFuncAttributeMaxDynamicSharedMemorySize, 73728);
    cudaFuncSetAttribute(k_gemm<1>, cudaFuncAttributeMaxDynamicSharedMemorySize, 73728);
    cudaFuncSetAttribute(k_final,   cudaFuncAttributeMaxDynamicSharedMemorySize, 49152);

    k_wsplit <<<96, 256>>>(Wq, Wv, Wk, Wu);
    k_projT  <<<148, 384, 114688>>>(rgb, depth, bq, bk, bv);
    k_gemm<0><<<dim3(8, 4, NB), 256, 73728>>>();
    k_softmax<<<NB*DD, 128>>>();
    k_gemm<1><<<dim3(25, 4, NB), 256, 73728>>>();
    k_final  <<<296, 256, 49152>>>(bu, out);
}